// round 2
// baseline (speedup 1.0000x reference)
#include <cuda_runtime.h>
#include <math.h>

#define Bb 4
#define Ss 4096
#define Hh 2048
#define Mm 128
#define CH 64
#define NC 64
#define NSLOTS 64
#define NTOK (Bb*Ss)   // 16384

// ---------------- scratch (static device globals; no allocation) ----------------
__device__ float g_q[NTOK*Mm];
__device__ float g_k[NTOK*Mm];
__device__ float g_v[NTOK*Mm];
__device__ float g_w[NTOK];
__device__ float g_r[NTOK*Mm];
__device__ float g_Kagg[NSLOTS*Mm];
__device__ float g_Vagg[NSLOTS*Mm];
__device__ float g_ws[NSLOTS];

// ---------------- canonical 128x128x8 fp32 GEMM body (C = A[M,K] @ Bm[N,K]^T) ----------------
__device__ __forceinline__ void sgemm_body(const float* __restrict__ A,
                                           const float* __restrict__ Bm,
                                           float* __restrict__ C,
                                           int K, int N)
{
    __shared__ __align__(16) float As[8][128];
    __shared__ __align__(16) float Bs[8][128];
    int tid = threadIdx.x;
    int m0 = blockIdx.x * 128;
    int n0 = blockIdx.y * 128;
    int lrow = tid >> 1;
    int lk = (tid & 1) << 2;
    const float* Ap = A + (size_t)(m0 + lrow) * K + lk;
    const float* Bp = Bm + (size_t)(n0 + lrow) * K + lk;
    int tx = tid & 15, ty = tid >> 4;

    float acc[8][8];
#pragma unroll
    for (int i = 0; i < 8; i++)
#pragma unroll
        for (int j = 0; j < 8; j++) acc[i][j] = 0.f;

    for (int k0 = 0; k0 < K; k0 += 8) {
        float4 av = *(const float4*)(Ap + k0);
        float4 bv = *(const float4*)(Bp + k0);
        __syncthreads();
        As[lk + 0][lrow] = av.x; As[lk + 1][lrow] = av.y;
        As[lk + 2][lrow] = av.z; As[lk + 3][lrow] = av.w;
        Bs[lk + 0][lrow] = bv.x; Bs[lk + 1][lrow] = bv.y;
        Bs[lk + 2][lrow] = bv.z; Bs[lk + 3][lrow] = bv.w;
        __syncthreads();
#pragma unroll
        for (int kk = 0; kk < 8; kk++) {
            float a[8], b[8];
            *(float4*)(a)     = *(const float4*)&As[kk][ty * 4];
            *(float4*)(a + 4) = *(const float4*)&As[kk][64 + ty * 4];
            *(float4*)(b)     = *(const float4*)&Bs[kk][tx * 4];
            *(float4*)(b + 4) = *(const float4*)&Bs[kk][64 + tx * 4];
#pragma unroll
            for (int i = 0; i < 8; i++)
#pragma unroll
                for (int j = 0; j < 8; j++)
                    acc[i][j] += a[i] * b[j];
        }
    }
#pragma unroll
    for (int i = 0; i < 8; i++) {
        int r = m0 + ((i < 4) ? (ty * 4 + i) : (64 + ty * 4 + (i - 4)));
        float* Cr = C + (size_t)r * N + n0;
        *(float4*)(Cr + tx * 4)      = make_float4(acc[i][0], acc[i][1], acc[i][2], acc[i][3]);
        *(float4*)(Cr + 64 + tx * 4) = make_float4(acc[i][4], acc[i][5], acc[i][6], acc[i][7]);
    }
}

__global__ void __launch_bounds__(256) sgemm_nt(const float* __restrict__ A,
                                                const float* __restrict__ Bm,
                                                float* __restrict__ C, int K, int N)
{
    sgemm_body(A, Bm, C, K, N);
}

// fused q/k/v projections via blockIdx.z for better occupancy (384 blocks)
__global__ void __launch_bounds__(256) proj_gemm(const float* __restrict__ x,
                                                 const float* __restrict__ Wq,
                                                 const float* __restrict__ Wk,
                                                 const float* __restrict__ Wv)
{
    const float* W; float* C;
    if (blockIdx.z == 0)      { W = Wq; C = g_q; }
    else if (blockIdx.z == 1) { W = Wk; C = g_k; }
    else                      { W = Wv; C = g_v; }
    sgemm_body(x, W, C, Hh, Mm);
}

// ---------------- gate: w[t] = sigmoid(x_t . Wg + b) ----------------
__global__ void __launch_bounds__(256) gate_kernel(const float* __restrict__ x,
                                                   const float* __restrict__ Wg,
                                                   const float* __restrict__ gb)
{
    int gwarp = (blockIdx.x * 256 + threadIdx.x) >> 5;
    int lane = threadIdx.x & 31;
    if (gwarp >= NTOK) return;
    const float4* x4 = (const float4*)(x + (size_t)gwarp * Hh);
    const float4* w4 = (const float4*)Wg;
    float s = 0.f;
    for (int d = lane; d < Hh / 4; d += 32) {
        float4 a = x4[d], b = w4[d];
        s += a.x * b.x + a.y * b.y + a.z * b.z + a.w * b.w;
    }
#pragma unroll
    for (int o = 16; o; o >>= 1) s += __shfl_xor_sync(0xffffffffu, s, o);
    if (lane == 0) g_w[gwarp] = 1.f / (1.f + expf(-(s + gb[0])));
}

// ---------------- per-chunk aggregates: k_agg, v_agg, write_str ----------------
__global__ void __launch_bounds__(256) agg_kernel()
{
    int i = blockIdx.x;     // chunk
    int tid = threadIdx.x;  // 256 = one thread per (b,c) token in phase 1
    __shared__ float sw[256];
    __shared__ float sik[256];
    __shared__ float siv[256];
    __shared__ float red[256];
    {
        int b = tid >> 6, c = tid & 63;
        size_t t = (size_t)b * Ss + (size_t)i * CH + c;
        const float* kr = g_k + t * Mm;
        const float* vr = g_v + t * Mm;
        float nk = 0.f, nv = 0.f;
        for (int d = 0; d < Mm; d++) {
            float a = kr[d]; nk += a * a;
            float u = vr[d]; nv += u * u;
        }
        sik[tid] = 1.f / fmaxf(sqrtf(nk), 1e-12f);
        siv[tid] = 1.f / fmaxf(sqrtf(nv), 1e-12f);
        float wv = g_w[t];
        sw[tid] = wv;
        red[tid] = wv;
    }
    __syncthreads();
    for (int o = 128; o; o >>= 1) { if (tid < o) red[tid] += red[tid + o]; __syncthreads(); }
    float sumw = red[0];
    float wsum = fmaxf(sumw, 1e-8f);
    __syncthreads();

    // phase 2: threads 0..127 accumulate k dims, 128..255 accumulate v dims (coalesced)
    int d = tid & 127;
    bool isv = (tid >= 128);
    const float* src = isv ? g_v : g_k;
    const float* inv = isv ? siv : sik;
    float acc = 0.f;
    for (int j = 0; j < 256; j++) {
        int b = j >> 6, c = j & 63;
        size_t tj = (size_t)b * Ss + (size_t)i * CH + c;
        acc += sw[j] * inv[j] * src[tj * Mm + d];
    }
    float mean = acc / wsum;
    red[tid] = mean * mean;
    __syncthreads();
    for (int o = 64; o; o >>= 1) { if ((tid & 127) < o) red[tid] += red[tid + o]; __syncthreads(); }
    float nrm = fmaxf(sqrtf(red[isv ? 128 : 0]), 1e-12f);
    float outv = mean / nrm;
    if (isv) g_Vagg[i * Mm + d] = outv;
    else     g_Kagg[i * Mm + d] = outv;
    if (tid == 0) g_ws[i] = sumw * (1.f / 256.f);
}

// ---------------- mean write strength ----------------
__global__ void meanws_kernel(float* __restrict__ out, int out_size)
{
    if (threadIdx.x == 0 && out_size > NTOK * Hh) {
        float s = 0.f;
        for (int j = 0; j < NC; j++) s += g_ws[j];
        out[(size_t)NTOK * Hh] = s / (float)NC;
    }
}

// ---------------- attention read: r_t = softmax(beta q_t . Kagg[active]) @ Vagg ----------------
// grid (chunk, batch); 256 threads = 8 warps, each warp handles 8 tokens.
__global__ void __launch_bounds__(256) attn_kernel(const float* __restrict__ log_beta,
                                                   float* __restrict__ r_out)
{
    extern __shared__ float sm[];
    float* ksm = sm;              // 64*129
    float* vsm = ksm + 64 * 129;  // 64*129
    float* qsm = vsm + 64 * 129;  // 64*129
    float* psm = qsm + 64 * 129;  // 8*64
    __shared__ float str[64];
    __shared__ float ssum;

    int i = blockIdx.x;   // chunk
    int bb = blockIdx.y;  // batch
    int tid = threadIdx.x;
    float beta = expf(log_beta[0]);

    for (int idx = tid; idx < 64 * 128; idx += 256) {
        int j = idx >> 7, d = idx & 127;
        ksm[j * 129 + d] = g_Kagg[idx];
        vsm[j * 129 + d] = g_Vagg[idx];
    }
    size_t tbase = (size_t)bb * Ss + (size_t)i * CH;
    for (int idx = tid; idx < 64 * 128; idx += 256) {
        int c = idx >> 7, d = idx & 127;
        qsm[c * 129 + d] = g_q[(tbase + c) * Mm + d];
    }
    if (tid < 64) {
        float dc = powf(0.999f, 64.f);
        float s = 0.f;
        if (tid < i) s = g_ws[tid] * powf(dc, (float)(i - 1 - tid));
        str[tid] = s;
    }
    __syncthreads();
    if (tid == 0) {
        float s = 0.f;
        for (int j = 0; j < 64; j++) s += str[j];
        ssum = s;
    }
    __syncthreads();

    bool valid = (ssum >= 1e-8f);
    int w = tid >> 5, lane = tid & 31;
    float m0ok = (str[lane] > 1e-8f)      ? 0.f : -1e9f;
    float m1ok = (str[lane + 32] > 1e-8f) ? 0.f : -1e9f;
    const float* k0 = ksm + lane * 129;
    const float* k1 = ksm + (lane + 32) * 129;

    for (int it = 0; it < 8; it++) {
        int c = w * 8 + it;
        const float* qrow = qsm + c * 129;
        float s0 = 0.f, s1 = 0.f;
#pragma unroll 8
        for (int d = 0; d < 128; d++) {
            float qd = qrow[d];
            s0 += qd * k0[d];
            s1 += qd * k1[d];
        }
        s0 = s0 * beta + m0ok;
        s1 = s1 * beta + m1ok;
        float mx = fmaxf(s0, s1);
#pragma unroll
        for (int o = 16; o; o >>= 1) mx = fmaxf(mx, __shfl_xor_sync(0xffffffffu, mx, o));
        float p0 = expf(s0 - mx);
        float p1 = expf(s1 - mx);
        float sum = p0 + p1;
#pragma unroll
        for (int o = 16; o; o >>= 1) sum += __shfl_xor_sync(0xffffffffu, sum, o);
        float invs = 1.f / sum;
        psm[w * 64 + lane]      = p0 * invs;
        psm[w * 64 + lane + 32] = p1 * invs;
        __syncwarp();
        float a0 = 0.f, a1 = 0.f, a2 = 0.f, a3 = 0.f;
#pragma unroll 4
        for (int j = 0; j < 64; j++) {
            float pj = psm[w * 64 + j];
            const float* vr = vsm + j * 129 + lane;
            a0 += pj * vr[0];
            a1 += pj * vr[32];
            a2 += pj * vr[64];
            a3 += pj * vr[96];
        }
        if (!valid) { a0 = a1 = a2 = a3 = 0.f; }
        float* ro = r_out + (tbase + c) * Mm;
        ro[lane]      = a0;
        ro[lane + 32] = a1;
        ro[lane + 64] = a2;
        ro[lane + 96] = a3;
        __syncwarp();
    }
}

// ---------------- per-token output norm clamp (deterministic, no atomics) ----------------
__global__ void __launch_bounds__(256) norm_kernel(float* __restrict__ out)
{
    __shared__ float red[256];
    size_t t = blockIdx.x;
    float* row = out + t * (size_t)Hh;
    int tid = threadIdx.x;
    float4* r4 = (float4*)row;
    float ss = 0.f;
#pragma unroll
    for (int u = 0; u < 2; u++) {
        float4 v = r4[tid + u * 256];
        ss += v.x * v.x + v.y * v.y + v.z * v.z + v.w * v.w;
    }
    red[tid] = ss;
    __syncthreads();
    for (int o = 128; o; o >>= 1) { if (tid < o) red[tid] += red[tid + o]; __syncthreads(); }
    float nrm = fmaxf(sqrtf(red[0]), 1e-6f);
    float sc = fminf(10.f / nrm, 1.f);
    if (sc < 1.f) {
#pragma unroll
        for (int u = 0; u < 2; u++) {
            float4 v = r4[tid + u * 256];
            v.x *= sc; v.y *= sc; v.z *= sc; v.w *= sc;
            r4[tid + u * 256] = v;
        }
    }
}

// ---------------- launch ----------------
extern "C" void kernel_launch(void* const* d_in, const int* in_sizes, int n_in,
                              void* d_out, int out_size)
{
    const float* x  = (const float*)d_in[0];
    const float* Wq = (const float*)d_in[1];
    const float* Wk = (const float*)d_in[2];
    const float* Wv = (const float*)d_in[3];
    const float* Wo = (const float*)d_in[4];
    const float* Wg = (const float*)d_in[5];
    const float* gb = (const float*)d_in[6];
    const float* lb = (const float*)d_in[7];
    float* out = (float*)d_out;

    float *pr;
    cudaGetSymbolAddress((void**)&pr, g_r);

    const int ATTN_SMEM = (3 * 64 * 129 + 8 * 64) * 4;  // ~99 KB
    cudaFuncSetAttribute(attn_kernel, cudaFuncAttributeMaxDynamicSharedMemorySize, ATTN_SMEM);

    // 1. projections q/k/v (384 blocks)
    proj_gemm<<<dim3(NTOK / 128, 1, 3), 256>>>(x, Wq, Wk, Wv);
    // 2. gate
    gate_kernel<<<NTOK / 8, 256>>>(x, Wg, gb);
    // 3. per-chunk write aggregates
    agg_kernel<<<NC, 256>>>();
    // 4. mean write strength (second output scalar)
    meanws_kernel<<<1, 32>>>(out, out_size);
    // 5. attention reads (fully parallel across chunks)
    attn_kernel<<<dim3(NC, Bb), 256, ATTN_SMEM>>>(lb, pr);
    // 6. output projection
    sgemm_nt<<<dim3(NTOK / 128, Hh / 128), 256>>>(pr, Wo, out, Mm, Hh);
    // 7. norm clamp
    norm_kernel<<<NTOK, 256>>>(out);
}

// round 3
// speedup vs baseline: 1.5597x; 1.5597x over previous
#include <cuda_runtime.h>
#include <math.h>

#define Bb 4
#define Ss 4096
#define Hh 2048
#define Mm 128
#define CH 64
#define NC 64
#define NSLOTS 64
#define NTOK (Bb*Ss)   // 16384

// ---------------- scratch (static device globals; no allocation) ----------------
__device__ float g_q[NTOK*Mm];
__device__ float g_k[NTOK*Mm];
__device__ float g_v[NTOK*Mm];
__device__ float g_w[NTOK];
__device__ float g_r[NTOK*Mm];
__device__ float g_Kagg[NSLOTS*Mm];
__device__ float g_Vagg[NSLOTS*Mm];
__device__ float g_ws[NSLOTS];

// ---------------- canonical 128x128x8 fp32 GEMM body (C = A[M,K] @ Bm[N,K]^T) ----------------
__device__ __forceinline__ void sgemm_body(const float* __restrict__ A,
                                           const float* __restrict__ Bm,
                                           float* __restrict__ C,
                                           int K, int N)
{
    __shared__ __align__(16) float As[8][128];
    __shared__ __align__(16) float Bs[8][128];
    int tid = threadIdx.x;
    int m0 = blockIdx.x * 128;
    int n0 = blockIdx.y * 128;
    int lrow = tid >> 1;
    int lk = (tid & 1) << 2;
    const float* Ap = A + (size_t)(m0 + lrow) * K + lk;
    const float* Bp = Bm + (size_t)(n0 + lrow) * K + lk;
    int tx = tid & 15, ty = tid >> 4;

    float acc[8][8];
#pragma unroll
    for (int i = 0; i < 8; i++)
#pragma unroll
        for (int j = 0; j < 8; j++) acc[i][j] = 0.f;

    for (int k0 = 0; k0 < K; k0 += 8) {
        float4 av = *(const float4*)(Ap + k0);
        float4 bv = *(const float4*)(Bp + k0);
        __syncthreads();
        As[lk + 0][lrow] = av.x; As[lk + 1][lrow] = av.y;
        As[lk + 2][lrow] = av.z; As[lk + 3][lrow] = av.w;
        Bs[lk + 0][lrow] = bv.x; Bs[lk + 1][lrow] = bv.y;
        Bs[lk + 2][lrow] = bv.z; Bs[lk + 3][lrow] = bv.w;
        __syncthreads();
#pragma unroll
        for (int kk = 0; kk < 8; kk++) {
            float a[8], b[8];
            *(float4*)(a)     = *(const float4*)&As[kk][ty * 4];
            *(float4*)(a + 4) = *(const float4*)&As[kk][64 + ty * 4];
            *(float4*)(b)     = *(const float4*)&Bs[kk][tx * 4];
            *(float4*)(b + 4) = *(const float4*)&Bs[kk][64 + tx * 4];
#pragma unroll
            for (int i = 0; i < 8; i++)
#pragma unroll
                for (int j = 0; j < 8; j++)
                    acc[i][j] += a[i] * b[j];
        }
    }
#pragma unroll
    for (int i = 0; i < 8; i++) {
        int r = m0 + ((i < 4) ? (ty * 4 + i) : (64 + ty * 4 + (i - 4)));
        float* Cr = C + (size_t)r * N + n0;
        *(float4*)(Cr + tx * 4)      = make_float4(acc[i][0], acc[i][1], acc[i][2], acc[i][3]);
        *(float4*)(Cr + 64 + tx * 4) = make_float4(acc[i][4], acc[i][5], acc[i][6], acc[i][7]);
    }
}

__global__ void __launch_bounds__(256) sgemm_nt(const float* __restrict__ A,
                                                const float* __restrict__ Bm,
                                                float* __restrict__ C, int K, int N)
{
    sgemm_body(A, Bm, C, K, N);
}

// fused q/k/v projections via blockIdx.z for better occupancy (384 blocks)
__global__ void __launch_bounds__(256) proj_gemm(const float* __restrict__ x,
                                                 const float* __restrict__ Wq,
                                                 const float* __restrict__ Wk,
                                                 const float* __restrict__ Wv)
{
    const float* W; float* C;
    if (blockIdx.z == 0)      { W = Wq; C = g_q; }
    else if (blockIdx.z == 1) { W = Wk; C = g_k; }
    else                      { W = Wv; C = g_v; }
    sgemm_body(x, W, C, Hh, Mm);
}

// ---------------- gate: w[t] = sigmoid(x_t . Wg + b) ----------------
__global__ void __launch_bounds__(256) gate_kernel(const float* __restrict__ x,
                                                   const float* __restrict__ Wg,
                                                   const float* __restrict__ gb)
{
    int gwarp = (blockIdx.x * 256 + threadIdx.x) >> 5;
    int lane = threadIdx.x & 31;
    if (gwarp >= NTOK) return;
    const float4* x4 = (const float4*)(x + (size_t)gwarp * Hh);
    const float4* w4 = (const float4*)Wg;
    float s = 0.f;
    for (int d = lane; d < Hh / 4; d += 32) {
        float4 a = x4[d], b = w4[d];
        s += a.x * b.x + a.y * b.y + a.z * b.z + a.w * b.w;
    }
#pragma unroll
    for (int o = 16; o; o >>= 1) s += __shfl_xor_sync(0xffffffffu, s, o);
    if (lane == 0) g_w[gwarp] = 1.f / (1.f + expf(-(s + gb[0])));
}

// ---------------- per-chunk aggregates: k_agg, v_agg, write_str ----------------
__global__ void __launch_bounds__(256) agg_kernel()
{
    int i = blockIdx.x;     // chunk
    int tid = threadIdx.x;  // 256 = one thread per (b,c) token in phase 1
    __shared__ float sw[256];
    __shared__ float sik[256];
    __shared__ float siv[256];
    __shared__ float red[256];
    {
        int b = tid >> 6, c = tid & 63;
        size_t t = (size_t)b * Ss + (size_t)i * CH + c;
        const float* kr = g_k + t * Mm;
        const float* vr = g_v + t * Mm;
        float nk = 0.f, nv = 0.f;
        for (int d = 0; d < Mm; d++) {
            float a = kr[d]; nk += a * a;
            float u = vr[d]; nv += u * u;
        }
        sik[tid] = 1.f / fmaxf(sqrtf(nk), 1e-12f);
        siv[tid] = 1.f / fmaxf(sqrtf(nv), 1e-12f);
        float wv = g_w[t];
        sw[tid] = wv;
        red[tid] = wv;
    }
    __syncthreads();
    for (int o = 128; o; o >>= 1) { if (tid < o) red[tid] += red[tid + o]; __syncthreads(); }
    float sumw = red[0];
    float wsum = fmaxf(sumw, 1e-8f);
    __syncthreads();

    // phase 2: threads 0..127 accumulate k dims, 128..255 accumulate v dims (coalesced)
    int d = tid & 127;
    bool isv = (tid >= 128);
    const float* src = isv ? g_v : g_k;
    const float* inv = isv ? siv : sik;
    float acc = 0.f;
    for (int j = 0; j < 256; j++) {
        int b = j >> 6, c = j & 63;
        size_t tj = (size_t)b * Ss + (size_t)i * CH + c;
        acc += sw[j] * inv[j] * src[tj * Mm + d];
    }
    float mean = acc / wsum;
    red[tid] = mean * mean;
    __syncthreads();
    for (int o = 64; o; o >>= 1) { if ((tid & 127) < o) red[tid] += red[tid + o]; __syncthreads(); }
    float nrm = fmaxf(sqrtf(red[isv ? 128 : 0]), 1e-12f);
    float outv = mean / nrm;
    if (isv) g_Vagg[i * Mm + d] = outv;
    else     g_Kagg[i * Mm + d] = outv;
    if (tid == 0) g_ws[i] = sumw * (1.f / 256.f);
}

// ---------------- mean write strength ----------------
__global__ void meanws_kernel(float* __restrict__ out, int out_size)
{
    if (threadIdx.x == 0 && out_size > NTOK * Hh) {
        float s = 0.f;
        for (int j = 0; j < NC; j++) s += g_ws[j];
        out[(size_t)NTOK * Hh] = s / (float)NC;
    }
}

// ---------------- attention read: r_t = softmax(beta q_t . Kagg[active]) @ Vagg ----------------
// grid (chunk, batch); 256 threads = 8 warps, each warp handles 8 tokens.
__global__ void __launch_bounds__(256) attn_kernel(const float* __restrict__ log_beta,
                                                   float* __restrict__ r_out)
{
    extern __shared__ float sm[];
    float* ksm = sm;              // 64*129
    float* vsm = ksm + 64 * 129;  // 64*129
    float* qsm = vsm + 64 * 129;  // 64*129
    float* psm = qsm + 64 * 129;  // 8*64
    __shared__ float str[64];
    __shared__ float ssum;

    int i = blockIdx.x;   // chunk
    int bb = blockIdx.y;  // batch
    int tid = threadIdx.x;
    float beta = expf(log_beta[0]);

    for (int idx = tid; idx < 64 * 128; idx += 256) {
        int j = idx >> 7, d = idx & 127;
        ksm[j * 129 + d] = g_Kagg[idx];
        vsm[j * 129 + d] = g_Vagg[idx];
    }
    size_t tbase = (size_t)bb * Ss + (size_t)i * CH;
    for (int idx = tid; idx < 64 * 128; idx += 256) {
        int c = idx >> 7, d = idx & 127;
        qsm[c * 129 + d] = g_q[(tbase + c) * Mm + d];
    }
    if (tid < 64) {
        float dc = powf(0.999f, 64.f);
        float s = 0.f;
        if (tid < i) s = g_ws[tid] * powf(dc, (float)(i - 1 - tid));
        str[tid] = s;
    }
    __syncthreads();
    if (tid == 0) {
        float s = 0.f;
        for (int j = 0; j < 64; j++) s += str[j];
        ssum = s;
    }
    __syncthreads();

    bool valid = (ssum >= 1e-8f);
    int w = tid >> 5, lane = tid & 31;
    float m0ok = (str[lane] > 1e-8f)      ? 0.f : -1e9f;
    float m1ok = (str[lane + 32] > 1e-8f) ? 0.f : -1e9f;
    const float* k0 = ksm + lane * 129;
    const float* k1 = ksm + (lane + 32) * 129;

    for (int it = 0; it < 8; it++) {
        int c = w * 8 + it;
        const float* qrow = qsm + c * 129;
        float s0 = 0.f, s1 = 0.f;
#pragma unroll 8
        for (int d = 0; d < 128; d++) {
            float qd = qrow[d];
            s0 += qd * k0[d];
            s1 += qd * k1[d];
        }
        s0 = s0 * beta + m0ok;
        s1 = s1 * beta + m1ok;
        float mx = fmaxf(s0, s1);
#pragma unroll
        for (int o = 16; o; o >>= 1) mx = fmaxf(mx, __shfl_xor_sync(0xffffffffu, mx, o));
        float p0 = expf(s0 - mx);
        float p1 = expf(s1 - mx);
        float sum = p0 + p1;
#pragma unroll
        for (int o = 16; o; o >>= 1) sum += __shfl_xor_sync(0xffffffffu, sum, o);
        float invs = 1.f / sum;
        psm[w * 64 + lane]      = p0 * invs;
        psm[w * 64 + lane + 32] = p1 * invs;
        __syncwarp();
        float a0 = 0.f, a1 = 0.f, a2 = 0.f, a3 = 0.f;
#pragma unroll 4
        for (int j = 0; j < 64; j++) {
            float pj = psm[w * 64 + j];
            const float* vr = vsm + j * 129 + lane;
            a0 += pj * vr[0];
            a1 += pj * vr[32];
            a2 += pj * vr[64];
            a3 += pj * vr[96];
        }
        if (!valid) { a0 = a1 = a2 = a3 = 0.f; }
        float* ro = r_out + (tbase + c) * Mm;
        ro[lane]      = a0;
        ro[lane + 32] = a1;
        ro[lane + 64] = a2;
        ro[lane + 96] = a3;
        __syncwarp();
    }
}

// ---------------- per-token output norm clamp (deterministic, no atomics) ----------------
__global__ void __launch_bounds__(256) norm_kernel(float* __restrict__ out)
{
    __shared__ float red[256];
    size_t t = blockIdx.x;
    float* row = out + t * (size_t)Hh;
    int tid = threadIdx.x;
    float4* r4 = (float4*)row;
    float ss = 0.f;
#pragma unroll
    for (int u = 0; u < 2; u++) {
        float4 v = r4[tid + u * 256];
        ss += v.x * v.x + v.y * v.y + v.z * v.z + v.w * v.w;
    }
    red[tid] = ss;
    __syncthreads();
    for (int o = 128; o; o >>= 1) { if (tid < o) red[tid] += red[tid + o]; __syncthreads(); }
    float nrm = fmaxf(sqrtf(red[0]), 1e-6f);
    float sc = fminf(10.f / nrm, 1.f);
    if (sc < 1.f) {
#pragma unroll
        for (int u = 0; u < 2; u++) {
            float4 v = r4[tid + u * 256];
            v.x *= sc; v.y *= sc; v.z *= sc; v.w *= sc;
            r4[tid + u * 256] = v;
        }
    }
}

// ---------------- launch ----------------
extern "C" void kernel_launch(void* const* d_in, const int* in_sizes, int n_in,
                              void* d_out, int out_size)
{
    const float* x  = (const float*)d_in[0];
    const float* Wq = (const float*)d_in[1];
    const float* Wk = (const float*)d_in[2];
    const float* Wv = (const float*)d_in[3];
    const float* Wo = (const float*)d_in[4];
    const float* Wg = (const float*)d_in[5];
    const float* gb = (const float*)d_in[6];
    const float* lb = (const float*)d_in[7];
    float* out = (float*)d_out;

    float *pr;
    cudaGetSymbolAddress((void**)&pr, g_r);

    const int ATTN_SMEM = (3 * 64 * 129 + 8 * 64) * 4;  // ~99 KB
    cudaFuncSetAttribute(attn_kernel, cudaFuncAttributeMaxDynamicSharedMemorySize, ATTN_SMEM);

    // 1. projections q/k/v (384 blocks)
    proj_gemm<<<dim3(NTOK / 128, 1, 3), 256>>>(x, Wq, Wk, Wv);
    // 2. gate
    gate_kernel<<<NTOK / 8, 256>>>(x, Wg, gb);
    // 3. per-chunk write aggregates
    agg_kernel<<<NC, 256>>>();
    // 4. mean write strength (second output scalar)
    meanws_kernel<<<1, 32>>>(out, out_size);
    // 5. attention reads (fully parallel across chunks)
    attn_kernel<<<dim3(NC, Bb), 256, ATTN_SMEM>>>(lb, pr);
    // 6. output projection
    sgemm_nt<<<dim3(NTOK / 128, Hh / 128), 256>>>(pr, Wo, out, Mm, Hh);
    // 7. norm clamp
    norm_kernel<<<NTOK, 256>>>(out);
}

// round 5
// speedup vs baseline: 3.2501x; 2.0838x over previous
#include <cuda_runtime.h>
#include <cuda_bf16.h>
#include <math.h>
#include <stdint.h>

#define Bb 4
#define Ss 4096
#define Hh 2048
#define Mm 128
#define CH 64
#define NC 64
#define NSLOTS 64
#define NTOK (Bb*Ss)   // 16384

// ---------------- scratch (static device globals; no allocation) ----------------
__device__ float g_q[NTOK*Mm];
__device__ float g_k[NTOK*Mm];
__device__ float g_v[NTOK*Mm];
__device__ float g_w[NTOK];
__device__ float g_r[NTOK*Mm];
__device__ float g_Kagg[NSLOTS*Mm];
__device__ float g_Vagg[NSLOTS*Mm];
__device__ float g_ws[NSLOTS];

// ================= helpers =================
__device__ __forceinline__ uint32_t smem_u32(const void* p){
    uint32_t a;
    asm("{ .reg .u64 t; cvta.to.shared.u64 t, %1; cvt.u32.u64 %0, t; }" : "=r"(a) : "l"(p));
    return a;
}
// pack two floats to bf16x2 (x -> low half, y -> high half, matching ldmatrix b32 layout)
__device__ __forceinline__ uint32_t bf2(float x, float y){
    uint32_t r; asm("cvt.rn.bf16x2.f32 %0, %1, %2;" : "=r"(r) : "f"(y), "f"(x)); return r;
}
__device__ __forceinline__ uint32_t swz(uint32_t x){ return x ^ ((x >> 3) & 0x70); }

#define LDSM4(r, addr) \
    asm volatile("ldmatrix.sync.aligned.m8n8.x4.shared.b16 {%0,%1,%2,%3}, [%4];" \
        : "=r"((r)[0]), "=r"((r)[1]), "=r"((r)[2]), "=r"((r)[3]) : "r"(addr))

#define MMA16816(d, a, b0, b1) \
    asm volatile("mma.sync.aligned.m16n8k16.row.col.f32.bf16.bf16.f32 " \
        "{%0,%1,%2,%3}, {%4,%5,%6,%7}, {%8,%9}, {%0,%1,%2,%3};" \
        : "+f"((d)[0]), "+f"((d)[1]), "+f"((d)[2]), "+f"((d)[3]) \
        : "r"((a)[0]), "r"((a)[1]), "r"((a)[2]), "r"((a)[3]), "r"(b0), "r"(b1))

#define TILE_B   16384   // 128 rows x 128B ([hi 64B | lo 64B]) per tile
#define STG_B    32768   // A tile + B tile
#define GEMM_SMEM 65536  // 2 stages

// ============ bf16-split tensor-core GEMM: C[128x128] tile = A[M,K] @ Bw[128,K]^T ============
// fp32-accurate via hi*hi + hi*lo + lo*hi (2-term bf16 split), fp32 accumulate.
__device__ __forceinline__ void gemm_body_mma(const float* __restrict__ A,
                                              const float* __restrict__ Bw,
                                              float* __restrict__ C,
                                              int K, int ldc, int m0)
{
    extern __shared__ __align__(1024) char smem[];
    int tid = threadIdx.x;
    int w = tid >> 5, l = tid & 31;
    const float* Arow = A + (size_t)m0 * K;
    const int NB = K >> 5;

    float4 ra[4], rb[4];
    float acc[2][8][4];
#pragma unroll
    for (int mi = 0; mi < 2; mi++)
#pragma unroll
        for (int nj = 0; nj < 8; nj++)
#pragma unroll
            for (int c = 0; c < 4; c++) acc[mi][nj][c] = 0.f;

    // ---- load K-block kb into registers ----
    auto load_g = [&](int k0) {
#pragma unroll
        for (int u = 0; u < 4; u++) {
            int idx = tid + (u << 8);
            int row = idx >> 3, c4 = idx & 7;
            size_t g = (size_t)row * K + k0 + (c4 << 2);
            ra[u] = *(const float4*)(Arow + g);
            rb[u] = *(const float4*)(Bw + g);
        }
    };
    // ---- split to bf16 hi/lo and store swizzled into stage ----
    auto store_s = [&](char* sb) {
        char* sA = sb;
        char* sB = sb + TILE_B;
#pragma unroll
        for (int u = 0; u < 4; u++) {
            int idx = tid + (u << 8);
            int row = idx >> 3, c4 = idx & 7;
            uint32_t base = (uint32_t)(row << 7) + (c4 << 3);
            uint32_t hoff = swz(base), loff = swz(base + 64);
            {
                float4 av = ra[u];
                uint32_t h0 = bf2(av.x, av.y), h1 = bf2(av.z, av.w);
                float lx = av.x - __uint_as_float(h0 << 16);
                float ly = av.y - __uint_as_float(h0 & 0xffff0000u);
                float lz = av.z - __uint_as_float(h1 << 16);
                float lw = av.w - __uint_as_float(h1 & 0xffff0000u);
                *(uint2*)(sA + hoff) = make_uint2(h0, h1);
                *(uint2*)(sA + loff) = make_uint2(bf2(lx, ly), bf2(lz, lw));
            }
            {
                float4 bv = rb[u];
                uint32_t h0 = bf2(bv.x, bv.y), h1 = bf2(bv.z, bv.w);
                float lx = bv.x - __uint_as_float(h0 << 16);
                float ly = bv.y - __uint_as_float(h0 & 0xffff0000u);
                float lz = bv.z - __uint_as_float(h1 << 16);
                float lw = bv.w - __uint_as_float(h1 & 0xffff0000u);
                *(uint2*)(sB + hoff) = make_uint2(h0, h1);
                *(uint2*)(sB + loff) = make_uint2(bf2(lx, ly), bf2(lz, lw));
            }
        }
    };

    int wm = (w >> 1) << 5;   // warp m offset: 0,32,64,96
    int wn = (w & 1) << 6;    // warp n offset: 0,64
    int lr = l & 15, lh = l >> 4;

    load_g(0);
    store_s(smem);

    for (int kb = 0; kb < NB; kb++) {
        __syncthreads();
        char* cur = smem + (size_t)(kb & 1) * STG_B;
        bool more = (kb + 1 < NB);
        if (more) load_g((kb + 1) << 5);

        uint32_t sAu = smem_u32(cur);
        uint32_t sBu = sAu + TILE_B;
#pragma unroll
        for (int ks = 0; ks < 2; ks++) {
            uint32_t kbyte = (uint32_t)(ks << 5) + (lh << 4);
            uint32_t Ah[2][4], Al[2][4], Bh[4][4], Bl[4][4];
#pragma unroll
            for (int t = 0; t < 2; t++) {
                uint32_t ro = (uint32_t)((wm + (t << 4) + lr) << 7) + kbyte;
                LDSM4(Ah[t], sAu + swz(ro));
                LDSM4(Al[t], sAu + swz(ro + 64));
            }
#pragma unroll
            for (int g = 0; g < 4; g++) {
                uint32_t ro = (uint32_t)((wn + (g << 4) + lr) << 7) + kbyte;
                LDSM4(Bh[g], sBu + swz(ro));
                LDSM4(Bl[g], sBu + swz(ro + 64));
            }
#pragma unroll
            for (int mi = 0; mi < 2; mi++)
#pragma unroll
                for (int nj = 0; nj < 8; nj++) {
                    int g = nj >> 1, p = nj & 1;
                    MMA16816(acc[mi][nj], Ah[mi], Bh[g][p], Bh[g][p + 2]);
                    MMA16816(acc[mi][nj], Ah[mi], Bl[g][p], Bl[g][p + 2]);
                    MMA16816(acc[mi][nj], Al[mi], Bh[g][p], Bh[g][p + 2]);
                }
        }
        if (more) store_s(smem + (size_t)((kb + 1) & 1) * STG_B);
    }

    // ---- epilogue: direct global stores ----
#pragma unroll
    for (int mi = 0; mi < 2; mi++) {
        int r0 = wm + (mi << 4) + (l >> 2);
#pragma unroll
        for (int nj = 0; nj < 8; nj++) {
            float* p = C + (size_t)(m0 + r0) * ldc + wn + (nj << 3) + ((l & 3) << 1);
            *(float2*)p = make_float2(acc[mi][nj][0], acc[mi][nj][1]);
            *(float2*)(p + (size_t)8 * ldc) = make_float2(acc[mi][nj][2], acc[mi][nj][3]);
        }
    }
}

__global__ void __launch_bounds__(256) proj_mma(const float* __restrict__ x,
                                                const float* __restrict__ Wq,
                                                const float* __restrict__ Wk,
                                                const float* __restrict__ Wv)
{
    const float* W; float* C;
    if (blockIdx.z == 0)      { W = Wq; C = g_q; }
    else if (blockIdx.z == 1) { W = Wk; C = g_k; }
    else                      { W = Wv; C = g_v; }
    gemm_body_mma(x, W, C, Hh, Mm, blockIdx.x * 128);
}

__global__ void __launch_bounds__(256) out_mma(const float* __restrict__ Wo,
                                               float* __restrict__ out)
{
    int n0 = blockIdx.y * 128;
    gemm_body_mma(g_r, Wo + (size_t)n0 * Mm, out + n0, Mm, Hh, blockIdx.x * 128);
}

// ---------------- gate: w[t] = sigmoid(x_t . Wg + b) ----------------
__global__ void __launch_bounds__(256) gate_kernel(const float* __restrict__ x,
                                                   const float* __restrict__ Wg,
                                                   const float* __restrict__ gb)
{
    int gwarp = (blockIdx.x * 256 + threadIdx.x) >> 5;
    int lane = threadIdx.x & 31;
    if (gwarp >= NTOK) return;
    const float4* x4 = (const float4*)(x + (size_t)gwarp * Hh);
    const float4* w4 = (const float4*)Wg;
    float s = 0.f;
    for (int d = lane; d < Hh / 4; d += 32) {
        float4 a = x4[d], b = w4[d];
        s += a.x * b.x + a.y * b.y + a.z * b.z + a.w * b.w;
    }
#pragma unroll
    for (int o = 16; o; o >>= 1) s += __shfl_xor_sync(0xffffffffu, s, o);
    if (lane == 0) g_w[gwarp] = 1.f / (1.f + expf(-(s + gb[0])));
}

// ---------------- per-chunk aggregates: k_agg, v_agg, write_str ----------------
__global__ void __launch_bounds__(256) agg_kernel()
{
    int i = blockIdx.x;
    int tid = threadIdx.x;
    __shared__ float sw[256];
    __shared__ float sik[256];
    __shared__ float siv[256];
    __shared__ float red[256];
    {
        int b = tid >> 6, c = tid & 63;
        size_t t = (size_t)b * Ss + (size_t)i * CH + c;
        const float* kr = g_k + t * Mm;
        const float* vr = g_v + t * Mm;
        float nk = 0.f, nv = 0.f;
        for (int d = 0; d < Mm; d++) {
            float a = kr[d]; nk += a * a;
            float u = vr[d]; nv += u * u;
        }
        sik[tid] = 1.f / fmaxf(sqrtf(nk), 1e-12f);
        siv[tid] = 1.f / fmaxf(sqrtf(nv), 1e-12f);
        float wv = g_w[t];
        sw[tid] = wv;
        red[tid] = wv;
    }
    __syncthreads();
    for (int o = 128; o; o >>= 1) { if (tid < o) red[tid] += red[tid + o]; __syncthreads(); }
    float sumw = red[0];
    float wsum = fmaxf(sumw, 1e-8f);
    __syncthreads();

    int d = tid & 127;
    bool isv = (tid >= 128);
    const float* src = isv ? g_v : g_k;
    const float* inv = isv ? siv : sik;
    float acc = 0.f;
    for (int j = 0; j < 256; j++) {
        size_t tj = (size_t)(j >> 6) * Ss + (size_t)i * CH + (j & 63);
        acc += sw[j] * inv[j] * src[tj * Mm + d];
    }
    float mean = acc / wsum;
    red[tid] = mean * mean;
    __syncthreads();
    for (int o = 64; o; o >>= 1) { if ((tid & 127) < o) red[tid] += red[tid + o]; __syncthreads(); }
    float nrm = fmaxf(sqrtf(red[isv ? 128 : 0]), 1e-12f);
    float outv = mean / nrm;
    if (isv) g_Vagg[i * Mm + d] = outv;
    else     g_Kagg[i * Mm + d] = outv;
    if (tid == 0) g_ws[i] = sumw * (1.f / 256.f);
}

// ---------------- mean write strength ----------------
__global__ void meanws_kernel(float* __restrict__ out, int out_size)
{
    if (threadIdx.x == 0 && out_size > NTOK * Hh) {
        float s = 0.f;
        for (int j = 0; j < NC; j++) s += g_ws[j];
        out[(size_t)NTOK * Hh] = s / (float)NC;
    }
}

// ---------------- attention read ----------------
__global__ void __launch_bounds__(256) attn_kernel(const float* __restrict__ log_beta,
                                                   float* __restrict__ r_out)
{
    extern __shared__ float sm[];
    float* ksm = sm;
    float* vsm = ksm + 64 * 129;
    float* qsm = vsm + 64 * 129;
    float* psm = qsm + 64 * 129;
    __shared__ float str[64];
    __shared__ float ssum;

    int i = blockIdx.x;
    int bb = blockIdx.y;
    int tid = threadIdx.x;
    float beta = expf(log_beta[0]);

    for (int idx = tid; idx < 64 * 128; idx += 256) {
        int j = idx >> 7, d = idx & 127;
        ksm[j * 129 + d] = g_Kagg[idx];
        vsm[j * 129 + d] = g_Vagg[idx];
    }
    size_t tbase = (size_t)bb * Ss + (size_t)i * CH;
    for (int idx = tid; idx < 64 * 128; idx += 256) {
        int c = idx >> 7, d = idx & 127;
        qsm[c * 129 + d] = g_q[(tbase + c) * Mm + d];
    }
    if (tid < 64) {
        float dc = powf(0.999f, 64.f);
        float s = 0.f;
        if (tid < i) s = g_ws[tid] * powf(dc, (float)(i - 1 - tid));
        str[tid] = s;
    }
    __syncthreads();
    if (tid == 0) {
        float s = 0.f;
        for (int j = 0; j < 64; j++) s += str[j];
        ssum = s;
    }
    __syncthreads();

    bool valid = (ssum >= 1e-8f);
    int w = tid >> 5, lane = tid & 31;
    float m0ok = (str[lane] > 1e-8f)      ? 0.f : -1e9f;
    float m1ok = (str[lane + 32] > 1e-8f) ? 0.f : -1e9f;
    const float* k0 = ksm + lane * 129;
    const float* k1 = ksm + (lane + 32) * 129;

    for (int it = 0; it < 8; it++) {
        int c = w * 8 + it;
        const float* qrow = qsm + c * 129;
        float s0 = 0.f, s1 = 0.f;
#pragma unroll 8
        for (int d = 0; d < 128; d++) {
            float qd = qrow[d];
            s0 += qd * k0[d];
            s1 += qd * k1[d];
        }
        s0 = s0 * beta + m0ok;
        s1 = s1 * beta + m1ok;
        float mx = fmaxf(s0, s1);
#pragma unroll
        for (int o = 16; o; o >>= 1) mx = fmaxf(mx, __shfl_xor_sync(0xffffffffu, mx, o));
        float p0 = expf(s0 - mx);
        float p1 = expf(s1 - mx);
        float sum = p0 + p1;
#pragma unroll
        for (int o = 16; o; o >>= 1) sum += __shfl_xor_sync(0xffffffffu, sum, o);
        float invs = 1.f / sum;
        psm[w * 64 + lane]      = p0 * invs;
        psm[w * 64 + lane + 32] = p1 * invs;
        __syncwarp();
        float a0 = 0.f, a1 = 0.f, a2 = 0.f, a3 = 0.f;
#pragma unroll 4
        for (int j = 0; j < 64; j++) {
            float pj = psm[w * 64 + j];
            const float* vr = vsm + j * 129 + lane;
            a0 += pj * vr[0];
            a1 += pj * vr[32];
            a2 += pj * vr[64];
            a3 += pj * vr[96];
        }
        if (!valid) { a0 = a1 = a2 = a3 = 0.f; }
        float* ro = r_out + (tbase + c) * Mm;
        ro[lane]      = a0;
        ro[lane + 32] = a1;
        ro[lane + 64] = a2;
        ro[lane + 96] = a3;
        __syncwarp();
    }
}

// ---------------- per-token output norm clamp ----------------
__global__ void __launch_bounds__(256) norm_kernel(float* __restrict__ out)
{
    __shared__ float red[256];
    size_t t = blockIdx.x;
    float* row = out + t * (size_t)Hh;
    int tid = threadIdx.x;
    float4* r4 = (float4*)row;
    float ss = 0.f;
#pragma unroll
    for (int u = 0; u < 2; u++) {
        float4 v = r4[tid + u * 256];
        ss += v.x * v.x + v.y * v.y + v.z * v.z + v.w * v.w;
    }
    red[tid] = ss;
    __syncthreads();
    for (int o = 128; o; o >>= 1) { if (tid < o) red[tid] += red[tid + o]; __syncthreads(); }
    float nrm = fmaxf(sqrtf(red[0]), 1e-6f);
    float sc = fminf(10.f / nrm, 1.f);
    if (sc < 1.f) {
#pragma unroll
        for (int u = 0; u < 2; u++) {
            float4 v = r4[tid + u * 256];
            v.x *= sc; v.y *= sc; v.z *= sc; v.w *= sc;
            r4[tid + u * 256] = v;
        }
    }
}

// ---------------- launch ----------------
extern "C" void kernel_launch(void* const* d_in, const int* in_sizes, int n_in,
                              void* d_out, int out_size)
{
    const float* x  = (const float*)d_in[0];
    const float* Wq = (const float*)d_in[1];
    const float* Wk = (const float*)d_in[2];
    const float* Wv = (const float*)d_in[3];
    const float* Wo = (const float*)d_in[4];
    const float* Wg = (const float*)d_in[5];
    const float* gb = (const float*)d_in[6];
    const float* lb = (const float*)d_in[7];
    float* out = (float*)d_out;

    float* pr;
    cudaGetSymbolAddress((void**)&pr, g_r);

    const int ATTN_SMEM = (3 * 64 * 129 + 8 * 64) * 4;
    cudaFuncSetAttribute(attn_kernel, cudaFuncAttributeMaxDynamicSharedMemorySize, ATTN_SMEM);
    cudaFuncSetAttribute(proj_mma, cudaFuncAttributeMaxDynamicSharedMemorySize, GEMM_SMEM);
    cudaFuncSetAttribute(out_mma,  cudaFuncAttributeMaxDynamicSharedMemorySize, GEMM_SMEM);

    // 1. projections q/k/v on tensor cores (bf16x3 split)
    proj_mma<<<dim3(NTOK / 128, 1, 3), 256, GEMM_SMEM>>>(x, Wq, Wk, Wv);
    // 2. gate
    gate_kernel<<<NTOK / 8, 256>>>(x, Wg, gb);
    // 3. per-chunk write aggregates
    agg_kernel<<<NC, 256>>>();
    // 4. mean write strength
    meanws_kernel<<<1, 32>>>(out, out_size);
    // 5. attention reads
    attn_kernel<<<dim3(NC, Bb), 256, ATTN_SMEM>>>(lb, pr);
    // 6. output projection on tensor cores
    out_mma<<<dim3(NTOK / 128, Hh / 128), 256, GEMM_SMEM>>>(Wo, out);
    // 7. norm clamp
    norm_kernel<<<NTOK, 256>>>(out);
}

// round 6
// speedup vs baseline: 3.4965x; 1.0758x over previous
#include <cuda_runtime.h>
#include <cuda_bf16.h>
#include <math.h>
#include <stdint.h>

#define Bb 4
#define Ss 4096
#define Hh 2048
#define Mm 128
#define CH 64
#define NC 64
#define NSLOTS 64
#define NTOK (Bb*Ss)   // 16384

// ---------------- scratch (static device globals; no allocation) ----------------
__device__ float g_q[NTOK*Mm];
__device__ float g_k[NTOK*Mm];
__device__ float g_v[NTOK*Mm];
__device__ float g_w[NTOK];
__device__ float g_r[NTOK*Mm];
__device__ float g_Kagg[NSLOTS*Mm];
__device__ float g_Vagg[NSLOTS*Mm];
__device__ float g_ws[NSLOTS];
// split (bf16 hi/lo) operands in smem-tile-ready layout:
// row r, kblock kb (32 K-elems): 128B = [hi: 32 bf16][lo: 32 bf16] at ((r*NB)+kb)*128
__device__ __align__(128) unsigned char g_xs [(size_t)NTOK * Hh * 4];   // 128 MB
__device__ __align__(128) unsigned char g_rs [(size_t)NTOK * Mm * 4];   // 8 MB
__device__ __align__(128) unsigned char g_wqs[(size_t)Mm * Hh * 4];
__device__ __align__(128) unsigned char g_wks[(size_t)Mm * Hh * 4];
__device__ __align__(128) unsigned char g_wvs[(size_t)Mm * Hh * 4];
__device__ __align__(128) unsigned char g_wos[(size_t)Hh * Mm * 4];

// ================= helpers =================
__device__ __forceinline__ uint32_t smem_u32(const void* p){
    uint32_t a;
    asm("{ .reg .u64 t; cvta.to.shared.u64 t, %1; cvt.u32.u64 %0, t; }" : "=r"(a) : "l"(p));
    return a;
}
// pack two floats to bf16x2 (x -> low half, y -> high half)
__device__ __forceinline__ uint32_t bf2(float x, float y){
    uint32_t r; asm("cvt.rn.bf16x2.f32 %0, %1, %2;" : "=r"(r) : "f"(y), "f"(x)); return r;
}
__device__ __forceinline__ uint32_t swz(uint32_t x){ return x ^ ((x >> 3) & 0x70); }

// split 8 consecutive floats into hi/lo bf16 16B words
__device__ __forceinline__ void pack8(float4 a0, float4 a1, uint4& h, uint4& lo){
    h.x = bf2(a0.x, a0.y); h.y = bf2(a0.z, a0.w);
    h.z = bf2(a1.x, a1.y); h.w = bf2(a1.z, a1.w);
    float l0 = a0.x - __uint_as_float(h.x << 16);
    float l1 = a0.y - __uint_as_float(h.x & 0xffff0000u);
    float l2 = a0.z - __uint_as_float(h.y << 16);
    float l3 = a0.w - __uint_as_float(h.y & 0xffff0000u);
    float l4 = a1.x - __uint_as_float(h.z << 16);
    float l5 = a1.y - __uint_as_float(h.z & 0xffff0000u);
    float l6 = a1.z - __uint_as_float(h.w << 16);
    float l7 = a1.w - __uint_as_float(h.w & 0xffff0000u);
    lo.x = bf2(l0, l1); lo.y = bf2(l2, l3); lo.z = bf2(l4, l5); lo.w = bf2(l6, l7);
}

#define LDSM4(r, addr) \
    asm volatile("ldmatrix.sync.aligned.m8n8.x4.shared.b16 {%0,%1,%2,%3}, [%4];" \
        : "=r"((r)[0]), "=r"((r)[1]), "=r"((r)[2]), "=r"((r)[3]) : "r"(addr))

#define MMA16816(d, a, b0, b1) \
    asm volatile("mma.sync.aligned.m16n8k16.row.col.f32.bf16.bf16.f32 " \
        "{%0,%1,%2,%3}, {%4,%5,%6,%7}, {%8,%9}, {%0,%1,%2,%3};" \
        : "+f"((d)[0]), "+f"((d)[1]), "+f"((d)[2]), "+f"((d)[3]) \
        : "r"((a)[0]), "r"((a)[1]), "r"((a)[2]), "r"((a)[3]), "r"(b0), "r"(b1))

#define CP16(dst, src) \
    asm volatile("cp.async.cg.shared.global [%0], [%1], 16;" :: "r"(dst), "l"(src) : "memory")
#define CP_COMMIT() asm volatile("cp.async.commit_group;" ::: "memory")
#define CP_WAIT3()  asm volatile("cp.async.wait_group 3;" ::: "memory")

#define NSTG 4
#define STAGE_B 32768     // A tile 16KB + B tile 16KB
#define GEMM_SMEM (NSTG * STAGE_B)   // 128KB

// ============ pre-split bf16x3 tensor-core GEMM: C[128x128] tile = A @ B^T ============
__device__ __forceinline__ void gemm_split(const unsigned char* __restrict__ As,
                                           const unsigned char* __restrict__ Bs,
                                           float* __restrict__ C,
                                           int NB, int ldc, int m0)
{
    extern __shared__ __align__(1024) char smem[];
    int tid = threadIdx.x;
    int w = tid >> 5, l = tid & 31;
    uint32_t smb = smem_u32(smem);

    unsigned long long gA = (unsigned long long)__cvta_generic_to_global(As);
    unsigned long long gB = (unsigned long long)__cvta_generic_to_global(Bs);

    auto issue = [&](int kb) {
        uint32_t st = smb + (uint32_t)(kb & (NSTG - 1)) * STAGE_B;
#pragma unroll
        for (int u = 0; u < 4; u++) {
            int c = tid + (u << 8);               // 0..1023
            int row = c >> 3;
            uint32_t seg = (uint32_t)(c & 7) << 4;
            unsigned long long srcA = gA + ((unsigned long long)(m0 + row) * NB + kb) * 128ull + seg;
            unsigned long long srcB = gB + ((unsigned long long)row * NB + kb) * 128ull + seg;
            uint32_t d = swz(((uint32_t)row << 7) + seg);
            CP16(st + d, srcA);
            CP16(st + 16384 + d, srcB);
        }
    };

    float acc[2][8][4];
#pragma unroll
    for (int mi = 0; mi < 2; mi++)
#pragma unroll
        for (int nj = 0; nj < 8; nj++)
#pragma unroll
            for (int cc = 0; cc < 4; cc++) acc[mi][nj][cc] = 0.f;

    int wm = (w >> 1) << 5;   // 0,32,64,96
    int wn = (w & 1) << 6;    // 0,64
    int lr = l & 15, lh = l >> 4;

#pragma unroll
    for (int s = 0; s < NSTG; s++) { if (s < NB) issue(s); CP_COMMIT(); }

    for (int kb = 0; kb < NB; kb++) {
        CP_WAIT3();
        __syncthreads();
        uint32_t sAu = smb + (uint32_t)(kb & (NSTG - 1)) * STAGE_B;
        uint32_t sBu = sAu + 16384;
#pragma unroll
        for (int ks = 0; ks < 2; ks++) {
            uint32_t kbyte = (uint32_t)(ks << 5) + (lh << 4);
            uint32_t Ah[2][4], Al[2][4], Bh[4][4], Bl[4][4];
#pragma unroll
            for (int t = 0; t < 2; t++) {
                uint32_t ro = (uint32_t)((wm + (t << 4) + lr) << 7) + kbyte;
                LDSM4(Ah[t], sAu + swz(ro));
                LDSM4(Al[t], sAu + swz(ro + 64));
            }
#pragma unroll
            for (int g = 0; g < 4; g++) {
                uint32_t ro = (uint32_t)((wn + (g << 4) + lr) << 7) + kbyte;
                LDSM4(Bh[g], sBu + swz(ro));
                LDSM4(Bl[g], sBu + swz(ro + 64));
            }
#pragma unroll
            for (int mi = 0; mi < 2; mi++)
#pragma unroll
                for (int nj = 0; nj < 8; nj++) {
                    int g = nj >> 1, p = nj & 1;
                    MMA16816(acc[mi][nj], Ah[mi], Bh[g][p], Bh[g][p + 2]);
                    MMA16816(acc[mi][nj], Ah[mi], Bl[g][p], Bl[g][p + 2]);
                    MMA16816(acc[mi][nj], Al[mi], Bh[g][p], Bh[g][p + 2]);
                }
        }
        __syncthreads();
        if (kb + NSTG < NB) issue(kb + NSTG);
        CP_COMMIT();
    }

#pragma unroll
    for (int mi = 0; mi < 2; mi++) {
        int r0 = wm + (mi << 4) + (l >> 2);
#pragma unroll
        for (int nj = 0; nj < 8; nj++) {
            float* p = C + (size_t)(m0 + r0) * ldc + wn + (nj << 3) + ((l & 3) << 1);
            *(float2*)p = make_float2(acc[mi][nj][0], acc[mi][nj][1]);
            *(float2*)(p + (size_t)8 * ldc) = make_float2(acc[mi][nj][2], acc[mi][nj][3]);
        }
    }
}

__global__ void __launch_bounds__(256) proj_mma()
{
    const unsigned char* Bs; float* C;
    if (blockIdx.z == 0)      { Bs = g_wqs; C = g_q; }
    else if (blockIdx.z == 1) { Bs = g_wks; C = g_k; }
    else                      { Bs = g_wvs; C = g_v; }
    gemm_split(g_xs, Bs, C, Hh / 32, Mm, blockIdx.x * 128);
}

__global__ void __launch_bounds__(256) out_mma(float* __restrict__ out)
{
    int n0 = blockIdx.y * 128;
    gemm_split(g_rs, g_wos + (size_t)n0 * 4 * 128, out + n0, Mm / 32, Hh, blockIdx.x * 128);
}

// ---------------- split x (tile layout) + fused gate ----------------
__global__ void __launch_bounds__(256) splitx_gate(const float* __restrict__ x,
                                                   const float* __restrict__ Wg,
                                                   const float* __restrict__ gb)
{
    int t = blockIdx.x, tid = threadIdx.x;
    const float4* xr = (const float4*)(x + (size_t)t * Hh);
    const float4* wg = (const float4*)Wg;
    float4 a0 = xr[2 * tid], a1 = xr[2 * tid + 1];
    float4 w0 = wg[2 * tid], w1 = wg[2 * tid + 1];
    float dot = a0.x * w0.x + a0.y * w0.y + a0.z * w0.z + a0.w * w0.w
              + a1.x * w1.x + a1.y * w1.y + a1.z * w1.z + a1.w * w1.w;
    uint4 h, lo; pack8(a0, a1, h, lo);
    size_t base = ((size_t)t * 64 + (tid >> 2)) * 128 + (size_t)(tid & 3) * 16;
    *(uint4*)(g_xs + base)      = h;
    *(uint4*)(g_xs + base + 64) = lo;

    __shared__ float red[8];
#pragma unroll
    for (int o = 16; o; o >>= 1) dot += __shfl_xor_sync(0xffffffffu, dot, o);
    if ((tid & 31) == 0) red[tid >> 5] = dot;
    __syncthreads();
    if (tid == 0) {
        float s = 0.f;
#pragma unroll
        for (int j = 0; j < 8; j++) s += red[j];
        g_w[t] = 1.f / (1.f + expf(-(s + gb[0])));
    }
}

// ---------------- generic split: src[rows x K] f32 -> tile-layout bf16 hi/lo ----------------
__global__ void __launch_bounds__(256) split_mat(const float* __restrict__ src,
                                                 unsigned char* __restrict__ dst,
                                                 int K, int total)
{
    int cpr = K >> 3, nkb = K >> 5;
    for (int g = blockIdx.x * 256 + threadIdx.x; g < total; g += gridDim.x * 256) {
        int row = g / cpr, pos = g - row * cpr;
        const float4* s = (const float4*)(src + (size_t)row * K + (size_t)pos * 8);
        float4 a0 = s[0], a1 = s[1];
        uint4 h, lo; pack8(a0, a1, h, lo);
        size_t base = ((size_t)row * nkb + (pos >> 2)) * 128 + (size_t)(pos & 3) * 16;
        *(uint4*)(dst + base)      = h;
        *(uint4*)(dst + base + 64) = lo;
    }
}

// ---------------- per-chunk aggregates: k_agg, v_agg, write_str ----------------
__global__ void __launch_bounds__(256) agg_kernel()
{
    int i = blockIdx.x;
    int tid = threadIdx.x;
    __shared__ float sw[256];
    __shared__ float sik[256];
    __shared__ float siv[256];
    __shared__ float red[256];
    {
        int b = tid >> 6, c = tid & 63;
        size_t t = (size_t)b * Ss + (size_t)i * CH + c;
        const float* kr = g_k + t * Mm;
        const float* vr = g_v + t * Mm;
        float nk = 0.f, nv = 0.f;
        for (int d = 0; d < Mm; d++) {
            float a = kr[d]; nk += a * a;
            float u = vr[d]; nv += u * u;
        }
        sik[tid] = 1.f / fmaxf(sqrtf(nk), 1e-12f);
        siv[tid] = 1.f / fmaxf(sqrtf(nv), 1e-12f);
        float wv = g_w[t];
        sw[tid] = wv;
        red[tid] = wv;
    }
    __syncthreads();
    for (int o = 128; o; o >>= 1) { if (tid < o) red[tid] += red[tid + o]; __syncthreads(); }
    float sumw = red[0];
    float wsum = fmaxf(sumw, 1e-8f);
    __syncthreads();

    int d = tid & 127;
    bool isv = (tid >= 128);
    const float* src = isv ? g_v : g_k;
    const float* inv = isv ? siv : sik;
    float acc = 0.f;
    for (int j = 0; j < 256; j++) {
        size_t tj = (size_t)(j >> 6) * Ss + (size_t)i * CH + (j & 63);
        acc += sw[j] * inv[j] * src[tj * Mm + d];
    }
    float mean = acc / wsum;
    red[tid] = mean * mean;
    __syncthreads();
    for (int o = 64; o; o >>= 1) { if ((tid & 127) < o) red[tid] += red[tid + o]; __syncthreads(); }
    float nrm = fmaxf(sqrtf(red[isv ? 128 : 0]), 1e-12f);
    float outv = mean / nrm;
    if (isv) g_Vagg[i * Mm + d] = outv;
    else     g_Kagg[i * Mm + d] = outv;
    if (tid == 0) g_ws[i] = sumw * (1.f / 256.f);
}

// ---------------- mean write strength ----------------
__global__ void meanws_kernel(float* __restrict__ out, int out_size)
{
    if (threadIdx.x == 0 && out_size > NTOK * Hh) {
        float s = 0.f;
        for (int j = 0; j < NC; j++) s += g_ws[j];
        out[(size_t)NTOK * Hh] = s / (float)NC;
    }
}

// ---------------- attention read (8 tokens per warp, transposed K, q from gmem) ----------------
#define ATTN_SMEM ((8192 + 8192 + 4096) * 4)   // kt + vsm + psm = 80KB
__global__ void __launch_bounds__(256) attn_kernel(const float* __restrict__ log_beta,
                                                   float* __restrict__ r_out)
{
    extern __shared__ float sm[];
    float* kt  = sm;               // [d][slot] 128x64
    float* vsm = kt + 8192;        // [slot][d] 64x128
    float* psm = vsm + 8192;       // [warp][c8][slot] 8x8x64
    __shared__ float str[64];
    __shared__ float ssum;

    int i = blockIdx.x;   // chunk
    int bb = blockIdx.y;  // batch
    int tid = threadIdx.x;
    float beta = expf(log_beta[0]);

    for (int idx = tid; idx < 8192; idx += 256) {
        int d = idx >> 6, slot = idx & 63;
        kt[idx] = g_Kagg[slot * 128 + d];
    }
    for (int idx = tid; idx < 8192; idx += 256) vsm[idx] = g_Vagg[idx];
    if (tid < 64) {
        float dc = powf(0.999f, 64.f);
        float s = 0.f;
        if (tid < i) s = g_ws[tid] * powf(dc, (float)(i - 1 - tid));
        str[tid] = s;
    }
    __syncthreads();
    if (tid == 0) {
        float s = 0.f;
        for (int j = 0; j < 64; j++) s += str[j];
        ssum = s;
    }
    __syncthreads();

    bool valid = (ssum >= 1e-8f);
    int w = tid >> 5, lane = tid & 31;
    float m0ok = (str[lane] > 1e-8f)      ? 0.f : -1e9f;
    float m1ok = (str[lane + 32] > 1e-8f) ? 0.f : -1e9f;
    size_t tbase = (size_t)bb * Ss + (size_t)i * CH;
    const float* qg = g_q + (tbase + (size_t)w * 8) * Mm;

    // ---- scores: 8 tokens per warp simultaneously ----
    float s0[8], s1[8];
#pragma unroll
    for (int c8 = 0; c8 < 8; c8++) { s0[c8] = 0.f; s1[c8] = 0.f; }
    for (int d4 = 0; d4 < 32; d4++) {
        float kv0[4], kv1[4];
#pragma unroll
        for (int ii = 0; ii < 4; ii++) {
            kv0[ii] = kt[(d4 * 4 + ii) * 64 + lane];
            kv1[ii] = kt[(d4 * 4 + ii) * 64 + 32 + lane];
        }
#pragma unroll
        for (int c8 = 0; c8 < 8; c8++) {
            float4 q = __ldg((const float4*)(qg + (size_t)c8 * Mm + d4 * 4));
            s0[c8] += q.x * kv0[0] + q.y * kv0[1] + q.z * kv0[2] + q.w * kv0[3];
            s1[c8] += q.x * kv1[0] + q.y * kv1[1] + q.z * kv1[2] + q.w * kv1[3];
        }
    }
    // ---- softmax per token ----
#pragma unroll
    for (int c8 = 0; c8 < 8; c8++) {
        float sv0 = s0[c8] * beta + m0ok;
        float sv1 = s1[c8] * beta + m1ok;
        float mx = fmaxf(sv0, sv1);
#pragma unroll
        for (int o = 16; o; o >>= 1) mx = fmaxf(mx, __shfl_xor_sync(0xffffffffu, mx, o));
        float p0 = expf(sv0 - mx);
        float p1 = expf(sv1 - mx);
        float sum = p0 + p1;
#pragma unroll
        for (int o = 16; o; o >>= 1) sum += __shfl_xor_sync(0xffffffffu, sum, o);
        float invs = 1.f / sum;
        psm[w * 512 + c8 * 64 + lane]      = p0 * invs;
        psm[w * 512 + c8 * 64 + 32 + lane] = p1 * invs;
    }
    __syncwarp();

    // ---- weighted V sum: reuse each v row for 8 tokens ----
    float a[8][4];
#pragma unroll
    for (int c8 = 0; c8 < 8; c8++)
#pragma unroll
        for (int cc = 0; cc < 4; cc++) a[c8][cc] = 0.f;
    for (int j = 0; j < 64; j++) {
        float v0 = vsm[j * 128 + lane];
        float v1 = vsm[j * 128 + 32 + lane];
        float v2 = vsm[j * 128 + 64 + lane];
        float v3 = vsm[j * 128 + 96 + lane];
#pragma unroll
        for (int c8 = 0; c8 < 8; c8++) {
            float pj = psm[w * 512 + c8 * 64 + j];
            a[c8][0] += pj * v0; a[c8][1] += pj * v1;
            a[c8][2] += pj * v2; a[c8][3] += pj * v3;
        }
    }
#pragma unroll
    for (int c8 = 0; c8 < 8; c8++) {
        float* ro = r_out + (tbase + (size_t)w * 8 + c8) * Mm;
        float b0 = valid ? a[c8][0] : 0.f;
        float b1 = valid ? a[c8][1] : 0.f;
        float b2 = valid ? a[c8][2] : 0.f;
        float b3 = valid ? a[c8][3] : 0.f;
        ro[lane]      = b0;
        ro[lane + 32] = b1;
        ro[lane + 64] = b2;
        ro[lane + 96] = b3;
    }
}

// ---------------- per-token output norm clamp ----------------
__global__ void __launch_bounds__(256) norm_kernel(float* __restrict__ out)
{
    __shared__ float red[256];
    size_t t = blockIdx.x;
    float* row = out + t * (size_t)Hh;
    int tid = threadIdx.x;
    float4* r4 = (float4*)row;
    float ss = 0.f;
#pragma unroll
    for (int u = 0; u < 2; u++) {
        float4 v = r4[tid + u * 256];
        ss += v.x * v.x + v.y * v.y + v.z * v.z + v.w * v.w;
    }
    red[tid] = ss;
    __syncthreads();
    for (int o = 128; o; o >>= 1) { if (tid < o) red[tid] += red[tid + o]; __syncthreads(); }
    float nrm = fmaxf(sqrtf(red[0]), 1e-6f);
    float sc = fminf(10.f / nrm, 1.f);
    if (sc < 1.f) {
#pragma unroll
        for (int u = 0; u < 2; u++) {
            float4 v = r4[tid + u * 256];
            v.x *= sc; v.y *= sc; v.z *= sc; v.w *= sc;
            r4[tid + u * 256] = v;
        }
    }
}

// ---------------- launch ----------------
extern "C" void kernel_launch(void* const* d_in, const int* in_sizes, int n_in,
                              void* d_out, int out_size)
{
    const float* x  = (const float*)d_in[0];
    const float* Wq = (const float*)d_in[1];
    const float* Wk = (const float*)d_in[2];
    const float* Wv = (const float*)d_in[3];
    const float* Wo = (const float*)d_in[4];
    const float* Wg = (const float*)d_in[5];
    const float* gb = (const float*)d_in[6];
    const float* lb = (const float*)d_in[7];
    float* out = (float*)d_out;

    float* pr;
    cudaGetSymbolAddress((void**)&pr, g_r);
    unsigned char *pwq, *pwk, *pwv, *pwo, *prs;
    cudaGetSymbolAddress((void**)&pwq, g_wqs);
    cudaGetSymbolAddress((void**)&pwk, g_wks);
    cudaGetSymbolAddress((void**)&pwv, g_wvs);
    cudaGetSymbolAddress((void**)&pwo, g_wos);
    cudaGetSymbolAddress((void**)&prs, g_rs);

    cudaFuncSetAttribute(attn_kernel, cudaFuncAttributeMaxDynamicSharedMemorySize, ATTN_SMEM);
    cudaFuncSetAttribute(proj_mma, cudaFuncAttributeMaxDynamicSharedMemorySize, GEMM_SMEM);
    cudaFuncSetAttribute(out_mma,  cudaFuncAttributeMaxDynamicSharedMemorySize, GEMM_SMEM);

    // 1. split x (+ fused gate) and weights into bf16 hi/lo tile layout
    splitx_gate<<<NTOK, 256>>>(x, Wg, gb);
    split_mat<<<128, 256>>>(Wq, pwq, Hh, Mm * (Hh / 8));
    split_mat<<<128, 256>>>(Wk, pwk, Hh, Mm * (Hh / 8));
    split_mat<<<128, 256>>>(Wv, pwv, Hh, Mm * (Hh / 8));
    split_mat<<<128, 256>>>(Wo, pwo, Mm, Hh * (Mm / 8));
    // 2. projections q/k/v (cp.async pipelined bf16x3 MMA)
    proj_mma<<<dim3(NTOK / 128, 1, 3), 256, GEMM_SMEM>>>();
    // 3. per-chunk write aggregates
    agg_kernel<<<NC, 256>>>();
    // 4. mean write strength
    meanws_kernel<<<1, 32>>>(out, out_size);
    // 5. attention reads
    attn_kernel<<<dim3(NC, Bb), 256, ATTN_SMEM>>>(lb, pr);
    // 6. split r, then output projection
    split_mat<<<1024, 256>>>(pr, prs, Mm, NTOK * (Mm / 8));
    out_mma<<<dim3(NTOK / 128, Hh / 128), 256, GEMM_SMEM>>>(out);
    // 7. norm clamp
    norm_kernel<<<NTOK, 256>>>(out);
}

// round 7
// speedup vs baseline: 3.6791x; 1.0522x over previous
#include <cuda_runtime.h>
#include <cuda_bf16.h>
#include <math.h>
#include <stdint.h>

#define Bb 4
#define Ss 4096
#define Hh 2048
#define Mm 128
#define CH 64
#define NC 64
#define NSLOTS 64
#define NTOK (Bb*Ss)   // 16384

// ---------------- scratch (static device globals; no allocation) ----------------
__device__ float g_q[NTOK*Mm];
__device__ float g_k[NTOK*Mm];
__device__ float g_v[NTOK*Mm];
__device__ float g_w[NTOK];
__device__ float g_r[NTOK*Mm];
__device__ float g_Kagg[NSLOTS*Mm];
__device__ float g_Vagg[NSLOTS*Mm];
__device__ float g_ws[NSLOTS];
__device__ __align__(128) unsigned char g_rs [(size_t)NTOK * Mm * 4];   // split r
__device__ __align__(128) unsigned char g_wqs[(size_t)Mm * Hh * 4];
__device__ __align__(128) unsigned char g_wks[(size_t)Mm * Hh * 4];
__device__ __align__(128) unsigned char g_wvs[(size_t)Mm * Hh * 4];
__device__ __align__(128) unsigned char g_wos[(size_t)Hh * Mm * 4];

// ================= helpers =================
__device__ __forceinline__ uint32_t smem_u32(const void* p){
    uint32_t a;
    asm("{ .reg .u64 t; cvta.to.shared.u64 t, %1; cvt.u32.u64 %0, t; }" : "=r"(a) : "l"(p));
    return a;
}
__device__ __forceinline__ uint32_t bf2(float x, float y){
    uint32_t r; asm("cvt.rn.bf16x2.f32 %0, %1, %2;" : "=r"(r) : "f"(y), "f"(x)); return r;
}
__device__ __forceinline__ uint32_t swz(uint32_t x){ return x ^ ((x >> 3) & 0x70); }

// split 4 floats -> hi/lo bf16x2 pairs
__device__ __forceinline__ void pack4(float4 a, uint2& h, uint2& lo){
    h.x = bf2(a.x, a.y); h.y = bf2(a.z, a.w);
    float l0 = a.x - __uint_as_float(h.x << 16);
    float l1 = a.y - __uint_as_float(h.x & 0xffff0000u);
    float l2 = a.z - __uint_as_float(h.y << 16);
    float l3 = a.w - __uint_as_float(h.y & 0xffff0000u);
    lo.x = bf2(l0, l1); lo.y = bf2(l2, l3);
}
__device__ __forceinline__ void pack8(float4 a0, float4 a1, uint4& h, uint4& lo){
    uint2 h0, l0, h1, l1;
    pack4(a0, h0, l0); pack4(a1, h1, l1);
    h.x = h0.x; h.y = h0.y; h.z = h1.x; h.w = h1.y;
    lo.x = l0.x; lo.y = l0.y; lo.z = l1.x; lo.w = l1.y;
}

#define LDSM4(r, addr) \
    asm volatile("ldmatrix.sync.aligned.m8n8.x4.shared.b16 {%0,%1,%2,%3}, [%4];" \
        : "=r"((r)[0]), "=r"((r)[1]), "=r"((r)[2]), "=r"((r)[3]) : "r"(addr))

#define MMA16816(d, a, b0, b1) \
    asm volatile("mma.sync.aligned.m16n8k16.row.col.f32.bf16.bf16.f32 " \
        "{%0,%1,%2,%3}, {%4,%5,%6,%7}, {%8,%9}, {%0,%1,%2,%3};" \
        : "+f"((d)[0]), "+f"((d)[1]), "+f"((d)[2]), "+f"((d)[3]) \
        : "r"((a)[0]), "r"((a)[1]), "r"((a)[2]), "r"((a)[3]), "r"(b0), "r"(b1))

#define CP16(dst, src) \
    asm volatile("cp.async.cg.shared.global [%0], [%1], 16;" :: "r"(dst), "l"(src) : "memory")
#define CP_COMMIT() asm volatile("cp.async.commit_group;" ::: "memory")
#define CP_WAIT1()  asm volatile("cp.async.wait_group 1;" ::: "memory")
#define CP_WAIT3()  asm volatile("cp.async.wait_group 3;" ::: "memory")

// ======================================================================
// mega_proj: fused fp32->bf16 split + gate + q/k/v projections.
// CTA: 64 token rows x (3 outputs x 128 cols). Grid 256.
// smem ring: 3 stages of [A fp32 8KB | B split 3x16KB], + Abf16 8KB + Wg 8KB.
// ======================================================================
#define PNSTG 3
#define AF32_OFF(s)   ((s) * 8192)
#define BSP_OFF(s, z) (24576 + (s) * 49152 + (z) * 16384)
#define ABF_OFF       172032
#define WG_OFF        180224
#define MEGA_SMEM     (180224 + 8192)

__global__ void __launch_bounds__(256, 1) mega_proj(const float* __restrict__ x,
                                                    const float* __restrict__ Wg,
                                                    const float* __restrict__ gb)
{
    extern __shared__ __align__(1024) char smem[];
    __shared__ float gred[64][8];
    int tid = threadIdx.x;
    int w = tid >> 5, l = tid & 31;
    int m0 = blockIdx.x * 64;
    uint32_t smb = smem_u32(smem);
    const int NB = Hh / 32;   // 64

    unsigned long long gX  = (unsigned long long)__cvta_generic_to_global(x);
    unsigned long long gWq = (unsigned long long)__cvta_generic_to_global(g_wqs);
    unsigned long long gWk = (unsigned long long)__cvta_generic_to_global(g_wks);
    unsigned long long gWv = (unsigned long long)__cvta_generic_to_global(g_wvs);

    // preload Wg into smem (8 floats per thread)
    {
        const float4* wg4 = (const float4*)Wg;
        float4 w0 = wg4[2 * tid], w1 = wg4[2 * tid + 1];
        *(float4*)(smem + WG_OFF + tid * 32)      = w0;
        *(float4*)(smem + WG_OFF + tid * 32 + 16) = w1;
    }

    // rows/chunks this thread owns for A-fp32 (fixed across kblocks)
    int rowA0 = tid >> 3;            // 0..31
    int rowA1 = 32 + (tid >> 3);     // 32..63
    int chk   = tid & 7;             // 0..7 (4 floats each)

    auto issue = [&](int kb) {
        int s = kb % PNSTG;
        uint32_t stA = smb + AF32_OFF(s);
        // A fp32: 512 x 16B chunks, 2 per thread
#pragma unroll
        for (int u = 0; u < 2; u++) {
            int row = (u == 0) ? rowA0 : rowA1;
            unsigned long long src = gX + (((unsigned long long)(m0 + row)) * Hh + (unsigned long long)kb * 32 + chk * 4) * 4ull;
            uint32_t d = stA + (uint32_t)row * 128 + (uint32_t)((chk ^ (row & 7)) * 16);
            CP16(d, src);
        }
        // B split: 3 x 1024 chunks, 12 per thread
        unsigned long long gws[3] = {gWq, gWk, gWv};
#pragma unroll
        for (int z = 0; z < 3; z++) {
            uint32_t stB = smb + BSP_OFF(s, z);
#pragma unroll
            for (int u = 0; u < 4; u++) {
                int c = tid + (u << 8);
                int row = c >> 3;
                uint32_t seg = (uint32_t)(c & 7) << 4;
                unsigned long long src = gws[z] + ((unsigned long long)row * NB + kb) * 128ull + seg;
                CP16(stB + swz(((uint32_t)row << 7) + seg), src);
            }
        }
    };

    float acc[3][2][4][4];
#pragma unroll
    for (int z = 0; z < 3; z++)
#pragma unroll
        for (int mi = 0; mi < 2; mi++)
#pragma unroll
            for (int nj = 0; nj < 4; nj++)
#pragma unroll
                for (int cc = 0; cc < 4; cc++) acc[z][mi][nj][cc] = 0.f;

    float gp0 = 0.f, gp1 = 0.f;
    int mw = w >> 2;          // 0..1  (32-row half)
    int nw = w & 3;           // 0..3  (32-col group)
    int lr = l & 15, lh = l >> 4;

    issue(0); CP_COMMIT();
    issue(1); CP_COMMIT();

    for (int kb = 0; kb < NB; kb++) {
        CP_WAIT1();
        __syncthreads();
        if (kb + 2 < NB) issue(kb + 2);
        CP_COMMIT();

        int s = kb % PNSTG;
        // ---- split phase: fp32 -> bf16 hi/lo into ABF, + gate partial ----
        {
            uint32_t stA = smb + AF32_OFF(s);
            const float* wgs = (const float*)(smem + WG_OFF) + kb * 32 + chk * 4;
            float wg0 = wgs[0], wg1 = wgs[1], wg2 = wgs[2], wg3 = wgs[3];
#pragma unroll
            for (int u = 0; u < 2; u++) {
                int row = (u == 0) ? rowA0 : rowA1;
                float4 a = *(const float4*)(smem + AF32_OFF(s) + row * 128 + (chk ^ (row & 7)) * 16);
                float gpart = a.x * wg0 + a.y * wg1 + a.z * wg2 + a.w * wg3;
                if (u == 0) gp0 += gpart; else gp1 += gpart;
                uint2 h, lo; pack4(a, h, lo);
                uint32_t base = (uint32_t)row * 128 + (uint32_t)chk * 8;
                *(uint2*)(smem + ABF_OFF + swz(base))      = h;
                *(uint2*)(smem + ABF_OFF + swz(base + 64)) = lo;
            }
            (void)stA;
        }
        __syncthreads();

        // ---- MMA phase ----
        uint32_t sAu = smb + ABF_OFF;
#pragma unroll
        for (int ks = 0; ks < 2; ks++) {
            uint32_t kbyte = (uint32_t)(ks << 5) + (lh << 4);
            uint32_t Ah[2][4], Al[2][4];
#pragma unroll
            for (int t = 0; t < 2; t++) {
                uint32_t ro = (uint32_t)((mw * 32 + (t << 4) + lr) << 7) + kbyte;
                LDSM4(Ah[t], sAu + swz(ro));
                LDSM4(Al[t], sAu + swz(ro + 64));
            }
#pragma unroll
            for (int z = 0; z < 3; z++) {
                uint32_t sBu = smb + BSP_OFF(s, z);
                uint32_t Bh[2][4], Bl[2][4];
#pragma unroll
                for (int p = 0; p < 2; p++) {
                    uint32_t ro = (uint32_t)((nw * 32 + (p << 4) + lr) << 7) + kbyte;
                    LDSM4(Bh[p], sBu + swz(ro));
                    LDSM4(Bl[p], sBu + swz(ro + 64));
                }
#pragma unroll
                for (int mi = 0; mi < 2; mi++)
#pragma unroll
                    for (int p = 0; p < 2; p++)
#pragma unroll
                        for (int j = 0; j < 2; j++) {
                            int nj = p * 2 + j;
                            MMA16816(acc[z][mi][nj], Ah[mi], Bh[p][j], Bh[p][j + 2]);
                            MMA16816(acc[z][mi][nj], Ah[mi], Bl[p][j], Bl[p][j + 2]);
                            MMA16816(acc[z][mi][nj], Al[mi], Bh[p][j], Bh[p][j + 2]);
                        }
            }
        }
    }

    // ---- gate reduce ----
    gred[rowA0][chk] = gp0;
    gred[rowA1][chk] = gp1;
    __syncthreads();
    if (tid < 64) {
        float s = 0.f;
#pragma unroll
        for (int j = 0; j < 8; j++) s += gred[tid][j];
        g_w[m0 + tid] = 1.f / (1.f + expf(-(s + gb[0])));
    }

    // ---- epilogue ----
    float* Cs[3] = {g_q, g_k, g_v};
#pragma unroll
    for (int z = 0; z < 3; z++) {
#pragma unroll
        for (int mi = 0; mi < 2; mi++) {
            int r0 = mw * 32 + (mi << 4) + (l >> 2);
#pragma unroll
            for (int nj = 0; nj < 4; nj++) {
                float* p = Cs[z] + (size_t)(m0 + r0) * Mm + nw * 32 + (nj << 3) + ((l & 3) << 1);
                *(float2*)p = make_float2(acc[z][mi][nj][0], acc[z][mi][nj][1]);
                *(float2*)(p + (size_t)8 * Mm) = make_float2(acc[z][mi][nj][2], acc[z][mi][nj][3]);
            }
        }
    }
}

// ======================================================================
// out gemm (pre-split operands, cp.async 4-stage) — unchanged from R6
// ======================================================================
#define NSTG 4
#define STAGE_B 32768
#define GEMM_SMEM (NSTG * STAGE_B)

__global__ void __launch_bounds__(256) out_mma(float* __restrict__ out)
{
    extern __shared__ __align__(1024) char smem[];
    int n0 = blockIdx.y * 128;
    int m0 = blockIdx.x * 128;
    const unsigned char* As = g_rs;
    const unsigned char* Bs = g_wos + (size_t)n0 * 4 * 128;
    float* C = out + n0;
    const int NB = Mm / 32, ldc = Hh;

    int tid = threadIdx.x;
    int w = tid >> 5, l = tid & 31;
    uint32_t smb = smem_u32(smem);
    unsigned long long gA = (unsigned long long)__cvta_generic_to_global(As);
    unsigned long long gB = (unsigned long long)__cvta_generic_to_global(Bs);

    auto issue = [&](int kb) {
        uint32_t st = smb + (uint32_t)(kb & (NSTG - 1)) * STAGE_B;
#pragma unroll
        for (int u = 0; u < 4; u++) {
            int c = tid + (u << 8);
            int row = c >> 3;
            uint32_t seg = (uint32_t)(c & 7) << 4;
            unsigned long long srcA = gA + ((unsigned long long)(m0 + row) * NB + kb) * 128ull + seg;
            unsigned long long srcB = gB + ((unsigned long long)row * NB + kb) * 128ull + seg;
            uint32_t d = swz(((uint32_t)row << 7) + seg);
            CP16(st + d, srcA);
            CP16(st + 16384 + d, srcB);
        }
    };

    float acc[2][8][4];
#pragma unroll
    for (int mi = 0; mi < 2; mi++)
#pragma unroll
        for (int nj = 0; nj < 8; nj++)
#pragma unroll
            for (int cc = 0; cc < 4; cc++) acc[mi][nj][cc] = 0.f;

    int wm = (w >> 1) << 5;
    int wn = (w & 1) << 6;
    int lr = l & 15, lh = l >> 4;

#pragma unroll
    for (int s = 0; s < NSTG; s++) { if (s < NB) issue(s); CP_COMMIT(); }

    for (int kb = 0; kb < NB; kb++) {
        CP_WAIT3();
        __syncthreads();
        uint32_t sAu = smb + (uint32_t)(kb & (NSTG - 1)) * STAGE_B;
        uint32_t sBu = sAu + 16384;
#pragma unroll
        for (int ks = 0; ks < 2; ks++) {
            uint32_t kbyte = (uint32_t)(ks << 5) + (lh << 4);
            uint32_t Ah[2][4], Al[2][4], Bh[4][4], Bl[4][4];
#pragma unroll
            for (int t = 0; t < 2; t++) {
                uint32_t ro = (uint32_t)((wm + (t << 4) + lr) << 7) + kbyte;
                LDSM4(Ah[t], sAu + swz(ro));
                LDSM4(Al[t], sAu + swz(ro + 64));
            }
#pragma unroll
            for (int g = 0; g < 4; g++) {
                uint32_t ro = (uint32_t)((wn + (g << 4) + lr) << 7) + kbyte;
                LDSM4(Bh[g], sBu + swz(ro));
                LDSM4(Bl[g], sBu + swz(ro + 64));
            }
#pragma unroll
            for (int mi = 0; mi < 2; mi++)
#pragma unroll
                for (int nj = 0; nj < 8; nj++) {
                    int g = nj >> 1, p = nj & 1;
                    MMA16816(acc[mi][nj], Ah[mi], Bh[g][p], Bh[g][p + 2]);
                    MMA16816(acc[mi][nj], Ah[mi], Bl[g][p], Bl[g][p + 2]);
                    MMA16816(acc[mi][nj], Al[mi], Bh[g][p], Bh[g][p + 2]);
                }
        }
        __syncthreads();
        if (kb + NSTG < NB) issue(kb + NSTG);
        CP_COMMIT();
    }

#pragma unroll
    for (int mi = 0; mi < 2; mi++) {
        int r0 = wm + (mi << 4) + (l >> 2);
#pragma unroll
        for (int nj = 0; nj < 8; nj++) {
            float* p = C + (size_t)(m0 + r0) * ldc + wn + (nj << 3) + ((l & 3) << 1);
            *(float2*)p = make_float2(acc[mi][nj][0], acc[mi][nj][1]);
            *(float2*)(p + (size_t)8 * ldc) = make_float2(acc[mi][nj][2], acc[mi][nj][3]);
        }
    }
}

// ---------------- generic split: src[rows x K] f32 -> tile-layout bf16 hi/lo ----------------
__global__ void __launch_bounds__(256) split_mat(const float* __restrict__ src,
                                                 unsigned char* __restrict__ dst,
                                                 int K, int total)
{
    int cpr = K >> 3, nkb = K >> 5;
    for (int g = blockIdx.x * 256 + threadIdx.x; g < total; g += gridDim.x * 256) {
        int row = g / cpr, pos = g - row * cpr;
        const float4* s = (const float4*)(src + (size_t)row * K + (size_t)pos * 8);
        float4 a0 = s[0], a1 = s[1];
        uint4 h, lo; pack8(a0, a1, h, lo);
        size_t base = ((size_t)row * nkb + (pos >> 2)) * 128 + (size_t)(pos & 3) * 16;
        *(uint4*)(dst + base)      = h;
        *(uint4*)(dst + base + 64) = lo;
    }
}

// ---------------- per-chunk aggregates: k_agg, v_agg, write_str ----------------
__global__ void __launch_bounds__(256) agg_kernel()
{
    int i = blockIdx.x;
    int tid = threadIdx.x;
    __shared__ float sw[256];
    __shared__ float sik[256];
    __shared__ float siv[256];
    __shared__ float red[256];
    {
        int b = tid >> 6, c = tid & 63;
        size_t t = (size_t)b * Ss + (size_t)i * CH + c;
        const float* kr = g_k + t * Mm;
        const float* vr = g_v + t * Mm;
        float nk = 0.f, nv = 0.f;
        for (int d = 0; d < Mm; d++) {
            float a = kr[d]; nk += a * a;
            float u = vr[d]; nv += u * u;
        }
        sik[tid] = 1.f / fmaxf(sqrtf(nk), 1e-12f);
        siv[tid] = 1.f / fmaxf(sqrtf(nv), 1e-12f);
        float wv = g_w[t];
        sw[tid] = wv;
        red[tid] = wv;
    }
    __syncthreads();
    for (int o = 128; o; o >>= 1) { if (tid < o) red[tid] += red[tid + o]; __syncthreads(); }
    float sumw = red[0];
    float wsum = fmaxf(sumw, 1e-8f);
    __syncthreads();

    int d = tid & 127;
    bool isv = (tid >= 128);
    const float* src = isv ? g_v : g_k;
    const float* inv = isv ? siv : sik;
    float acc = 0.f;
    for (int j = 0; j < 256; j++) {
        size_t tj = (size_t)(j >> 6) * Ss + (size_t)i * CH + (j & 63);
        acc += sw[j] * inv[j] * src[tj * Mm + d];
    }
    float mean = acc / wsum;
    red[tid] = mean * mean;
    __syncthreads();
    for (int o = 64; o; o >>= 1) { if ((tid & 127) < o) red[tid] += red[tid + o]; __syncthreads(); }
    float nrm = fmaxf(sqrtf(red[isv ? 128 : 0]), 1e-12f);
    float outv = mean / nrm;
    if (isv) g_Vagg[i * Mm + d] = outv;
    else     g_Kagg[i * Mm + d] = outv;
    if (tid == 0) g_ws[i] = sumw * (1.f / 256.f);
}

// ---------------- mean write strength ----------------
__global__ void meanws_kernel(float* __restrict__ out, int out_size)
{
    if (threadIdx.x == 0 && out_size > NTOK * Hh) {
        float s = 0.f;
        for (int j = 0; j < NC; j++) s += g_ws[j];
        out[(size_t)NTOK * Hh] = s / (float)NC;
    }
}

// ---------------- attention read (8 tokens per warp, transposed K, q from gmem) ----------------
#define ATTN_SMEM ((8192 + 8192 + 4096) * 4)   // kt + vsm + psm = 80KB
__global__ void __launch_bounds__(256) attn_kernel(const float* __restrict__ log_beta,
                                                   float* __restrict__ r_out)
{
    extern __shared__ float sm[];
    float* kt  = sm;               // [d][slot] 128x64
    float* vsm = kt + 8192;        // [slot][d] 64x128
    float* psm = vsm + 8192;       // [warp][c8][slot] 8x8x64
    __shared__ float str[64];
    __shared__ float ssum;

    int i = blockIdx.x;
    int bb = blockIdx.y;
    int tid = threadIdx.x;
    float beta = expf(log_beta[0]);

    for (int idx = tid; idx < 8192; idx += 256) {
        int d = idx >> 6, slot = idx & 63;
        kt[idx] = g_Kagg[slot * 128 + d];
    }
    for (int idx = tid; idx < 8192; idx += 256) vsm[idx] = g_Vagg[idx];
    if (tid < 64) {
        float dc = powf(0.999f, 64.f);
        float s = 0.f;
        if (tid < i) s = g_ws[tid] * powf(dc, (float)(i - 1 - tid));
        str[tid] = s;
    }
    __syncthreads();
    if (tid == 0) {
        float s = 0.f;
        for (int j = 0; j < 64; j++) s += str[j];
        ssum = s;
    }
    __syncthreads();

    bool valid = (ssum >= 1e-8f);
    int w = tid >> 5, lane = tid & 31;
    float m0ok = (str[lane] > 1e-8f)      ? 0.f : -1e9f;
    float m1ok = (str[lane + 32] > 1e-8f) ? 0.f : -1e9f;
    size_t tbase = (size_t)bb * Ss + (size_t)i * CH;
    const float* qg = g_q + (tbase + (size_t)w * 8) * Mm;

    float s0[8], s1[8];
#pragma unroll
    for (int c8 = 0; c8 < 8; c8++) { s0[c8] = 0.f; s1[c8] = 0.f; }
    for (int d4 = 0; d4 < 32; d4++) {
        float kv0[4], kv1[4];
#pragma unroll
        for (int ii = 0; ii < 4; ii++) {
            kv0[ii] = kt[(d4 * 4 + ii) * 64 + lane];
            kv1[ii] = kt[(d4 * 4 + ii) * 64 + 32 + lane];
        }
#pragma unroll
        for (int c8 = 0; c8 < 8; c8++) {
            float4 q = __ldg((const float4*)(qg + (size_t)c8 * Mm + d4 * 4));
            s0[c8] += q.x * kv0[0] + q.y * kv0[1] + q.z * kv0[2] + q.w * kv0[3];
            s1[c8] += q.x * kv1[0] + q.y * kv1[1] + q.z * kv1[2] + q.w * kv1[3];
        }
    }
#pragma unroll
    for (int c8 = 0; c8 < 8; c8++) {
        float sv0 = s0[c8] * beta + m0ok;
        float sv1 = s1[c8] * beta + m1ok;
        float mx = fmaxf(sv0, sv1);
#pragma unroll
        for (int o = 16; o; o >>= 1) mx = fmaxf(mx, __shfl_xor_sync(0xffffffffu, mx, o));
        float p0 = expf(sv0 - mx);
        float p1 = expf(sv1 - mx);
        float sum = p0 + p1;
#pragma unroll
        for (int o = 16; o; o >>= 1) sum += __shfl_xor_sync(0xffffffffu, sum, o);
        float invs = 1.f / sum;
        psm[w * 512 + c8 * 64 + lane]      = p0 * invs;
        psm[w * 512 + c8 * 64 + 32 + lane] = p1 * invs;
    }
    __syncwarp();

    float a[8][4];
#pragma unroll
    for (int c8 = 0; c8 < 8; c8++)
#pragma unroll
        for (int cc = 0; cc < 4; cc++) a[c8][cc] = 0.f;
    for (int j = 0; j < 64; j++) {
        float v0 = vsm[j * 128 + lane];
        float v1 = vsm[j * 128 + 32 + lane];
        float v2 = vsm[j * 128 + 64 + lane];
        float v3 = vsm[j * 128 + 96 + lane];
#pragma unroll
        for (int c8 = 0; c8 < 8; c8++) {
            float pj = psm[w * 512 + c8 * 64 + j];
            a[c8][0] += pj * v0; a[c8][1] += pj * v1;
            a[c8][2] += pj * v2; a[c8][3] += pj * v3;
        }
    }
#pragma unroll
    for (int c8 = 0; c8 < 8; c8++) {
        float* ro = r_out + (tbase + (size_t)w * 8 + c8) * Mm;
        float b0 = valid ? a[c8][0] : 0.f;
        float b1 = valid ? a[c8][1] : 0.f;
        float b2 = valid ? a[c8][2] : 0.f;
        float b3 = valid ? a[c8][3] : 0.f;
        ro[lane]      = b0;
        ro[lane + 32] = b1;
        ro[lane + 64] = b2;
        ro[lane + 96] = b3;
    }
}

// ---------------- per-token output norm clamp ----------------
__global__ void __launch_bounds__(256) norm_kernel(float* __restrict__ out)
{
    __shared__ float red[256];
    size_t t = blockIdx.x;
    float* row = out + t * (size_t)Hh;
    int tid = threadIdx.x;
    float4* r4 = (float4*)row;
    float ss = 0.f;
#pragma unroll
    for (int u = 0; u < 2; u++) {
        float4 v = r4[tid + u * 256];
        ss += v.x * v.x + v.y * v.y + v.z * v.z + v.w * v.w;
    }
    red[tid] = ss;
    __syncthreads();
    for (int o = 128; o; o >>= 1) { if (tid < o) red[tid] += red[tid + o]; __syncthreads(); }
    float nrm = fmaxf(sqrtf(red[0]), 1e-6f);
    float sc = fminf(10.f / nrm, 1.f);
    if (sc < 1.f) {
#pragma unroll
        for (int u = 0; u < 2; u++) {
            float4 v = r4[tid + u * 256];
            v.x *= sc; v.y *= sc; v.z *= sc; v.w *= sc;
            r4[tid + u * 256] = v;
        }
    }
}

// ---------------- launch ----------------
extern "C" void kernel_launch(void* const* d_in, const int* in_sizes, int n_in,
                              void* d_out, int out_size)
{
    const float* x  = (const float*)d_in[0];
    const float* Wq = (const float*)d_in[1];
    const float* Wk = (const float*)d_in[2];
    const float* Wv = (const float*)d_in[3];
    const float* Wo = (const float*)d_in[4];
    const float* Wg = (const float*)d_in[5];
    const float* gb = (const float*)d_in[6];
    const float* lb = (const float*)d_in[7];
    float* out = (float*)d_out;

    float* pr;
    cudaGetSymbolAddress((void**)&pr, g_r);
    unsigned char *pwq, *pwk, *pwv, *pwo, *prs;
    cudaGetSymbolAddress((void**)&pwq, g_wqs);
    cudaGetSymbolAddress((void**)&pwk, g_wks);
    cudaGetSymbolAddress((void**)&pwv, g_wvs);
    cudaGetSymbolAddress((void**)&pwo, g_wos);
    cudaGetSymbolAddress((void**)&prs, g_rs);

    cudaFuncSetAttribute(attn_kernel, cudaFuncAttributeMaxDynamicSharedMemorySize, ATTN_SMEM);
    cudaFuncSetAttribute(mega_proj, cudaFuncAttributeMaxDynamicSharedMemorySize, MEGA_SMEM);
    cudaFuncSetAttribute(out_mma,  cudaFuncAttributeMaxDynamicSharedMemorySize, GEMM_SMEM);

    // 1. split weights into bf16 hi/lo tile layout (small)
    split_mat<<<128, 256>>>(Wq, pwq, Hh, Mm * (Hh / 8));
    split_mat<<<128, 256>>>(Wk, pwk, Hh, Mm * (Hh / 8));
    split_mat<<<128, 256>>>(Wv, pwv, Hh, Mm * (Hh / 8));
    split_mat<<<128, 256>>>(Wo, pwo, Mm, Hh * (Mm / 8));
    // 2. fused split + gate + q/k/v projections (x read exactly once)
    mega_proj<<<NTOK / 64, 256, MEGA_SMEM>>>(x, Wg, gb);
    // 3. per-chunk write aggregates
    agg_kernel<<<NC, 256>>>();
    // 4. mean write strength
    meanws_kernel<<<1, 32>>>(out, out_size);
    // 5. attention reads
    attn_kernel<<<dim3(NC, Bb), 256, ATTN_SMEM>>>(lb, pr);
    // 6. split r, then output projection
    split_mat<<<1024, 256>>>(pr, prs, Mm, NTOK * (Mm / 8));
    out_mma<<<dim3(NTOK / 128, Hh / 128), 256, GEMM_SMEM>>>(out);
    // 7. norm clamp
    norm_kernel<<<NTOK, 256>>>(out);
}

// round 8
// speedup vs baseline: 3.8956x; 1.0589x over previous
#include <cuda_runtime.h>
#include <cuda_bf16.h>
#include <math.h>
#include <stdint.h>

#define Bb 4
#define Ss 4096
#define Hh 2048
#define Mm 128
#define CH 64
#define NC 64
#define NSLOTS 64
#define NTOK (Bb*Ss)   // 16384

// ---------------- scratch (static device globals; no allocation) ----------------
__device__ float g_q[NTOK*Mm];
__device__ float g_k[NTOK*Mm];
__device__ float g_v[NTOK*Mm];
__device__ float g_w[NTOK];
__device__ float g_Kagg[NSLOTS*Mm];
__device__ float g_Vagg[NSLOTS*Mm];
__device__ float g_ws[NSLOTS];
__device__ __align__(128) unsigned char g_rs [(size_t)NTOK * Mm * 4];   // split r
__device__ __align__(128) unsigned char g_wqs[(size_t)Mm * Hh * 4];
__device__ __align__(128) unsigned char g_wks[(size_t)Mm * Hh * 4];
__device__ __align__(128) unsigned char g_wvs[(size_t)Mm * Hh * 4];
__device__ __align__(128) unsigned char g_wos[(size_t)Hh * Mm * 4];

// ================= helpers =================
__device__ __forceinline__ uint32_t smem_u32(const void* p){
    uint32_t a;
    asm("{ .reg .u64 t; cvta.to.shared.u64 t, %1; cvt.u32.u64 %0, t; }" : "=r"(a) : "l"(p));
    return a;
}
__device__ __forceinline__ uint32_t bf2(float x, float y){
    uint32_t r; asm("cvt.rn.bf16x2.f32 %0, %1, %2;" : "=r"(r) : "f"(y), "f"(x)); return r;
}
__device__ __forceinline__ uint32_t swz(uint32_t x){ return x ^ ((x >> 3) & 0x70); }

__device__ __forceinline__ void pack4(float4 a, uint2& h, uint2& lo){
    h.x = bf2(a.x, a.y); h.y = bf2(a.z, a.w);
    float l0 = a.x - __uint_as_float(h.x << 16);
    float l1 = a.y - __uint_as_float(h.x & 0xffff0000u);
    float l2 = a.z - __uint_as_float(h.y << 16);
    float l3 = a.w - __uint_as_float(h.y & 0xffff0000u);
    lo.x = bf2(l0, l1); lo.y = bf2(l2, l3);
}
__device__ __forceinline__ void pack8(float4 a0, float4 a1, uint4& h, uint4& lo){
    uint2 h0, l0, h1, l1;
    pack4(a0, h0, l0); pack4(a1, h1, l1);
    h.x = h0.x; h.y = h0.y; h.z = h1.x; h.w = h1.y;
    lo.x = l0.x; lo.y = l0.y; lo.z = l1.x; lo.w = l1.y;
}

#define LDSM4(r, addr) \
    asm volatile("ldmatrix.sync.aligned.m8n8.x4.shared.b16 {%0,%1,%2,%3}, [%4];" \
        : "=r"((r)[0]), "=r"((r)[1]), "=r"((r)[2]), "=r"((r)[3]) : "r"(addr))

#define MMA16816(d, a, b0, b1) \
    asm volatile("mma.sync.aligned.m16n8k16.row.col.f32.bf16.bf16.f32 " \
        "{%0,%1,%2,%3}, {%4,%5,%6,%7}, {%8,%9}, {%0,%1,%2,%3};" \
        : "+f"((d)[0]), "+f"((d)[1]), "+f"((d)[2]), "+f"((d)[3]) \
        : "r"((a)[0]), "r"((a)[1]), "r"((a)[2]), "r"((a)[3]), "r"(b0), "r"(b1))

#define CP16(dst, src) \
    asm volatile("cp.async.cg.shared.global [%0], [%1], 16;" :: "r"(dst), "l"(src) : "memory")
#define CP_COMMIT() asm volatile("cp.async.commit_group;" ::: "memory")
#define CP_WAIT1()  asm volatile("cp.async.wait_group 1;" ::: "memory")

// ======================================================================
// mega_proj v2: fused split + gate + q/k/v projections, split overlapped
// with MMA via double ABF buffer. 64 token rows per CTA, grid 256.
// ======================================================================
#define PNSTG 3
#define AF32_OFF(s)   ((s) * 8192)
#define BSP_OFF(s, z) (24576 + (s) * 49152 + (z) * 16384)
#define ABF_OFF(p)    (172032 + (p) * 8192)
#define WG_OFF        188416
#define MEGA_SMEM     (188416 + 8192)   // 192 KB

__global__ void __launch_bounds__(256, 1) mega_proj(const float* __restrict__ x,
                                                    const float* __restrict__ Wg,
                                                    const float* __restrict__ gb)
{
    extern __shared__ __align__(1024) char smem[];
    __shared__ float gred[64][8];
    int tid = threadIdx.x;
    int w = tid >> 5, l = tid & 31;
    int m0 = blockIdx.x * 64;
    uint32_t smb = smem_u32(smem);
    const int NB = Hh / 32;   // 64

    unsigned long long gX  = (unsigned long long)__cvta_generic_to_global(x);
    unsigned long long gWq = (unsigned long long)__cvta_generic_to_global(g_wqs);
    unsigned long long gWk = (unsigned long long)__cvta_generic_to_global(g_wks);
    unsigned long long gWv = (unsigned long long)__cvta_generic_to_global(g_wvs);

    {
        const float4* wg4 = (const float4*)Wg;
        float4 w0 = wg4[2 * tid], w1 = wg4[2 * tid + 1];
        *(float4*)(smem + WG_OFF + tid * 32)      = w0;
        *(float4*)(smem + WG_OFF + tid * 32 + 16) = w1;
    }

    int rowA0 = tid >> 3;            // 0..31
    int rowA1 = 32 + (tid >> 3);     // 32..63
    int chk   = tid & 7;             // 0..7

    auto issue = [&](int kb) {
        int s = kb % PNSTG;
        uint32_t stA = smb + AF32_OFF(s);
#pragma unroll
        for (int u = 0; u < 2; u++) {
            int row = (u == 0) ? rowA0 : rowA1;
            unsigned long long src = gX + (((unsigned long long)(m0 + row)) * Hh + (unsigned long long)kb * 32 + chk * 4) * 4ull;
            CP16(stA + (uint32_t)row * 128 + (uint32_t)((chk ^ (row & 7)) * 16), src);
        }
        unsigned long long gws[3] = {gWq, gWk, gWv};
#pragma unroll
        for (int z = 0; z < 3; z++) {
            uint32_t stB = smb + BSP_OFF(s, z);
#pragma unroll
            for (int u = 0; u < 4; u++) {
                int c = tid + (u << 8);
                int row = c >> 3;
                uint32_t seg = (uint32_t)(c & 7) << 4;
                unsigned long long src = gws[z] + ((unsigned long long)row * NB + kb) * 128ull + seg;
                CP16(stB + swz(((uint32_t)row << 7) + seg), src);
            }
        }
    };

    float gp0 = 0.f, gp1 = 0.f;

    auto split_phase = [&](int kb) {
        int s = kb % PNSTG;
        char* abf = smem + ABF_OFF(kb & 1);
        const float* wgs = (const float*)(smem + WG_OFF) + kb * 32 + chk * 4;
        float wg0 = wgs[0], wg1 = wgs[1], wg2 = wgs[2], wg3 = wgs[3];
#pragma unroll
        for (int u = 0; u < 2; u++) {
            int row = (u == 0) ? rowA0 : rowA1;
            float4 a = *(const float4*)(smem + AF32_OFF(s) + row * 128 + (chk ^ (row & 7)) * 16);
            float gpart = a.x * wg0 + a.y * wg1 + a.z * wg2 + a.w * wg3;
            if (u == 0) gp0 += gpart; else gp1 += gpart;
            uint2 h, lo; pack4(a, h, lo);
            uint32_t base = (uint32_t)row * 128 + (uint32_t)chk * 8;
            *(uint2*)(abf + swz(base))      = h;
            *(uint2*)(abf + swz(base + 64)) = lo;
        }
    };

    float acc[3][2][4][4];
#pragma unroll
    for (int z = 0; z < 3; z++)
#pragma unroll
        for (int mi = 0; mi < 2; mi++)
#pragma unroll
            for (int nj = 0; nj < 4; nj++)
#pragma unroll
                for (int cc = 0; cc < 4; cc++) acc[z][mi][nj][cc] = 0.f;

    int mw = w >> 2;          // 0..1
    int nw = w & 3;           // 0..3
    int lr = l & 15, lh = l >> 4;

    issue(0); CP_COMMIT();
    issue(1); CP_COMMIT();
    CP_WAIT1();
    __syncthreads();
    split_phase(0);

    for (int kb = 0; kb < NB; kb++) {
        __syncthreads();                 // ABF[kb&1] complete; stages free for reuse
        if (kb + 2 < NB) issue(kb + 2);
        CP_COMMIT();
        CP_WAIT1();
        __syncthreads();                 // stage kb+1 visible to all threads
        if (kb + 1 < NB) split_phase(kb + 1);

        // ---- MMA(kb): reads ABF[kb&1] + B stage kb%3 ----
        int s = kb % PNSTG;
        uint32_t sAu = smb + ABF_OFF(kb & 1);
#pragma unroll
        for (int ks = 0; ks < 2; ks++) {
            uint32_t kbyte = (uint32_t)(ks << 5) + (lh << 4);
            uint32_t Ah[2][4], Al[2][4];
#pragma unroll
            for (int t = 0; t < 2; t++) {
                uint32_t ro = (uint32_t)((mw * 32 + (t << 4) + lr) << 7) + kbyte;
                LDSM4(Ah[t], sAu + swz(ro));
                LDSM4(Al[t], sAu + swz(ro + 64));
            }
#pragma unroll
            for (int z = 0; z < 3; z++) {
                uint32_t sBu = smb + BSP_OFF(s, z);
                uint32_t Bh[2][4], Bl[2][4];
#pragma unroll
                for (int p = 0; p < 2; p++) {
                    uint32_t ro = (uint32_t)((nw * 32 + (p << 4) + lr) << 7) + kbyte;
                    LDSM4(Bh[p], sBu + swz(ro));
                    LDSM4(Bl[p], sBu + swz(ro + 64));
                }
#pragma unroll
                for (int mi = 0; mi < 2; mi++)
#pragma unroll
                    for (int p = 0; p < 2; p++)
#pragma unroll
                        for (int j = 0; j < 2; j++) {
                            int nj = p * 2 + j;
                            MMA16816(acc[z][mi][nj], Ah[mi], Bh[p][j], Bh[p][j + 2]);
                            MMA16816(acc[z][mi][nj], Ah[mi], Bl[p][j], Bl[p][j + 2]);
                            MMA16816(acc[z][mi][nj], Al[mi], Bh[p][j], Bh[p][j + 2]);
                        }
            }
        }
    }

    // ---- gate reduce ----
    gred[rowA0][chk] = gp0;
    gred[rowA1][chk] = gp1;
    __syncthreads();
    if (tid < 64) {
        float s = 0.f;
#pragma unroll
        for (int j = 0; j < 8; j++) s += gred[tid][j];
        g_w[m0 + tid] = 1.f / (1.f + expf(-(s + gb[0])));
    }

    // ---- epilogue ----
    float* Cs[3] = {g_q, g_k, g_v};
#pragma unroll
    for (int z = 0; z < 3; z++) {
#pragma unroll
        for (int mi = 0; mi < 2; mi++) {
            int r0 = mw * 32 + (mi << 4) + (l >> 2);
#pragma unroll
            for (int nj = 0; nj < 4; nj++) {
                float* p = Cs[z] + (size_t)(m0 + r0) * Mm + nw * 32 + (nj << 3) + ((l & 3) << 1);
                *(float2*)p = make_float2(acc[z][mi][nj][0], acc[z][mi][nj][1]);
                *(float2*)(p + (size_t)8 * Mm) = make_float2(acc[z][mi][nj][2], acc[z][mi][nj][3]);
            }
        }
    }
}

// ======================================================================
// out gemm: pre-split operands, 2-stage cp.async, 2 CTAs/SM
// ======================================================================
#define NSTG 2
#define STAGE_B 32768
#define GEMM_SMEM (NSTG * STAGE_B)   // 64 KB

__global__ void __launch_bounds__(256, 2) out_mma(float* __restrict__ out)
{
    extern __shared__ __align__(1024) char smem[];
    int n0 = blockIdx.y * 128;
    int m0 = blockIdx.x * 128;
    const unsigned char* As = g_rs;
    const unsigned char* Bs = g_wos + (size_t)n0 * 4 * 128;
    float* C = out + n0;
    const int NB = Mm / 32, ldc = Hh;

    int tid = threadIdx.x;
    int w = tid >> 5, l = tid & 31;
    uint32_t smb = smem_u32(smem);
    unsigned long long gA = (unsigned long long)__cvta_generic_to_global(As);
    unsigned long long gB = (unsigned long long)__cvta_generic_to_global(Bs);

    auto issue = [&](int kb) {
        uint32_t st = smb + (uint32_t)(kb & (NSTG - 1)) * STAGE_B;
#pragma unroll
        for (int u = 0; u < 4; u++) {
            int c = tid + (u << 8);
            int row = c >> 3;
            uint32_t seg = (uint32_t)(c & 7) << 4;
            unsigned long long srcA = gA + ((unsigned long long)(m0 + row) * NB + kb) * 128ull + seg;
            unsigned long long srcB = gB + ((unsigned long long)row * NB + kb) * 128ull + seg;
            uint32_t d = swz(((uint32_t)row << 7) + seg);
            CP16(st + d, srcA);
            CP16(st + 16384 + d, srcB);
        }
    };

    float acc[2][8][4];
#pragma unroll
    for (int mi = 0; mi < 2; mi++)
#pragma unroll
        for (int nj = 0; nj < 8; nj++)
#pragma unroll
            for (int cc = 0; cc < 4; cc++) acc[mi][nj][cc] = 0.f;

    int wm = (w >> 1) << 5;
    int wn = (w & 1) << 6;
    int lr = l & 15, lh = l >> 4;

    issue(0); CP_COMMIT();
    issue(1); CP_COMMIT();

    for (int kb = 0; kb < NB; kb++) {
        CP_WAIT1();
        __syncthreads();
        uint32_t sAu = smb + (uint32_t)(kb & (NSTG - 1)) * STAGE_B;
        uint32_t sBu = sAu + 16384;
#pragma unroll
        for (int ks = 0; ks < 2; ks++) {
            uint32_t kbyte = (uint32_t)(ks << 5) + (lh << 4);
            uint32_t Ah[2][4], Al[2][4], Bh[4][4], Bl[4][4];
#pragma unroll
            for (int t = 0; t < 2; t++) {
                uint32_t ro = (uint32_t)((wm + (t << 4) + lr) << 7) + kbyte;
                LDSM4(Ah[t], sAu + swz(ro));
                LDSM4(Al[t], sAu + swz(ro + 64));
            }
#pragma unroll
            for (int g = 0; g < 4; g++) {
                uint32_t ro = (uint32_t)((wn + (g << 4) + lr) << 7) + kbyte;
                LDSM4(Bh[g], sBu + swz(ro));
                LDSM4(Bl[g], sBu + swz(ro + 64));
            }
#pragma unroll
            for (int mi = 0; mi < 2; mi++)
#pragma unroll
                for (int nj = 0; nj < 8; nj++) {
                    int g = nj >> 1, p = nj & 1;
                    MMA16816(acc[mi][nj], Ah[mi], Bh[g][p], Bh[g][p + 2]);
                    MMA16816(acc[mi][nj], Ah[mi], Bl[g][p], Bl[g][p + 2]);
                    MMA16816(acc[mi][nj], Al[mi], Bh[g][p], Bh[g][p + 2]);
                }
        }
        __syncthreads();
        if (kb + NSTG < NB) issue(kb + NSTG);
        CP_COMMIT();
    }

#pragma unroll
    for (int mi = 0; mi < 2; mi++) {
        int r0 = wm + (mi << 4) + (l >> 2);
#pragma unroll
        for (int nj = 0; nj < 8; nj++) {
            float* p = C + (size_t)(m0 + r0) * ldc + wn + (nj << 3) + ((l & 3) << 1);
            *(float2*)p = make_float2(acc[mi][nj][0], acc[mi][nj][1]);
            *(float2*)(p + (size_t)8 * ldc) = make_float2(acc[mi][nj][2], acc[mi][nj][3]);
        }
    }
}

// ---------------- fused weight splits (one launch, 4 matrices) ----------------
__global__ void __launch_bounds__(256) wsplit(const float* __restrict__ Wq,
                                              const float* __restrict__ Wk,
                                              const float* __restrict__ Wv,
                                              const float* __restrict__ Wo)
{
    int z = blockIdx.y;
    const float* src; unsigned char* dst; int K;
    if (z == 0)      { src = Wq; dst = g_wqs; K = Hh; }
    else if (z == 1) { src = Wk; dst = g_wks; K = Hh; }
    else if (z == 2) { src = Wv; dst = g_wvs; K = Hh; }
    else             { src = Wo; dst = g_wos; K = Mm; }
    int cpr = K >> 3, nkb = K >> 5;
    int g = blockIdx.x * 256 + threadIdx.x;   // 0..32767, exactly one chunk each
    int row = g / cpr, pos = g - row * cpr;
    const float4* s = (const float4*)(src + (size_t)row * K + (size_t)pos * 8);
    float4 a0 = s[0], a1 = s[1];
    uint4 h, lo; pack8(a0, a1, h, lo);
    size_t base = ((size_t)row * nkb + (pos >> 2)) * 128 + (size_t)(pos & 3) * 16;
    *(uint4*)(dst + base)      = h;
    *(uint4*)(dst + base + 64) = lo;
}

// ---------------- per-chunk aggregates ----------------
__global__ void __launch_bounds__(256) agg_kernel()
{
    int i = blockIdx.x;
    int tid = threadIdx.x;
    __shared__ float sw[256];
    __shared__ float sik[256];
    __shared__ float siv[256];
    __shared__ float red[256];
    {
        int b = tid >> 6, c = tid & 63;
        size_t t = (size_t)b * Ss + (size_t)i * CH + c;
        const float4* kr4 = (const float4*)(g_k + t * Mm);
        const float4* vr4 = (const float4*)(g_v + t * Mm);
        float nk = 0.f, nv = 0.f;
#pragma unroll 4
        for (int d = 0; d < 32; d++) {
            float4 a = kr4[d]; nk += a.x * a.x + a.y * a.y + a.z * a.z + a.w * a.w;
            float4 u = vr4[d]; nv += u.x * u.x + u.y * u.y + u.z * u.z + u.w * u.w;
        }
        sik[tid] = 1.f / fmaxf(sqrtf(nk), 1e-12f);
        siv[tid] = 1.f / fmaxf(sqrtf(nv), 1e-12f);
        float wv = g_w[t];
        sw[tid] = wv;
        red[tid] = wv;
    }
    __syncthreads();
    for (int o = 128; o; o >>= 1) { if (tid < o) red[tid] += red[tid + o]; __syncthreads(); }
    float sumw = red[0];
    float wsum = fmaxf(sumw, 1e-8f);
    __syncthreads();

    int d = tid & 127;
    bool isv = (tid >= 128);
    const float* src = isv ? g_v : g_k;
    const float* inv = isv ? siv : sik;
    float acc = 0.f;
#pragma unroll 4
    for (int j = 0; j < 256; j++) {
        size_t tj = (size_t)(j >> 6) * Ss + (size_t)i * CH + (j & 63);
        acc += sw[j] * inv[j] * src[tj * Mm + d];
    }
    float mean = acc / wsum;
    red[tid] = mean * mean;
    __syncthreads();
    for (int o = 64; o; o >>= 1) { if ((tid & 127) < o) red[tid] += red[tid + o]; __syncthreads(); }
    float nrm = fmaxf(sqrtf(red[isv ? 128 : 0]), 1e-12f);
    float outv = mean / nrm;
    if (isv) g_Vagg[i * Mm + d] = outv;
    else     g_Kagg[i * Mm + d] = outv;
    if (tid == 0) g_ws[i] = sumw * (1.f / 256.f);
}

// ---------------- attention read + fused r-split + fused mean_ws ----------------
#define ATTN_SMEM ((8192 + 8192 + 4096) * 4)   // kt(/rsm) + vsm + psm = 80KB
__global__ void __launch_bounds__(256) attn_kernel(const float* __restrict__ log_beta,
                                                   float* __restrict__ out, int out_size)
{
    extern __shared__ float sm[];
    float* kt  = sm;               // [d][slot] 128x64 — reused as rsm [tok][dim] later
    float* vsm = kt + 8192;        // [slot][d] 64x128
    float* psm = vsm + 8192;       // [warp][c8][slot]
    __shared__ float str[64];
    __shared__ float ssum;

    int i = blockIdx.x;
    int bb = blockIdx.y;
    int tid = threadIdx.x;
    float beta = expf(log_beta[0]);

    for (int idx = tid; idx < 8192; idx += 256) {
        int d = idx >> 6, slot = idx & 63;
        kt[idx] = g_Kagg[slot * 128 + d];
    }
    for (int idx = tid; idx < 8192; idx += 256) vsm[idx] = g_Vagg[idx];
    if (tid < 64) {
        float dc = powf(0.999f, 64.f);
        float s = 0.f;
        if (tid < i) s = g_ws[tid] * powf(dc, (float)(i - 1 - tid));
        str[tid] = s;
    }
    __syncthreads();
    if (tid == 0) {
        float s = 0.f;
        for (int j = 0; j < 64; j++) s += str[j];
        ssum = s;
        if (i == 0 && bb == 0 && out_size > NTOK * Hh) {
            float m = 0.f;
            for (int j = 0; j < NC; j++) m += g_ws[j];
            out[(size_t)NTOK * Hh] = m / (float)NC;
        }
    }
    __syncthreads();

    bool valid = (ssum >= 1e-8f);
    int w = tid >> 5, lane = tid & 31;
    float m0ok = (str[lane] > 1e-8f)      ? 0.f : -1e9f;
    float m1ok = (str[lane + 32] > 1e-8f) ? 0.f : -1e9f;
    size_t tbase = (size_t)bb * Ss + (size_t)i * CH;
    const float* qg = g_q + (tbase + (size_t)w * 8) * Mm;

    float s0[8], s1[8];
#pragma unroll
    for (int c8 = 0; c8 < 8; c8++) { s0[c8] = 0.f; s1[c8] = 0.f; }
    for (int d4 = 0; d4 < 32; d4++) {
        float kv0[4], kv1[4];
#pragma unroll
        for (int ii = 0; ii < 4; ii++) {
            kv0[ii] = kt[(d4 * 4 + ii) * 64 + lane];
            kv1[ii] = kt[(d4 * 4 + ii) * 64 + 32 + lane];
        }
#pragma unroll
        for (int c8 = 0; c8 < 8; c8++) {
            float4 q = __ldg((const float4*)(qg + (size_t)c8 * Mm + d4 * 4));
            s0[c8] += q.x * kv0[0] + q.y * kv0[1] + q.z * kv0[2] + q.w * kv0[3];
            s1[c8] += q.x * kv1[0] + q.y * kv1[1] + q.z * kv1[2] + q.w * kv1[3];
        }
    }
#pragma unroll
    for (int c8 = 0; c8 < 8; c8++) {
        float sv0 = s0[c8] * beta + m0ok;
        float sv1 = s1[c8] * beta + m1ok;
        float mx = fmaxf(sv0, sv1);
#pragma unroll
        for (int o = 16; o; o >>= 1) mx = fmaxf(mx, __shfl_xor_sync(0xffffffffu, mx, o));
        float p0 = expf(sv0 - mx);
        float p1 = expf(sv1 - mx);
        float sum = p0 + p1;
#pragma unroll
        for (int o = 16; o; o >>= 1) sum += __shfl_xor_sync(0xffffffffu, sum, o);
        float invs = 1.f / sum;
        psm[w * 512 + c8 * 64 + lane]      = p0 * invs;
        psm[w * 512 + c8 * 64 + 32 + lane] = p1 * invs;
    }
    __syncthreads();   // all warps done reading kt (scores) — kt now reusable as rsm

    float a[8][4];
#pragma unroll
    for (int c8 = 0; c8 < 8; c8++)
#pragma unroll
        for (int cc = 0; cc < 4; cc++) a[c8][cc] = 0.f;
    for (int j = 0; j < 64; j++) {
        float v0 = vsm[j * 128 + lane];
        float v1 = vsm[j * 128 + 32 + lane];
        float v2 = vsm[j * 128 + 64 + lane];
        float v3 = vsm[j * 128 + 96 + lane];
#pragma unroll
        for (int c8 = 0; c8 < 8; c8++) {
            float pj = psm[w * 512 + c8 * 64 + j];
            a[c8][0] += pj * v0; a[c8][1] += pj * v1;
            a[c8][2] += pj * v2; a[c8][3] += pj * v3;
        }
    }
    float* rsm = kt;   // [local token][dim]
#pragma unroll
    for (int c8 = 0; c8 < 8; c8++) {
        int lt = w * 8 + c8;
        rsm[lt * 128 + lane]      = valid ? a[c8][0] : 0.f;
        rsm[lt * 128 + lane + 32] = valid ? a[c8][1] : 0.f;
        rsm[lt * 128 + lane + 64] = valid ? a[c8][2] : 0.f;
        rsm[lt * 128 + lane + 96] = valid ? a[c8][3] : 0.f;
    }
    __syncthreads();

    // ---- pack r -> g_rs (bf16 hi/lo tile layout), skipping fp32 round-trip ----
#pragma unroll
    for (int u = 0; u < 4; u++) {
        int c = tid + (u << 8);          // 0..1023 chunks (64 tok x 16)
        int lt = c >> 4, pos = c & 15;
        float4 a0 = *(float4*)(rsm + lt * 128 + pos * 8);
        float4 a1 = *(float4*)(rsm + lt * 128 + pos * 8 + 4);
        uint4 h, lo; pack8(a0, a1, h, lo);
        size_t grow = tbase + lt;
        size_t base = (grow * 4 + (size_t)(pos >> 2)) * 128 + (size_t)(pos & 3) * 16;
        *(uint4*)(g_rs + base)      = h;
        *(uint4*)(g_rs + base + 64) = lo;
    }
}

// ---------------- per-token output norm clamp ----------------
__global__ void __launch_bounds__(256) norm_kernel(float* __restrict__ out)
{
    __shared__ float red[256];
    size_t t = blockIdx.x;
    float* row = out + t * (size_t)Hh;
    int tid = threadIdx.x;
    float4* r4 = (float4*)row;
    float ss = 0.f;
#pragma unroll
    for (int u = 0; u < 2; u++) {
        float4 v = r4[tid + u * 256];
        ss += v.x * v.x + v.y * v.y + v.z * v.z + v.w * v.w;
    }
    red[tid] = ss;
    __syncthreads();
    for (int o = 128; o; o >>= 1) { if (tid < o) red[tid] += red[tid + o]; __syncthreads(); }
    float nrm = fmaxf(sqrtf(red[0]), 1e-6f);
    float sc = fminf(10.f / nrm, 1.f);
    if (sc < 1.f) {
#pragma unroll
        for (int u = 0; u < 2; u++) {
            float4 v = r4[tid + u * 256];
            v.x *= sc; v.y *= sc; v.z *= sc; v.w *= sc;
            r4[tid + u * 256] = v;
        }
    }
}

// ---------------- launch ----------------
extern "C" void kernel_launch(void* const* d_in, const int* in_sizes, int n_in,
                              void* d_out, int out_size)
{
    const float* x  = (const float*)d_in[0];
    const float* Wq = (const float*)d_in[1];
    const float* Wk = (const float*)d_in[2];
    const float* Wv = (const float*)d_in[3];
    const float* Wo = (const float*)d_in[4];
    const float* Wg = (const float*)d_in[5];
    const float* gb = (const float*)d_in[6];
    const float* lb = (const float*)d_in[7];
    float* out = (float*)d_out;

    cudaFuncSetAttribute(attn_kernel, cudaFuncAttributeMaxDynamicSharedMemorySize, ATTN_SMEM);
    cudaFuncSetAttribute(mega_proj, cudaFuncAttributeMaxDynamicSharedMemorySize, MEGA_SMEM);
    cudaFuncSetAttribute(out_mma,  cudaFuncAttributeMaxDynamicSharedMemorySize, GEMM_SMEM);

    // 1. all weight splits in one launch
    wsplit<<<dim3(128, 4), 256>>>(Wq, Wk, Wv, Wo);
    // 2. fused split + gate + q/k/v projections
    mega_proj<<<NTOK / 64, 256, MEGA_SMEM>>>(x, Wg, gb);
    // 3. per-chunk write aggregates
    agg_kernel<<<NC, 256>>>();
    // 4. attention reads (+ fused r-split + mean_ws)
    attn_kernel<<<dim3(NC, Bb), 256, ATTN_SMEM>>>(lb, out, out_size);
    // 5. output projection
    out_mma<<<dim3(NTOK / 128, Hh / 128), 256, GEMM_SMEM>>>(out);
    // 6. norm clamp
    norm_kernel<<<NTOK, 256>>>(out);
}

// round 9
// speedup vs baseline: 3.9043x; 1.0022x over previous
#include <cuda_runtime.h>
#include <cuda_bf16.h>
#include <math.h>
#include <stdint.h>

#define Bb 4
#define Ss 4096
#define Hh 2048
#define Mm 128
#define CH 64
#define NC 64
#define NSLOTS 64
#define NTOK (Bb*Ss)   // 16384

// ---------------- scratch (static device globals; no allocation) ----------------
__device__ float g_q[NTOK*Mm];
__device__ float g_k[NTOK*Mm];
__device__ float g_v[NTOK*Mm];
__device__ float g_w[NTOK];
__device__ float g_Kagg[NSLOTS*Mm];
__device__ float g_Vagg[NSLOTS*Mm];
__device__ float g_ws[NSLOTS];
__device__ __align__(128) unsigned char g_rs [(size_t)NTOK * Mm * 4];   // split r
__device__ __align__(128) unsigned char g_wqs[(size_t)Mm * Hh * 4];
__device__ __align__(128) unsigned char g_wks[(size_t)Mm * Hh * 4];
__device__ __align__(128) unsigned char g_wvs[(size_t)Mm * Hh * 4];
__device__ __align__(128) unsigned char g_wos[(size_t)Hh * Mm * 4];

// ================= helpers =================
__device__ __forceinline__ uint32_t smem_u32(const void* p){
    uint32_t a;
    asm("{ .reg .u64 t; cvta.to.shared.u64 t, %1; cvt.u32.u64 %0, t; }" : "=r"(a) : "l"(p));
    return a;
}
__device__ __forceinline__ uint32_t bf2(float x, float y){
    uint32_t r; asm("cvt.rn.bf16x2.f32 %0, %1, %2;" : "=r"(r) : "f"(y), "f"(x)); return r;
}
__device__ __forceinline__ uint32_t swz(uint32_t x){ return x ^ ((x >> 3) & 0x70); }

__device__ __forceinline__ void pack4(float4 a, uint2& h, uint2& lo){
    h.x = bf2(a.x, a.y); h.y = bf2(a.z, a.w);
    float l0 = a.x - __uint_as_float(h.x << 16);
    float l1 = a.y - __uint_as_float(h.x & 0xffff0000u);
    float l2 = a.z - __uint_as_float(h.y << 16);
    float l3 = a.w - __uint_as_float(h.y & 0xffff0000u);
    lo.x = bf2(l0, l1); lo.y = bf2(l2, l3);
}
__device__ __forceinline__ void pack8(float4 a0, float4 a1, uint4& h, uint4& lo){
    uint2 h0, l0, h1, l1;
    pack4(a0, h0, l0); pack4(a1, h1, l1);
    h.x = h0.x; h.y = h0.y; h.z = h1.x; h.w = h1.y;
    lo.x = l0.x; lo.y = l0.y; lo.z = l1.x; lo.w = l1.y;
}

#define LDSM4(r, addr) \
    asm volatile("ldmatrix.sync.aligned.m8n8.x4.shared.b16 {%0,%1,%2,%3}, [%4];" \
        : "=r"((r)[0]), "=r"((r)[1]), "=r"((r)[2]), "=r"((r)[3]) : "r"(addr))

#define MMA16816(d, a, b0, b1) \
    asm volatile("mma.sync.aligned.m16n8k16.row.col.f32.bf16.bf16.f32 " \
        "{%0,%1,%2,%3}, {%4,%5,%6,%7}, {%8,%9}, {%0,%1,%2,%3};" \
        : "+f"((d)[0]), "+f"((d)[1]), "+f"((d)[2]), "+f"((d)[3]) \
        : "r"((a)[0]), "r"((a)[1]), "r"((a)[2]), "r"((a)[3]), "r"(b0), "r"(b1))

#define CP16(dst, src) \
    asm volatile("cp.async.cg.shared.global [%0], [%1], 16;" :: "r"(dst), "l"(src) : "memory")
#define CP_COMMIT() asm volatile("cp.async.commit_group;" ::: "memory")
#define CP_WAIT1()  asm volatile("cp.async.wait_group 1;" ::: "memory")

// ======================================================================
// mega_proj v2: fused split + gate + q/k/v projections, split overlapped
// with MMA via double ABF buffer. 64 token rows per CTA, grid 256.
// ======================================================================
#define PNSTG 3
#define AF32_OFF(s)   ((s) * 8192)
#define BSP_OFF(s, z) (24576 + (s) * 49152 + (z) * 16384)
#define ABF_OFF(p)    (172032 + (p) * 8192)
#define WG_OFF        188416
#define MEGA_SMEM     (188416 + 8192)   // 192 KB

__global__ void __launch_bounds__(256, 1) mega_proj(const float* __restrict__ x,
                                                    const float* __restrict__ Wg,
                                                    const float* __restrict__ gb)
{
    extern __shared__ __align__(1024) char smem[];
    __shared__ float gred[64][8];
    int tid = threadIdx.x;
    int w = tid >> 5, l = tid & 31;
    int m0 = blockIdx.x * 64;
    uint32_t smb = smem_u32(smem);
    const int NB = Hh / 32;   // 64

    unsigned long long gX  = (unsigned long long)__cvta_generic_to_global(x);
    unsigned long long gWq = (unsigned long long)__cvta_generic_to_global(g_wqs);
    unsigned long long gWk = (unsigned long long)__cvta_generic_to_global(g_wks);
    unsigned long long gWv = (unsigned long long)__cvta_generic_to_global(g_wvs);

    {
        const float4* wg4 = (const float4*)Wg;
        float4 w0 = wg4[2 * tid], w1 = wg4[2 * tid + 1];
        *(float4*)(smem + WG_OFF + tid * 32)      = w0;
        *(float4*)(smem + WG_OFF + tid * 32 + 16) = w1;
    }

    int rowA0 = tid >> 3;            // 0..31
    int rowA1 = 32 + (tid >> 3);     // 32..63
    int chk   = tid & 7;             // 0..7

    auto issue = [&](int kb) {
        int s = kb % PNSTG;
        uint32_t stA = smb + AF32_OFF(s);
#pragma unroll
        for (int u = 0; u < 2; u++) {
            int row = (u == 0) ? rowA0 : rowA1;
            unsigned long long src = gX + (((unsigned long long)(m0 + row)) * Hh + (unsigned long long)kb * 32 + chk * 4) * 4ull;
            CP16(stA + (uint32_t)row * 128 + (uint32_t)((chk ^ (row & 7)) * 16), src);
        }
        unsigned long long gws[3] = {gWq, gWk, gWv};
#pragma unroll
        for (int z = 0; z < 3; z++) {
            uint32_t stB = smb + BSP_OFF(s, z);
#pragma unroll
            for (int u = 0; u < 4; u++) {
                int c = tid + (u << 8);
                int row = c >> 3;
                uint32_t seg = (uint32_t)(c & 7) << 4;
                unsigned long long src = gws[z] + ((unsigned long long)row * NB + kb) * 128ull + seg;
                CP16(stB + swz(((uint32_t)row << 7) + seg), src);
            }
        }
    };

    float gp0 = 0.f, gp1 = 0.f;

    auto split_phase = [&](int kb) {
        int s = kb % PNSTG;
        char* abf = smem + ABF_OFF(kb & 1);
        const float* wgs = (const float*)(smem + WG_OFF) + kb * 32 + chk * 4;
        float wg0 = wgs[0], wg1 = wgs[1], wg2 = wgs[2], wg3 = wgs[3];
#pragma unroll
        for (int u = 0; u < 2; u++) {
            int row = (u == 0) ? rowA0 : rowA1;
            float4 a = *(const float4*)(smem + AF32_OFF(s) + row * 128 + (chk ^ (row & 7)) * 16);
            float gpart = a.x * wg0 + a.y * wg1 + a.z * wg2 + a.w * wg3;
            if (u == 0) gp0 += gpart; else gp1 += gpart;
            uint2 h, lo; pack4(a, h, lo);
            uint32_t base = (uint32_t)row * 128 + (uint32_t)chk * 8;
            *(uint2*)(abf + swz(base))      = h;
            *(uint2*)(abf + swz(base + 64)) = lo;
        }
    };

    float acc[3][2][4][4];
#pragma unroll
    for (int z = 0; z < 3; z++)
#pragma unroll
        for (int mi = 0; mi < 2; mi++)
#pragma unroll
            for (int nj = 0; nj < 4; nj++)
#pragma unroll
                for (int cc = 0; cc < 4; cc++) acc[z][mi][nj][cc] = 0.f;

    int mw = w >> 2;          // 0..1
    int nw = w & 3;           // 0..3
    int lr = l & 15, lh = l >> 4;

    issue(0); CP_COMMIT();
    issue(1); CP_COMMIT();
    CP_WAIT1();
    __syncthreads();
    split_phase(0);

    for (int kb = 0; kb < NB; kb++) {
        __syncthreads();                 // ABF[kb&1] complete; stages free for reuse
        if (kb + 2 < NB) issue(kb + 2);
        CP_COMMIT();
        CP_WAIT1();
        __syncthreads();                 // stage kb+1 visible to all threads
        if (kb + 1 < NB) split_phase(kb + 1);

        // ---- MMA(kb): reads ABF[kb&1] + B stage kb%3 ----
        int s = kb % PNSTG;
        uint32_t sAu = smb + ABF_OFF(kb & 1);
#pragma unroll
        for (int ks = 0; ks < 2; ks++) {
            uint32_t kbyte = (uint32_t)(ks << 5) + (lh << 4);
            uint32_t Ah[2][4], Al[2][4];
#pragma unroll
            for (int t = 0; t < 2; t++) {
                uint32_t ro = (uint32_t)((mw * 32 + (t << 4) + lr) << 7) + kbyte;
                LDSM4(Ah[t], sAu + swz(ro));
                LDSM4(Al[t], sAu + swz(ro + 64));
            }
#pragma unroll
            for (int z = 0; z < 3; z++) {
                uint32_t sBu = smb + BSP_OFF(s, z);
                uint32_t Bh[2][4], Bl[2][4];
#pragma unroll
                for (int p = 0; p < 2; p++) {
                    uint32_t ro = (uint32_t)((nw * 32 + (p << 4) + lr) << 7) + kbyte;
                    LDSM4(Bh[p], sBu + swz(ro));
                    LDSM4(Bl[p], sBu + swz(ro + 64));
                }
#pragma unroll
                for (int mi = 0; mi < 2; mi++)
#pragma unroll
                    for (int p = 0; p < 2; p++)
#pragma unroll
                        for (int j = 0; j < 2; j++) {
                            int nj = p * 2 + j;
                            MMA16816(acc[z][mi][nj], Ah[mi], Bh[p][j], Bh[p][j + 2]);
                            MMA16816(acc[z][mi][nj], Ah[mi], Bl[p][j], Bl[p][j + 2]);
                            MMA16816(acc[z][mi][nj], Al[mi], Bh[p][j], Bh[p][j + 2]);
                        }
            }
        }
    }

    // ---- gate reduce ----
    gred[rowA0][chk] = gp0;
    gred[rowA1][chk] = gp1;
    __syncthreads();
    if (tid < 64) {
        float s = 0.f;
#pragma unroll
        for (int j = 0; j < 8; j++) s += gred[tid][j];
        g_w[m0 + tid] = 1.f / (1.f + expf(-(s + gb[0])));
    }

    // ---- epilogue ----
    float* Cs[3] = {g_q, g_k, g_v};
#pragma unroll
    for (int z = 0; z < 3; z++) {
#pragma unroll
        for (int mi = 0; mi < 2; mi++) {
            int r0 = mw * 32 + (mi << 4) + (l >> 2);
#pragma unroll
            for (int nj = 0; nj < 4; nj++) {
                float* p = Cs[z] + (size_t)(m0 + r0) * Mm + nw * 32 + (nj << 3) + ((l & 3) << 1);
                *(float2*)p = make_float2(acc[z][mi][nj][0], acc[z][mi][nj][1]);
                *(float2*)(p + (size_t)8 * Mm) = make_float2(acc[z][mi][nj][2], acc[z][mi][nj][3]);
            }
        }
    }
}

// ======================================================================
// out gemm: pre-split operands, 2-stage cp.async, 2 CTAs/SM
// ======================================================================
#define NSTG 2
#define STAGE_B 32768
#define GEMM_SMEM (NSTG * STAGE_B)   // 64 KB

__global__ void __launch_bounds__(256, 2) out_mma(float* __restrict__ out)
{
    extern __shared__ __align__(1024) char smem[];
    int n0 = blockIdx.y * 128;
    int m0 = blockIdx.x * 128;
    const unsigned char* As = g_rs;
    const unsigned char* Bs = g_wos + (size_t)n0 * 4 * 128;
    float* C = out + n0;
    const int NB = Mm / 32, ldc = Hh;

    int tid = threadIdx.x;
    int w = tid >> 5, l = tid & 31;
    uint32_t smb = smem_u32(smem);
    unsigned long long gA = (unsigned long long)__cvta_generic_to_global(As);
    unsigned long long gB = (unsigned long long)__cvta_generic_to_global(Bs);

    auto issue = [&](int kb) {
        uint32_t st = smb + (uint32_t)(kb & (NSTG - 1)) * STAGE_B;
#pragma unroll
        for (int u = 0; u < 4; u++) {
            int c = tid + (u << 8);
            int row = c >> 3;
            uint32_t seg = (uint32_t)(c & 7) << 4;
            unsigned long long srcA = gA + ((unsigned long long)(m0 + row) * NB + kb) * 128ull + seg;
            unsigned long long srcB = gB + ((unsigned long long)row * NB + kb) * 128ull + seg;
            uint32_t d = swz(((uint32_t)row << 7) + seg);
            CP16(st + d, srcA);
            CP16(st + 16384 + d, srcB);
        }
    };

    float acc[2][8][4];
#pragma unroll
    for (int mi = 0; mi < 2; mi++)
#pragma unroll
        for (int nj = 0; nj < 8; nj++)
#pragma unroll
            for (int cc = 0; cc < 4; cc++) acc[mi][nj][cc] = 0.f;

    int wm = (w >> 1) << 5;
    int wn = (w & 1) << 6;
    int lr = l & 15, lh = l >> 4;

    issue(0); CP_COMMIT();
    issue(1); CP_COMMIT();

    for (int kb = 0; kb < NB; kb++) {
        CP_WAIT1();
        __syncthreads();
        uint32_t sAu = smb + (uint32_t)(kb & (NSTG - 1)) * STAGE_B;
        uint32_t sBu = sAu + 16384;
#pragma unroll
        for (int ks = 0; ks < 2; ks++) {
            uint32_t kbyte = (uint32_t)(ks << 5) + (lh << 4);
            uint32_t Ah[2][4], Al[2][4], Bh[4][4], Bl[4][4];
#pragma unroll
            for (int t = 0; t < 2; t++) {
                uint32_t ro = (uint32_t)((wm + (t << 4) + lr) << 7) + kbyte;
                LDSM4(Ah[t], sAu + swz(ro));
                LDSM4(Al[t], sAu + swz(ro + 64));
            }
#pragma unroll
            for (int g = 0; g < 4; g++) {
                uint32_t ro = (uint32_t)((wn + (g << 4) + lr) << 7) + kbyte;
                LDSM4(Bh[g], sBu + swz(ro));
                LDSM4(Bl[g], sBu + swz(ro + 64));
            }
#pragma unroll
            for (int mi = 0; mi < 2; mi++)
#pragma unroll
                for (int nj = 0; nj < 8; nj++) {
                    int g = nj >> 1, p = nj & 1;
                    MMA16816(acc[mi][nj], Ah[mi], Bh[g][p], Bh[g][p + 2]);
                    MMA16816(acc[mi][nj], Ah[mi], Bl[g][p], Bl[g][p + 2]);
                    MMA16816(acc[mi][nj], Al[mi], Bh[g][p], Bh[g][p + 2]);
                }
        }
        __syncthreads();
        if (kb + NSTG < NB) issue(kb + NSTG);
        CP_COMMIT();
    }

#pragma unroll
    for (int mi = 0; mi < 2; mi++) {
        int r0 = wm + (mi << 4) + (l >> 2);
#pragma unroll
        for (int nj = 0; nj < 8; nj++) {
            float* p = C + (size_t)(m0 + r0) * ldc + wn + (nj << 3) + ((l & 3) << 1);
            *(float2*)p = make_float2(acc[mi][nj][0], acc[mi][nj][1]);
            *(float2*)(p + (size_t)8 * ldc) = make_float2(acc[mi][nj][2], acc[mi][nj][3]);
        }
    }
}

// ---------------- fused weight splits (one launch, 4 matrices) ----------------
__global__ void __launch_bounds__(256) wsplit(const float* __restrict__ Wq,
                                              const float* __restrict__ Wk,
                                              const float* __restrict__ Wv,
                                              const float* __restrict__ Wo)
{
    int z = blockIdx.y;
    const float* src; unsigned char* dst; int K;
    if (z == 0)      { src = Wq; dst = g_wqs; K = Hh; }
    else if (z == 1) { src = Wk; dst = g_wks; K = Hh; }
    else if (z == 2) { src = Wv; dst = g_wvs; K = Hh; }
    else             { src = Wo; dst = g_wos; K = Mm; }
    int cpr = K >> 3, nkb = K >> 5;
    int g = blockIdx.x * 256 + threadIdx.x;   // 0..32767, exactly one chunk each
    int row = g / cpr, pos = g - row * cpr;
    const float4* s = (const float4*)(src + (size_t)row * K + (size_t)pos * 8);
    float4 a0 = s[0], a1 = s[1];
    uint4 h, lo; pack8(a0, a1, h, lo);
    size_t base = ((size_t)row * nkb + (pos >> 2)) * 128 + (size_t)(pos & 3) * 16;
    *(uint4*)(dst + base)      = h;
    *(uint4*)(dst + base + 64) = lo;
}

// ---------------- per-chunk aggregates ----------------
__global__ void __launch_bounds__(256) agg_kernel()
{
    int i = blockIdx.x;
    int tid = threadIdx.x;
    __shared__ float sw[256];
    __shared__ float sik[256];
    __shared__ float siv[256];
    __shared__ float red[256];
    {
        int b = tid >> 6, c = tid & 63;
        size_t t = (size_t)b * Ss + (size_t)i * CH + c;
        const float4* kr4 = (const float4*)(g_k + t * Mm);
        const float4* vr4 = (const float4*)(g_v + t * Mm);
        float nk = 0.f, nv = 0.f;
#pragma unroll 4
        for (int d = 0; d < 32; d++) {
            float4 a = kr4[d]; nk += a.x * a.x + a.y * a.y + a.z * a.z + a.w * a.w;
            float4 u = vr4[d]; nv += u.x * u.x + u.y * u.y + u.z * u.z + u.w * u.w;
        }
        sik[tid] = 1.f / fmaxf(sqrtf(nk), 1e-12f);
        siv[tid] = 1.f / fmaxf(sqrtf(nv), 1e-12f);
        float wv = g_w[t];
        sw[tid] = wv;
        red[tid] = wv;
    }
    __syncthreads();
    for (int o = 128; o; o >>= 1) { if (tid < o) red[tid] += red[tid + o]; __syncthreads(); }
    float sumw = red[0];
    float wsum = fmaxf(sumw, 1e-8f);
    __syncthreads();

    int d = tid & 127;
    bool isv = (tid >= 128);
    const float* src = isv ? g_v : g_k;
    const float* inv = isv ? siv : sik;
    float acc = 0.f;
#pragma unroll 4
    for (int j = 0; j < 256; j++) {
        size_t tj = (size_t)(j >> 6) * Ss + (size_t)i * CH + (j & 63);
        acc += sw[j] * inv[j] * src[tj * Mm + d];
    }
    float mean = acc / wsum;
    red[tid] = mean * mean;
    __syncthreads();
    for (int o = 64; o; o >>= 1) { if ((tid & 127) < o) red[tid] += red[tid + o]; __syncthreads(); }
    float nrm = fmaxf(sqrtf(red[isv ? 128 : 0]), 1e-12f);
    float outv = mean / nrm;
    if (isv) g_Vagg[i * Mm + d] = outv;
    else     g_Kagg[i * Mm + d] = outv;
    if (tid == 0) g_ws[i] = sumw * (1.f / 256.f);
}

// ---------------- attention read + fused r-split + fused mean_ws ----------------
#define ATTN_SMEM ((8192 + 8192 + 4096) * 4)   // kt(/rsm) + vsm + psm = 80KB
__global__ void __launch_bounds__(256) attn_kernel(const float* __restrict__ log_beta,
                                                   float* __restrict__ out, int out_size)
{
    extern __shared__ float sm[];
    float* kt  = sm;               // [d][slot] 128x64 — reused as rsm [tok][dim] later
    float* vsm = kt + 8192;        // [slot][d] 64x128
    float* psm = vsm + 8192;       // [warp][c8][slot]
    __shared__ float str[64];
    __shared__ float ssum;

    int i = blockIdx.x;
    int bb = blockIdx.y;
    int tid = threadIdx.x;
    float beta = expf(log_beta[0]);

    for (int idx = tid; idx < 8192; idx += 256) {
        int d = idx >> 6, slot = idx & 63;
        kt[idx] = g_Kagg[slot * 128 + d];
    }
    for (int idx = tid; idx < 8192; idx += 256) vsm[idx] = g_Vagg[idx];
    if (tid < 64) {
        float dc = powf(0.999f, 64.f);
        float s = 0.f;
        if (tid < i) s = g_ws[tid] * powf(dc, (float)(i - 1 - tid));
        str[tid] = s;
    }
    __syncthreads();
    if (tid == 0) {
        float s = 0.f;
        for (int j = 0; j < 64; j++) s += str[j];
        ssum = s;
        if (i == 0 && bb == 0 && out_size > NTOK * Hh) {
            float m = 0.f;
            for (int j = 0; j < NC; j++) m += g_ws[j];
            out[(size_t)NTOK * Hh] = m / (float)NC;
        }
    }
    __syncthreads();

    bool valid = (ssum >= 1e-8f);
    int w = tid >> 5, lane = tid & 31;
    float m0ok = (str[lane] > 1e-8f)      ? 0.f : -1e9f;
    float m1ok = (str[lane + 32] > 1e-8f) ? 0.f : -1e9f;
    size_t tbase = (size_t)bb * Ss + (size_t)i * CH;
    const float* qg = g_q + (tbase + (size_t)w * 8) * Mm;

    float s0[8], s1[8];
#pragma unroll
    for (int c8 = 0; c8 < 8; c8++) { s0[c8] = 0.f; s1[c8] = 0.f; }
    for (int d4 = 0; d4 < 32; d4++) {
        float kv0[4], kv1[4];
#pragma unroll
        for (int ii = 0; ii < 4; ii++) {
            kv0[ii] = kt[(d4 * 4 + ii) * 64 + lane];
            kv1[ii] = kt[(d4 * 4 + ii) * 64 + 32 + lane];
        }
#pragma unroll
        for (int c8 = 0; c8 < 8; c8++) {
            float4 q = __ldg((const float4*)(qg + (size_t)c8 * Mm + d4 * 4));
            s0[c8] += q.x * kv0[0] + q.y * kv0[1] + q.z * kv0[2] + q.w * kv0[3];
            s1[c8] += q.x * kv1[0] + q.y * kv1[1] + q.z * kv1[2] + q.w * kv1[3];
        }
    }
#pragma unroll
    for (int c8 = 0; c8 < 8; c8++) {
        float sv0 = s0[c8] * beta + m0ok;
        float sv1 = s1[c8] * beta + m1ok;
        float mx = fmaxf(sv0, sv1);
#pragma unroll
        for (int o = 16; o; o >>= 1) mx = fmaxf(mx, __shfl_xor_sync(0xffffffffu, mx, o));
        float p0 = expf(sv0 - mx);
        float p1 = expf(sv1 - mx);
        float sum = p0 + p1;
#pragma unroll
        for (int o = 16; o; o >>= 1) sum += __shfl_xor_sync(0xffffffffu, sum, o);
        float invs = 1.f / sum;
        psm[w * 512 + c8 * 64 + lane]      = p0 * invs;
        psm[w * 512 + c8 * 64 + 32 + lane] = p1 * invs;
    }
    __syncthreads();   // all warps done reading kt (scores) — kt now reusable as rsm

    float a[8][4];
#pragma unroll
    for (int c8 = 0; c8 < 8; c8++)
#pragma unroll
        for (int cc = 0; cc < 4; cc++) a[c8][cc] = 0.f;
    for (int j = 0; j < 64; j++) {
        float v0 = vsm[j * 128 + lane];
        float v1 = vsm[j * 128 + 32 + lane];
        float v2 = vsm[j * 128 + 64 + lane];
        float v3 = vsm[j * 128 + 96 + lane];
#pragma unroll
        for (int c8 = 0; c8 < 8; c8++) {
            float pj = psm[w * 512 + c8 * 64 + j];
            a[c8][0] += pj * v0; a[c8][1] += pj * v1;
            a[c8][2] += pj * v2; a[c8][3] += pj * v3;
        }
    }
    float* rsm = kt;   // [local token][dim]
#pragma unroll
    for (int c8 = 0; c8 < 8; c8++) {
        int lt = w * 8 + c8;
        rsm[lt * 128 + lane]      = valid ? a[c8][0] : 0.f;
        rsm[lt * 128 + lane + 32] = valid ? a[c8][1] : 0.f;
        rsm[lt * 128 + lane + 64] = valid ? a[c8][2] : 0.f;
        rsm[lt * 128 + lane + 96] = valid ? a[c8][3] : 0.f;
    }
    __syncthreads();

    // ---- pack r -> g_rs (bf16 hi/lo tile layout), skipping fp32 round-trip ----
#pragma unroll
    for (int u = 0; u < 4; u++) {
        int c = tid + (u << 8);          // 0..1023 chunks (64 tok x 16)
        int lt = c >> 4, pos = c & 15;
        float4 a0 = *(float4*)(rsm + lt * 128 + pos * 8);
        float4 a1 = *(float4*)(rsm + lt * 128 + pos * 8 + 4);
        uint4 h, lo; pack8(a0, a1, h, lo);
        size_t grow = tbase + lt;
        size_t base = (grow * 4 + (size_t)(pos >> 2)) * 128 + (size_t)(pos & 3) * 16;
        *(uint4*)(g_rs + base)      = h;
        *(uint4*)(g_rs + base + 64) = lo;
    }
}

// ---------------- per-token output norm clamp ----------------
__global__ void __launch_bounds__(256) norm_kernel(float* __restrict__ out)
{
    __shared__ float red[256];
    size_t t = blockIdx.x;
    float* row = out + t * (size_t)Hh;
    int tid = threadIdx.x;
    float4* r4 = (float4*)row;
    float ss = 0.f;
#pragma unroll
    for (int u = 0; u < 2; u++) {
        float4 v = r4[tid + u * 256];
        ss += v.x * v.x + v.y * v.y + v.z * v.z + v.w * v.w;
    }
    red[tid] = ss;
    __syncthreads();
    for (int o = 128; o; o >>= 1) { if (tid < o) red[tid] += red[tid + o]; __syncthreads(); }
    float nrm = fmaxf(sqrtf(red[0]), 1e-6f);
    float sc = fminf(10.f / nrm, 1.f);
    if (sc < 1.f) {
#pragma unroll
        for (int u = 0; u < 2; u++) {
            float4 v = r4[tid + u * 256];
            v.x *= sc; v.y *= sc; v.z *= sc; v.w *= sc;
            r4[tid + u * 256] = v;
        }
    }
}

// ---------------- launch ----------------
extern "C" void kernel_launch(void* const* d_in, const int* in_sizes, int n_in,
                              void* d_out, int out_size)
{
    const float* x  = (const float*)d_in[0];
    const float* Wq = (const float*)d_in[1];
    const float* Wk = (const float*)d_in[2];
    const float* Wv = (const float*)d_in[3];
    const float* Wo = (const float*)d_in[4];
    const float* Wg = (const float*)d_in[5];
    const float* gb = (const float*)d_in[6];
    const float* lb = (const float*)d_in[7];
    float* out = (float*)d_out;

    cudaFuncSetAttribute(attn_kernel, cudaFuncAttributeMaxDynamicSharedMemorySize, ATTN_SMEM);
    cudaFuncSetAttribute(mega_proj, cudaFuncAttributeMaxDynamicSharedMemorySize, MEGA_SMEM);
    cudaFuncSetAttribute(out_mma,  cudaFuncAttributeMaxDynamicSharedMemorySize, GEMM_SMEM);

    // 1. all weight splits in one launch
    wsplit<<<dim3(128, 4), 256>>>(Wq, Wk, Wv, Wo);
    // 2. fused split + gate + q/k/v projections
    mega_proj<<<NTOK / 64, 256, MEGA_SMEM>>>(x, Wg, gb);
    // 3. per-chunk write aggregates
    agg_kernel<<<NC, 256>>>();
    // 4. attention reads (+ fused r-split + mean_ws)
    attn_kernel<<<dim3(NC, Bb), 256, ATTN_SMEM>>>(lb, out, out_size);
    // 5. output projection
    out_mma<<<dim3(NTOK / 128, Hh / 128), 256, GEMM_SMEM>>>(out);
    // 6. norm clamp
    norm_kernel<<<NTOK, 256>>>(out);
}

// round 11
// speedup vs baseline: 3.9494x; 1.0116x over previous
#include <cuda_runtime.h>
#include <cuda_bf16.h>
#include <math.h>
#include <stdint.h>

#define Bb 4
#define Ss 4096
#define Hh 2048
#define Mm 128
#define CH 64
#define NC 64
#define NSLOTS 64
#define NTOK (Bb*Ss)   // 16384

// ---------------- scratch (static device globals; no allocation) ----------------
__device__ float g_q[NTOK*Mm];
__device__ float g_k[NTOK*Mm];
__device__ float g_v[NTOK*Mm];
__device__ float g_w[NTOK];
__device__ float g_Kagg[NSLOTS*Mm];
__device__ float g_Vagg[NSLOTS*Mm];
__device__ float g_ws[NSLOTS];
__device__ __align__(128) unsigned char g_rs [(size_t)NTOK * Mm * 4];   // split r
__device__ __align__(128) unsigned char g_wqs[(size_t)Mm * Hh * 4];
__device__ __align__(128) unsigned char g_wks[(size_t)Mm * Hh * 4];
__device__ __align__(128) unsigned char g_wvs[(size_t)Mm * Hh * 4];
__device__ __align__(128) unsigned char g_wos[(size_t)Hh * Mm * 4];

// ================= helpers =================
__device__ __forceinline__ uint32_t smem_u32(const void* p){
    uint32_t a;
    asm("{ .reg .u64 t; cvta.to.shared.u64 t, %1; cvt.u32.u64 %0, t; }" : "=r"(a) : "l"(p));
    return a;
}
__device__ __forceinline__ uint32_t bf2(float x, float y){
    uint32_t r; asm("cvt.rn.bf16x2.f32 %0, %1, %2;" : "=r"(r) : "f"(y), "f"(x)); return r;
}
__device__ __forceinline__ uint32_t swz(uint32_t x){ return x ^ ((x >> 3) & 0x70); }

__device__ __forceinline__ void pack4(float4 a, uint2& h, uint2& lo){
    h.x = bf2(a.x, a.y); h.y = bf2(a.z, a.w);
    float l0 = a.x - __uint_as_float(h.x << 16);
    float l1 = a.y - __uint_as_float(h.x & 0xffff0000u);
    float l2 = a.z - __uint_as_float(h.y << 16);
    float l3 = a.w - __uint_as_float(h.y & 0xffff0000u);
    lo.x = bf2(l0, l1); lo.y = bf2(l2, l3);
}
__device__ __forceinline__ void pack8(float4 a0, float4 a1, uint4& h, uint4& lo){
    uint2 h0, l0, h1, l1;
    pack4(a0, h0, l0); pack4(a1, h1, l1);
    h.x = h0.x; h.y = h0.y; h.z = h1.x; h.w = h1.y;
    lo.x = l0.x; lo.y = l0.y; lo.z = l1.x; lo.w = l1.y;
}

#define LDSM4(r, addr) \
    asm volatile("ldmatrix.sync.aligned.m8n8.x4.shared.b16 {%0,%1,%2,%3}, [%4];" \
        : "=r"((r)[0]), "=r"((r)[1]), "=r"((r)[2]), "=r"((r)[3]) : "r"(addr))

#define MMA16816(d, a, b0, b1) \
    asm volatile("mma.sync.aligned.m16n8k16.row.col.f32.bf16.bf16.f32 " \
        "{%0,%1,%2,%3}, {%4,%5,%6,%7}, {%8,%9}, {%0,%1,%2,%3};" \
        : "+f"((d)[0]), "+f"((d)[1]), "+f"((d)[2]), "+f"((d)[3]) \
        : "r"((a)[0]), "r"((a)[1]), "r"((a)[2]), "r"((a)[3]), "r"(b0), "r"(b1))

#define CP16(dst, src) \
    asm volatile("cp.async.cg.shared.global [%0], [%1], 16;" :: "r"(dst), "l"(src) : "memory")
#define CP_COMMIT() asm volatile("cp.async.commit_group;" ::: "memory")
#define CP_WAIT1()  asm volatile("cp.async.wait_group 1;" ::: "memory")

// ======================================================================
// mega_proj v3b: A via registers (ldg prefetch + in-reg split), B via
// cp.async 3-stage; ONE barrier per K-block; split(kb+1) overlaps MMA(kb).
// FIX vs v3: barrier after Wg preload, before split_phase(0).
// ======================================================================
#define PNSTG 3
#define BSP_OFF(s, z) ((s) * 49152 + (z) * 16384)   // 0..147455
#define ABF_OFF(p)    (147456 + (p) * 8192)          // double ABF
#define WG_OFF        163840
#define MEGA_SMEM     172032                         // 168 KB

__global__ void __launch_bounds__(256, 1) mega_proj(const float* __restrict__ x,
                                                    const float* __restrict__ Wg,
                                                    const float* __restrict__ gb)
{
    extern __shared__ __align__(1024) char smem[];
    __shared__ float gred[64][8];
    int tid = threadIdx.x;
    int w = tid >> 5, l = tid & 31;
    int m0 = blockIdx.x * 64;
    uint32_t smb = smem_u32(smem);
    const int NB = Hh / 32;   // 64

    unsigned long long gWq = (unsigned long long)__cvta_generic_to_global(g_wqs);
    unsigned long long gWk = (unsigned long long)__cvta_generic_to_global(g_wks);
    unsigned long long gWv = (unsigned long long)__cvta_generic_to_global(g_wvs);

    {
        const float4* wg4 = (const float4*)Wg;
        float4 w0 = wg4[2 * tid], w1 = wg4[2 * tid + 1];
        *(float4*)(smem + WG_OFF + tid * 32)      = w0;
        *(float4*)(smem + WG_OFF + tid * 32 + 16) = w1;
    }

    int rowA0 = tid >> 3;            // 0..31
    int rowA1 = 32 + (tid >> 3);     // 32..63
    int chk   = tid & 7;             // 0..7

    auto issueB = [&](int kb) {
        int s = kb % PNSTG;
        unsigned long long gws[3] = {gWq, gWk, gWv};
#pragma unroll
        for (int z = 0; z < 3; z++) {
            uint32_t stB = smb + BSP_OFF(s, z);
#pragma unroll
            for (int u = 0; u < 4; u++) {
                int c = tid + (u << 8);
                int row = c >> 3;
                uint32_t seg = (uint32_t)(c & 7) << 4;
                unsigned long long src = gws[z] + ((unsigned long long)row * NB + kb) * 128ull + seg;
                CP16(stB + swz(((uint32_t)row << 7) + seg), src);
            }
        }
    };

    auto ldgA = [&](int kb, float4& a0, float4& a1) {
        const float* base = x + (size_t)kb * 32 + chk * 4;
        a0 = __ldg((const float4*)(base + (size_t)(m0 + rowA0) * Hh));
        a1 = __ldg((const float4*)(base + (size_t)(m0 + rowA1) * Hh));
    };

    float gp0 = 0.f, gp1 = 0.f;

    auto split_phase = [&](int kb, float4 a0, float4 a1) {
        char* abf = smem + ABF_OFF(kb & 1);
        const float* wgs = (const float*)(smem + WG_OFF) + kb * 32 + chk * 4;
        float wg0 = wgs[0], wg1 = wgs[1], wg2 = wgs[2], wg3 = wgs[3];
        gp0 += a0.x * wg0 + a0.y * wg1 + a0.z * wg2 + a0.w * wg3;
        gp1 += a1.x * wg0 + a1.y * wg1 + a1.z * wg2 + a1.w * wg3;
        uint2 h0, lo0, h1, lo1;
        pack4(a0, h0, lo0);
        pack4(a1, h1, lo1);
        uint32_t b0 = (uint32_t)rowA0 * 128 + (uint32_t)chk * 8;
        uint32_t b1 = (uint32_t)rowA1 * 128 + (uint32_t)chk * 8;
        *(uint2*)(abf + swz(b0))      = h0;
        *(uint2*)(abf + swz(b0 + 64)) = lo0;
        *(uint2*)(abf + swz(b1))      = h1;
        *(uint2*)(abf + swz(b1 + 64)) = lo1;
    };

    float acc[3][2][4][4];
#pragma unroll
    for (int z = 0; z < 3; z++)
#pragma unroll
        for (int mi = 0; mi < 2; mi++)
#pragma unroll
            for (int nj = 0; nj < 4; nj++)
#pragma unroll
                for (int cc = 0; cc < 4; cc++) acc[z][mi][nj][cc] = 0.f;

    int mw = w >> 2;          // 0..1
    int nw = w & 3;           // 0..3
    int lr = l & 15, lh = l >> 4;

    // preamble
    issueB(0); CP_COMMIT();
    issueB(1); CP_COMMIT();
    float4 a0, a1;
    ldgA(0, a0, a1);
    __syncthreads();                 // Wg preload visible to ALL threads (v3 bug fix)
    split_phase(0, a0, a1);          // writes ABF[0]
    ldgA(1, a0, a1);                 // prefetch for split(1)

    for (int kb = 0; kb < NB; kb++) {
        CP_WAIT1();                  // B stage kb arrived (thread-local)
        __syncthreads();             // stage kb + ABF[kb&1] visible; ABF[(kb+1)&1] free
        if (kb + 2 < NB) { issueB(kb + 2); }
        CP_COMMIT();
        if (kb + 1 < NB) {
            split_phase(kb + 1, a0, a1);   // writes ABF[(kb+1)&1], overlaps MMA below
            int kn = (kb + 2 < NB) ? (kb + 2) : (NB - 1);
            ldgA(kn, a0, a1);
        }

        // ---- MMA(kb): ABF[kb&1] + B stage kb%3 ----
        int s = kb % PNSTG;
        uint32_t sAu = smb + ABF_OFF(kb & 1);
#pragma unroll
        for (int ks = 0; ks < 2; ks++) {
            uint32_t kbyte = (uint32_t)(ks << 5) + (lh << 4);
            uint32_t Ah[2][4], Al[2][4];
#pragma unroll
            for (int t = 0; t < 2; t++) {
                uint32_t ro = (uint32_t)((mw * 32 + (t << 4) + lr) << 7) + kbyte;
                LDSM4(Ah[t], sAu + swz(ro));
                LDSM4(Al[t], sAu + swz(ro + 64));
            }
#pragma unroll
            for (int z = 0; z < 3; z++) {
                uint32_t sBu = smb + BSP_OFF(s, z);
                uint32_t Bh[2][4], Bl[2][4];
#pragma unroll
                for (int p = 0; p < 2; p++) {
                    uint32_t ro = (uint32_t)((nw * 32 + (p << 4) + lr) << 7) + kbyte;
                    LDSM4(Bh[p], sBu + swz(ro));
                    LDSM4(Bl[p], sBu + swz(ro + 64));
                }
#pragma unroll
                for (int mi = 0; mi < 2; mi++)
#pragma unroll
                    for (int p = 0; p < 2; p++)
#pragma unroll
                        for (int j = 0; j < 2; j++) {
                            int nj = p * 2 + j;
                            MMA16816(acc[z][mi][nj], Ah[mi], Bh[p][j], Bh[p][j + 2]);
                            MMA16816(acc[z][mi][nj], Ah[mi], Bl[p][j], Bl[p][j + 2]);
                            MMA16816(acc[z][mi][nj], Al[mi], Bh[p][j], Bh[p][j + 2]);
                        }
            }
        }
    }

    // ---- gate reduce ----
    gred[rowA0][chk] = gp0;
    gred[rowA1][chk] = gp1;
    __syncthreads();
    if (tid < 64) {
        float s = 0.f;
#pragma unroll
        for (int j = 0; j < 8; j++) s += gred[tid][j];
        g_w[m0 + tid] = 1.f / (1.f + expf(-(s + gb[0])));
    }

    // ---- epilogue ----
    float* Cs[3] = {g_q, g_k, g_v};
#pragma unroll
    for (int z = 0; z < 3; z++) {
#pragma unroll
        for (int mi = 0; mi < 2; mi++) {
            int r0 = mw * 32 + (mi << 4) + (l >> 2);
#pragma unroll
            for (int nj = 0; nj < 4; nj++) {
                float* p = Cs[z] + (size_t)(m0 + r0) * Mm + nw * 32 + (nj << 3) + ((l & 3) << 1);
                *(float2*)p = make_float2(acc[z][mi][nj][0], acc[z][mi][nj][1]);
                *(float2*)(p + (size_t)8 * Mm) = make_float2(acc[z][mi][nj][2], acc[z][mi][nj][3]);
            }
        }
    }
}

// ======================================================================
// out gemm: pre-split operands, 2-stage cp.async, 2 CTAs/SM
// ======================================================================
#define NSTG 2
#define STAGE_B 32768
#define GEMM_SMEM (NSTG * STAGE_B)   // 64 KB

__global__ void __launch_bounds__(256, 2) out_mma(float* __restrict__ out)
{
    extern __shared__ __align__(1024) char smem[];
    int n0 = blockIdx.y * 128;
    int m0 = blockIdx.x * 128;
    const unsigned char* As = g_rs;
    const unsigned char* Bs = g_wos + (size_t)n0 * 4 * 128;
    float* C = out + n0;
    const int NB = Mm / 32, ldc = Hh;

    int tid = threadIdx.x;
    int w = tid >> 5, l = tid & 31;
    uint32_t smb = smem_u32(smem);
    unsigned long long gA = (unsigned long long)__cvta_generic_to_global(As);
    unsigned long long gB = (unsigned long long)__cvta_generic_to_global(Bs);

    auto issue = [&](int kb) {
        uint32_t st = smb + (uint32_t)(kb & (NSTG - 1)) * STAGE_B;
#pragma unroll
        for (int u = 0; u < 4; u++) {
            int c = tid + (u << 8);
            int row = c >> 3;
            uint32_t seg = (uint32_t)(c & 7) << 4;
            unsigned long long srcA = gA + ((unsigned long long)(m0 + row) * NB + kb) * 128ull + seg;
            unsigned long long srcB = gB + ((unsigned long long)row * NB + kb) * 128ull + seg;
            uint32_t d = swz(((uint32_t)row << 7) + seg);
            CP16(st + d, srcA);
            CP16(st + 16384 + d, srcB);
        }
    };

    float acc[2][8][4];
#pragma unroll
    for (int mi = 0; mi < 2; mi++)
#pragma unroll
        for (int nj = 0; nj < 8; nj++)
#pragma unroll
            for (int cc = 0; cc < 4; cc++) acc[mi][nj][cc] = 0.f;

    int wm = (w >> 1) << 5;
    int wn = (w & 1) << 6;
    int lr = l & 15, lh = l >> 4;

    issue(0); CP_COMMIT();
    issue(1); CP_COMMIT();

    for (int kb = 0; kb < NB; kb++) {
        CP_WAIT1();
        __syncthreads();
        uint32_t sAu = smb + (uint32_t)(kb & (NSTG - 1)) * STAGE_B;
        uint32_t sBu = sAu + 16384;
#pragma unroll
        for (int ks = 0; ks < 2; ks++) {
            uint32_t kbyte = (uint32_t)(ks << 5) + (lh << 4);
            uint32_t Ah[2][4], Al[2][4], Bh[4][4], Bl[4][4];
#pragma unroll
            for (int t = 0; t < 2; t++) {
                uint32_t ro = (uint32_t)((wm + (t << 4) + lr) << 7) + kbyte;
                LDSM4(Ah[t], sAu + swz(ro));
                LDSM4(Al[t], sAu + swz(ro + 64));
            }
#pragma unroll
            for (int g = 0; g < 4; g++) {
                uint32_t ro = (uint32_t)((wn + (g << 4) + lr) << 7) + kbyte;
                LDSM4(Bh[g], sBu + swz(ro));
                LDSM4(Bl[g], sBu + swz(ro + 64));
            }
#pragma unroll
            for (int mi = 0; mi < 2; mi++)
#pragma unroll
                for (int nj = 0; nj < 8; nj++) {
                    int g = nj >> 1, p = nj & 1;
                    MMA16816(acc[mi][nj], Ah[mi], Bh[g][p], Bh[g][p + 2]);
                    MMA16816(acc[mi][nj], Ah[mi], Bl[g][p], Bl[g][p + 2]);
                    MMA16816(acc[mi][nj], Al[mi], Bh[g][p], Bh[g][p + 2]);
                }
        }
        __syncthreads();
        if (kb + NSTG < NB) issue(kb + NSTG);
        CP_COMMIT();
    }

#pragma unroll
    for (int mi = 0; mi < 2; mi++) {
        int r0 = wm + (mi << 4) + (l >> 2);
#pragma unroll
        for (int nj = 0; nj < 8; nj++) {
            float* p = C + (size_t)(m0 + r0) * ldc + wn + (nj << 3) + ((l & 3) << 1);
            *(float2*)p = make_float2(acc[mi][nj][0], acc[mi][nj][1]);
            *(float2*)(p + (size_t)8 * ldc) = make_float2(acc[mi][nj][2], acc[mi][nj][3]);
        }
    }
}

// ---------------- fused weight splits (one launch, 4 matrices) ----------------
__global__ void __launch_bounds__(256) wsplit(const float* __restrict__ Wq,
                                              const float* __restrict__ Wk,
                                              const float* __restrict__ Wv,
                                              const float* __restrict__ Wo)
{
    int z = blockIdx.y;
    const float* src; unsigned char* dst; int K;
    if (z == 0)      { src = Wq; dst = g_wqs; K = Hh; }
    else if (z == 1) { src = Wk; dst = g_wks; K = Hh; }
    else if (z == 2) { src = Wv; dst = g_wvs; K = Hh; }
    else             { src = Wo; dst = g_wos; K = Mm; }
    int cpr = K >> 3, nkb = K >> 5;
    int g = blockIdx.x * 256 + threadIdx.x;
    int row = g / cpr, pos = g - row * cpr;
    const float4* s = (const float4*)(src + (size_t)row * K + (size_t)pos * 8);
    float4 a0 = s[0], a1 = s[1];
    uint4 h, lo; pack8(a0, a1, h, lo);
    size_t base = ((size_t)row * nkb + (pos >> 2)) * 128 + (size_t)(pos & 3) * 16;
    *(uint4*)(dst + base)      = h;
    *(uint4*)(dst + base + 64) = lo;
}

// ---------------- per-chunk aggregates ----------------
__global__ void __launch_bounds__(256) agg_kernel()
{
    int i = blockIdx.x;
    int tid = threadIdx.x;
    __shared__ float sw[256];
    __shared__ float sik[256];
    __shared__ float siv[256];
    __shared__ float red[256];
    {
        int b = tid >> 6, c = tid & 63;
        size_t t = (size_t)b * Ss + (size_t)i * CH + c;
        const float4* kr4 = (const float4*)(g_k + t * Mm);
        const float4* vr4 = (const float4*)(g_v + t * Mm);
        float nk = 0.f, nv = 0.f;
#pragma unroll 4
        for (int d = 0; d < 32; d++) {
            float4 a = kr4[d]; nk += a.x * a.x + a.y * a.y + a.z * a.z + a.w * a.w;
            float4 u = vr4[d]; nv += u.x * u.x + u.y * u.y + u.z * u.z + u.w * u.w;
        }
        sik[tid] = 1.f / fmaxf(sqrtf(nk), 1e-12f);
        siv[tid] = 1.f / fmaxf(sqrtf(nv), 1e-12f);
        float wv = g_w[t];
        sw[tid] = wv;
        red[tid] = wv;
    }
    __syncthreads();
    for (int o = 128; o; o >>= 1) { if (tid < o) red[tid] += red[tid + o]; __syncthreads(); }
    float sumw = red[0];
    float wsum = fmaxf(sumw, 1e-8f);
    __syncthreads();

    int d = tid & 127;
    bool isv = (tid >= 128);
    const float* src = isv ? g_v : g_k;
    const float* inv = isv ? siv : sik;
    float acc = 0.f;
#pragma unroll 4
    for (int j = 0; j < 256; j++) {
        size_t tj = (size_t)(j >> 6) * Ss + (size_t)i * CH + (j & 63);
        acc += sw[j] * inv[j] * src[tj * Mm + d];
    }
    float mean = acc / wsum;
    red[tid] = mean * mean;
    __syncthreads();
    for (int o = 64; o; o >>= 1) { if ((tid & 127) < o) red[tid] += red[tid + o]; __syncthreads(); }
    float nrm = fmaxf(sqrtf(red[isv ? 128 : 0]), 1e-12f);
    float outv = mean / nrm;
    if (isv) g_Vagg[i * Mm + d] = outv;
    else     g_Kagg[i * Mm + d] = outv;
    if (tid == 0) g_ws[i] = sumw * (1.f / 256.f);
}

// ---------------- attention read + fused r-split + fused mean_ws ----------------
#define ATTN_SMEM ((8192 + 8192 + 4096 + 8192) * 4)   // kt(/rsm) + vsm + psm + qsm = 112KB
__global__ void __launch_bounds__(256) attn_kernel(const float* __restrict__ log_beta,
                                                   float* __restrict__ out, int out_size)
{
    extern __shared__ float sm[];
    float* kt  = sm;               // [d][slot] 128x64 — reused as rsm later
    float* vsm = kt + 8192;        // [slot][d] 64x128
    float* psm = vsm + 8192;       // [warp][c8][slot]
    float* qsm = psm + 4096;       // [tok][d] 64x128
    __shared__ float str[64];
    __shared__ float ssum;

    int i = blockIdx.x;
    int bb = blockIdx.y;
    int tid = threadIdx.x;
    float beta = expf(log_beta[0]);
    size_t tbase = (size_t)bb * Ss + (size_t)i * CH;

    for (int idx = tid; idx < 8192; idx += 256) {
        int d = idx >> 6, slot = idx & 63;
        kt[idx] = g_Kagg[slot * 128 + d];
    }
    for (int idx = tid; idx < 8192; idx += 256) vsm[idx] = g_Vagg[idx];
    for (int idx = tid; idx < 8192; idx += 256)
        qsm[idx] = g_q[(tbase + (size_t)(idx >> 7)) * Mm + (idx & 127)];
    if (tid < 64) {
        float dc = powf(0.999f, 64.f);
        float s = 0.f;
        if (tid < i) s = g_ws[tid] * powf(dc, (float)(i - 1 - tid));
        str[tid] = s;
    }
    __syncthreads();
    if (tid == 0) {
        float s = 0.f;
        for (int j = 0; j < 64; j++) s += str[j];
        ssum = s;
        if (i == 0 && bb == 0 && out_size > NTOK * Hh) {
            float m = 0.f;
            for (int j = 0; j < NC; j++) m += g_ws[j];
            out[(size_t)NTOK * Hh] = m / (float)NC;
        }
    }
    __syncthreads();

    bool valid = (ssum >= 1e-8f);
    int w = tid >> 5, lane = tid & 31;
    float m0ok = (str[lane] > 1e-8f)      ? 0.f : -1e9f;
    float m1ok = (str[lane + 32] > 1e-8f) ? 0.f : -1e9f;

    float s0[8], s1[8];
#pragma unroll
    for (int c8 = 0; c8 < 8; c8++) { s0[c8] = 0.f; s1[c8] = 0.f; }
    for (int d4 = 0; d4 < 32; d4++) {
        float kv0[4], kv1[4];
#pragma unroll
        for (int ii = 0; ii < 4; ii++) {
            kv0[ii] = kt[(d4 * 4 + ii) * 64 + lane];
            kv1[ii] = kt[(d4 * 4 + ii) * 64 + 32 + lane];
        }
#pragma unroll
        for (int c8 = 0; c8 < 8; c8++) {
            float4 q = *(const float4*)(qsm + (w * 8 + c8) * 128 + d4 * 4);  // LDS broadcast
            s0[c8] += q.x * kv0[0] + q.y * kv0[1] + q.z * kv0[2] + q.w * kv0[3];
            s1[c8] += q.x * kv1[0] + q.y * kv1[1] + q.z * kv1[2] + q.w * kv1[3];
        }
    }
#pragma unroll
    for (int c8 = 0; c8 < 8; c8++) {
        float sv0 = s0[c8] * beta + m0ok;
        float sv1 = s1[c8] * beta + m1ok;
        float mx = fmaxf(sv0, sv1);
#pragma unroll
        for (int o = 16; o; o >>= 1) mx = fmaxf(mx, __shfl_xor_sync(0xffffffffu, mx, o));
        float p0 = expf(sv0 - mx);
        float p1 = expf(sv1 - mx);
        float sum = p0 + p1;
#pragma unroll
        for (int o = 16; o; o >>= 1) sum += __shfl_xor_sync(0xffffffffu, sum, o);
        float invs = 1.f / sum;
        psm[w * 512 + c8 * 64 + lane]      = p0 * invs;
        psm[w * 512 + c8 * 64 + 32 + lane] = p1 * invs;
    }
    __syncthreads();   // all warps done with kt — reusable as rsm

    float a[8][4];
#pragma unroll
    for (int c8 = 0; c8 < 8; c8++)
#pragma unroll
        for (int cc = 0; cc < 4; cc++) a[c8][cc] = 0.f;
    for (int j = 0; j < 64; j++) {
        float v0 = vsm[j * 128 + lane];
        float v1 = vsm[j * 128 + 32 + lane];
        float v2 = vsm[j * 128 + 64 + lane];
        float v3 = vsm[j * 128 + 96 + lane];
#pragma unroll
        for (int c8 = 0; c8 < 8; c8++) {
            float pj = psm[w * 512 + c8 * 64 + j];
            a[c8][0] += pj * v0; a[c8][1] += pj * v1;
            a[c8][2] += pj * v2; a[c8][3] += pj * v3;
        }
    }
    float* rsm = kt;
#pragma unroll
    for (int c8 = 0; c8 < 8; c8++) {
        int lt = w * 8 + c8;
        rsm[lt * 128 + lane]      = valid ? a[c8][0] : 0.f;
        rsm[lt * 128 + lane + 32] = valid ? a[c8][1] : 0.f;
        rsm[lt * 128 + lane + 64] = valid ? a[c8][2] : 0.f;
        rsm[lt * 128 + lane + 96] = valid ? a[c8][3] : 0.f;
    }
    __syncthreads();

    // ---- pack r -> g_rs (bf16 hi/lo tile layout) ----
#pragma unroll
    for (int u = 0; u < 4; u++) {
        int c = tid + (u << 8);
        int lt = c >> 4, pos = c & 15;
        float4 a0 = *(float4*)(rsm + lt * 128 + pos * 8);
        float4 a1 = *(float4*)(rsm + lt * 128 + pos * 8 + 4);
        uint4 h, lo; pack8(a0, a1, h, lo);
        size_t grow = tbase + lt;
        size_t base = (grow * 4 + (size_t)(pos >> 2)) * 128 + (size_t)(pos & 3) * 16;
        *(uint4*)(g_rs + base)      = h;
        *(uint4*)(g_rs + base + 64) = lo;
    }
}

// ---------------- per-token output norm clamp ----------------
__global__ void __launch_bounds__(256) norm_kernel(float* __restrict__ out)
{
    __shared__ float red[256];
    size_t t = blockIdx.x;
    float* row = out + t * (size_t)Hh;
    int tid = threadIdx.x;
    float4* r4 = (float4*)row;
    float ss = 0.f;
#pragma unroll
    for (int u = 0; u < 2; u++) {
        float4 v = r4[tid + u * 256];
        ss += v.x * v.x + v.y * v.y + v.z * v.z + v.w * v.w;
    }
    red[tid] = ss;
    __syncthreads();
    for (int o = 128; o; o >>= 1) { if (tid < o) red[tid] += red[tid + o]; __syncthreads(); }
    float nrm = fmaxf(sqrtf(red[0]), 1e-6f);
    float sc = fminf(10.f / nrm, 1.f);
    if (sc < 1.f) {
#pragma unroll
        for (int u = 0; u < 2; u++) {
            float4 v = r4[tid + u * 256];
            v.x *= sc; v.y *= sc; v.z *= sc; v.w *= sc;
            r4[tid + u * 256] = v;
        }
    }
}

// ---------------- launch ----------------
extern "C" void kernel_launch(void* const* d_in, const int* in_sizes, int n_in,
                              void* d_out, int out_size)
{
    const float* x  = (const float*)d_in[0];
    const float* Wq = (const float*)d_in[1];
    const float* Wk = (const float*)d_in[2];
    const float* Wv = (const float*)d_in[3];
    const float* Wo = (const float*)d_in[4];
    const float* Wg = (const float*)d_in[5];
    const float* gb = (const float*)d_in[6];
    const float* lb = (const float*)d_in[7];
    float* out = (float*)d_out;

    cudaFuncSetAttribute(attn_kernel, cudaFuncAttributeMaxDynamicSharedMemorySize, ATTN_SMEM);
    cudaFuncSetAttribute(mega_proj, cudaFuncAttributeMaxDynamicSharedMemorySize, MEGA_SMEM);
    cudaFuncSetAttribute(out_mma,  cudaFuncAttributeMaxDynamicSharedMemorySize, GEMM_SMEM);

    // 1. all weight splits in one launch
    wsplit<<<dim3(128, 4), 256>>>(Wq, Wk, Wv, Wo);
    // 2. fused split + gate + q/k/v projections (A via regs, 1 barrier/K-block)
    mega_proj<<<NTOK / 64, 256, MEGA_SMEM>>>(x, Wg, gb);
    // 3. per-chunk write aggregates
    agg_kernel<<<NC, 256>>>();
    // 4. attention reads (+ fused r-split + mean_ws)
    attn_kernel<<<dim3(NC, Bb), 256, ATTN_SMEM>>>(lb, out, out_size);
    // 5. output projection
    out_mma<<<dim3(NTOK / 128, Hh / 128), 256, GEMM_SMEM>>>(out);
    // 6. norm clamp
    norm_kernel<<<NTOK, 256>>>(out);
}

// round 12
// speedup vs baseline: 4.0367x; 1.0221x over previous
#include <cuda_runtime.h>
#include <cuda_bf16.h>
#include <math.h>
#include <stdint.h>

#define Bb 4
#define Ss 4096
#define Hh 2048
#define Mm 128
#define CH 64
#define NC 64
#define NSLOTS 64
#define NTOK (Bb*Ss)   // 16384

// ---------------- scratch (static device globals; no allocation) ----------------
__device__ float g_q[NTOK*Mm];
__device__ float g_k[NTOK*Mm];
__device__ float g_v[NTOK*Mm];
__device__ float g_w[NTOK];
__device__ float g_Kagg[NSLOTS*Mm];
__device__ float g_Vagg[NSLOTS*Mm];
__device__ float g_ws[NSLOTS];
__device__ __align__(128) unsigned char g_rs [(size_t)NTOK * Mm * 4];   // split r
__device__ __align__(128) unsigned char g_wqs[(size_t)Mm * Hh * 4];
__device__ __align__(128) unsigned char g_wks[(size_t)Mm * Hh * 4];
__device__ __align__(128) unsigned char g_wvs[(size_t)Mm * Hh * 4];
__device__ __align__(128) unsigned char g_wos[(size_t)Hh * Mm * 4];

// ================= helpers =================
__device__ __forceinline__ uint32_t smem_u32(const void* p){
    uint32_t a;
    asm("{ .reg .u64 t; cvta.to.shared.u64 t, %1; cvt.u32.u64 %0, t; }" : "=r"(a) : "l"(p));
    return a;
}
__device__ __forceinline__ uint32_t bf2(float x, float y){
    uint32_t r; asm("cvt.rn.bf16x2.f32 %0, %1, %2;" : "=r"(r) : "f"(y), "f"(x)); return r;
}
__device__ __forceinline__ uint32_t swz(uint32_t x){ return x ^ (((x) >> 3) & 0x70); }

__device__ __forceinline__ void pack4(float4 a, uint2& h, uint2& lo){
    h.x = bf2(a.x, a.y); h.y = bf2(a.z, a.w);
    float l0 = a.x - __uint_as_float(h.x << 16);
    float l1 = a.y - __uint_as_float(h.x & 0xffff0000u);
    float l2 = a.z - __uint_as_float(h.y << 16);
    float l3 = a.w - __uint_as_float(h.y & 0xffff0000u);
    lo.x = bf2(l0, l1); lo.y = bf2(l2, l3);
}
__device__ __forceinline__ void pack8(float4 a0, float4 a1, uint4& h, uint4& lo){
    uint2 h0, l0, h1, l1;
    pack4(a0, h0, l0); pack4(a1, h1, l1);
    h.x = h0.x; h.y = h0.y; h.z = h1.x; h.w = h1.y;
    lo.x = l0.x; lo.y = l0.y; lo.z = l1.x; lo.w = l1.y;
}

#define LDSM4(r, addr) \
    asm volatile("ldmatrix.sync.aligned.m8n8.x4.shared.b16 {%0,%1,%2,%3}, [%4];" \
        : "=r"((r)[0]), "=r"((r)[1]), "=r"((r)[2]), "=r"((r)[3]) : "r"(addr))

#define MMA16816(d, a, b0, b1) \
    asm volatile("mma.sync.aligned.m16n8k16.row.col.f32.bf16.bf16.f32 " \
        "{%0,%1,%2,%3}, {%4,%5,%6,%7}, {%8,%9}, {%0,%1,%2,%3};" \
        : "+f"((d)[0]), "+f"((d)[1]), "+f"((d)[2]), "+f"((d)[3]) \
        : "r"((a)[0]), "r"((a)[1]), "r"((a)[2]), "r"((a)[3]), "r"(b0), "r"(b1))

#define CP16(dst, src) \
    asm volatile("cp.async.cg.shared.global [%0], [%1], 16;" :: "r"(dst), "l"(src) : "memory")
#define CP_COMMIT() asm volatile("cp.async.commit_group;" ::: "memory")
#define CP_WAIT1()  asm volatile("cp.async.wait_group 1;" ::: "memory")

// ======================================================================
// mega_proj v4: 512 threads / 16 warps (4 per SMSP) for latency hiding.
// A via registers (ldg prefetch + in-reg split), B via cp.async 3-stage;
// ONE barrier per K-block; split(kb+1) overlaps MMA(kb).
// ======================================================================
#define PNSTG 3
#define BSP_OFF(s, z) ((s) * 49152 + (z) * 16384)   // 0..147455
#define ABF_OFF(p)    (147456 + (p) * 8192)          // double ABF
#define WG_OFF        163840
#define MEGA_SMEM     172032                         // 168 KB

__global__ void __launch_bounds__(512, 1) mega_proj(const float* __restrict__ x,
                                                    const float* __restrict__ Wg,
                                                    const float* __restrict__ gb)
{
    extern __shared__ __align__(1024) char smem[];
    __shared__ float gred[64][8];
    int tid = threadIdx.x;
    int w = tid >> 5, l = tid & 31;
    int m0 = blockIdx.x * 64;
    uint32_t smb = smem_u32(smem);
    const int NB = Hh / 32;   // 64

    unsigned long long gWq = (unsigned long long)__cvta_generic_to_global(g_wqs);
    unsigned long long gWk = (unsigned long long)__cvta_generic_to_global(g_wks);
    unsigned long long gWv = (unsigned long long)__cvta_generic_to_global(g_wvs);

    {
        const float4* wg4 = (const float4*)Wg;
        *(float4*)(smem + WG_OFF + tid * 16) = wg4[tid];
    }

    int row = tid >> 3;     // 0..63 (one row per thread)
    int chk = tid & 7;      // 0..7

    auto issueB = [&](int kb) {
        int s = kb % PNSTG;
        unsigned long long gws[3] = {gWq, gWk, gWv};
#pragma unroll
        for (int z = 0; z < 3; z++) {
            uint32_t stB = smb + BSP_OFF(s, z);
#pragma unroll
            for (int u = 0; u < 2; u++) {
                int c = tid + (u << 9);              // 0..1023
                int r = c >> 3;
                uint32_t seg = (uint32_t)(c & 7) << 4;
                unsigned long long src = gws[z] + ((unsigned long long)r * NB + kb) * 128ull + seg;
                CP16(stB + swz(((uint32_t)r << 7) + seg), src);
            }
        }
    };

    auto ldgA = [&](int kb, float4& a0) {
        a0 = __ldg((const float4*)(x + (size_t)(m0 + row) * Hh + (size_t)kb * 32 + chk * 4));
    };

    float gp0 = 0.f;

    auto split_phase = [&](int kb, float4 a0) {
        char* abf = smem + ABF_OFF(kb & 1);
        const float* wgs = (const float*)(smem + WG_OFF) + kb * 32 + chk * 4;
        gp0 += a0.x * wgs[0] + a0.y * wgs[1] + a0.z * wgs[2] + a0.w * wgs[3];
        uint2 h0, lo0;
        pack4(a0, h0, lo0);
        uint32_t b0 = (uint32_t)row * 128 + (uint32_t)chk * 8;
        *(uint2*)(abf + swz(b0))      = h0;
        *(uint2*)(abf + swz(b0 + 64)) = lo0;
    };

    float acc[3][2][2][4];
#pragma unroll
    for (int z = 0; z < 3; z++)
#pragma unroll
        for (int mi = 0; mi < 2; mi++)
#pragma unroll
            for (int nj = 0; nj < 2; nj++)
#pragma unroll
                for (int cc = 0; cc < 4; cc++) acc[z][mi][nj][cc] = 0.f;

    int mw = w >> 3;          // 0..1 (32-row half)
    int nw = w & 7;           // 0..7 (16-col group)
    int lr = l & 15, lh = l >> 4;

    // preamble
    issueB(0); CP_COMMIT();
    issueB(1); CP_COMMIT();
    float4 a0;
    ldgA(0, a0);
    __syncthreads();                 // Wg preload visible to ALL threads
    split_phase(0, a0);              // writes ABF[0]
    ldgA(1, a0);                     // prefetch for split(1)

    for (int kb = 0; kb < NB; kb++) {
        CP_WAIT1();                  // B stage kb arrived (thread-local)
        __syncthreads();             // stage kb + ABF[kb&1] visible; prior reads done
        if (kb + 2 < NB) { issueB(kb + 2); }
        CP_COMMIT();
        if (kb + 1 < NB) {
            split_phase(kb + 1, a0);       // writes ABF[(kb+1)&1], overlaps MMA below
            int kn = (kb + 2 < NB) ? (kb + 2) : (NB - 1);
            ldgA(kn, a0);
        }

        // ---- MMA(kb): ABF[kb&1] + B stage kb%3 ----
        int s = kb % PNSTG;
        uint32_t sAu = smb + ABF_OFF(kb & 1);
#pragma unroll
        for (int ks = 0; ks < 2; ks++) {
            uint32_t kbyte = (uint32_t)(ks << 5) + (lh << 4);
            uint32_t Ah[2][4], Al[2][4];
#pragma unroll
            for (int t = 0; t < 2; t++) {
                uint32_t ro = (uint32_t)((mw * 32 + (t << 4) + lr) << 7) + kbyte;
                LDSM4(Ah[t], sAu + swz(ro));
                LDSM4(Al[t], sAu + swz(ro + 64));
            }
#pragma unroll
            for (int z = 0; z < 3; z++) {
                uint32_t sBu = smb + BSP_OFF(s, z);
                uint32_t Bh[4], Bl[4];
                uint32_t ro = (uint32_t)((nw * 16 + lr) << 7) + kbyte;
                LDSM4(Bh, sBu + swz(ro));
                LDSM4(Bl, sBu + swz(ro + 64));
#pragma unroll
                for (int mi = 0; mi < 2; mi++)
#pragma unroll
                    for (int j = 0; j < 2; j++) {
                        MMA16816(acc[z][mi][j], Ah[mi], Bh[j], Bh[j + 2]);
                        MMA16816(acc[z][mi][j], Ah[mi], Bl[j], Bl[j + 2]);
                        MMA16816(acc[z][mi][j], Al[mi], Bh[j], Bh[j + 2]);
                    }
            }
        }
    }

    // ---- gate reduce ----
    gred[row][chk] = gp0;
    __syncthreads();
    if (tid < 64) {
        float s = 0.f;
#pragma unroll
        for (int j = 0; j < 8; j++) s += gred[tid][j];
        g_w[m0 + tid] = 1.f / (1.f + expf(-(s + gb[0])));
    }

    // ---- epilogue ----
    float* Cs[3] = {g_q, g_k, g_v};
#pragma unroll
    for (int z = 0; z < 3; z++) {
#pragma unroll
        for (int mi = 0; mi < 2; mi++) {
            int r0 = mw * 32 + (mi << 4) + (l >> 2);
#pragma unroll
            for (int j = 0; j < 2; j++) {
                float* p = Cs[z] + (size_t)(m0 + r0) * Mm + nw * 16 + (j << 3) + ((l & 3) << 1);
                *(float2*)p = make_float2(acc[z][mi][j][0], acc[z][mi][j][1]);
                *(float2*)(p + (size_t)8 * Mm) = make_float2(acc[z][mi][j][2], acc[z][mi][j][3]);
            }
        }
    }
}

// ======================================================================
// out gemm: pre-split operands, 2-stage cp.async, 2 CTAs/SM
// ======================================================================
#define NSTG 2
#define STAGE_B 32768
#define GEMM_SMEM (NSTG * STAGE_B)   // 64 KB

__global__ void __launch_bounds__(256, 2) out_mma(float* __restrict__ out)
{
    extern __shared__ __align__(1024) char smem[];
    int n0 = blockIdx.y * 128;
    int m0 = blockIdx.x * 128;
    const unsigned char* As = g_rs;
    const unsigned char* Bs = g_wos + (size_t)n0 * 4 * 128;
    float* C = out + n0;
    const int NB = Mm / 32, ldc = Hh;

    int tid = threadIdx.x;
    int w = tid >> 5, l = tid & 31;
    uint32_t smb = smem_u32(smem);
    unsigned long long gA = (unsigned long long)__cvta_generic_to_global(As);
    unsigned long long gB = (unsigned long long)__cvta_generic_to_global(Bs);

    auto issue = [&](int kb) {
        uint32_t st = smb + (uint32_t)(kb & (NSTG - 1)) * STAGE_B;
#pragma unroll
        for (int u = 0; u < 4; u++) {
            int c = tid + (u << 8);
            int row = c >> 3;
            uint32_t seg = (uint32_t)(c & 7) << 4;
            unsigned long long srcA = gA + ((unsigned long long)(m0 + row) * NB + kb) * 128ull + seg;
            unsigned long long srcB = gB + ((unsigned long long)row * NB + kb) * 128ull + seg;
            uint32_t d = swz(((uint32_t)row << 7) + seg);
            CP16(st + d, srcA);
            CP16(st + 16384 + d, srcB);
        }
    };

    float acc[2][8][4];
#pragma unroll
    for (int mi = 0; mi < 2; mi++)
#pragma unroll
        for (int nj = 0; nj < 8; nj++)
#pragma unroll
            for (int cc = 0; cc < 4; cc++) acc[mi][nj][cc] = 0.f;

    int wm = (w >> 1) << 5;
    int wn = (w & 1) << 6;
    int lr = l & 15, lh = l >> 4;

    issue(0); CP_COMMIT();
    issue(1); CP_COMMIT();

    for (int kb = 0; kb < NB; kb++) {
        CP_WAIT1();
        __syncthreads();
        uint32_t sAu = smb + (uint32_t)(kb & (NSTG - 1)) * STAGE_B;
        uint32_t sBu = sAu + 16384;
#pragma unroll
        for (int ks = 0; ks < 2; ks++) {
            uint32_t kbyte = (uint32_t)(ks << 5) + (lh << 4);
            uint32_t Ah[2][4], Al[2][4], Bh[4][4], Bl[4][4];
#pragma unroll
            for (int t = 0; t < 2; t++) {
                uint32_t ro = (uint32_t)((wm + (t << 4) + lr) << 7) + kbyte;
                LDSM4(Ah[t], sAu + swz(ro));
                LDSM4(Al[t], sAu + swz(ro + 64));
            }
#pragma unroll
            for (int g = 0; g < 4; g++) {
                uint32_t ro = (uint32_t)((wn + (g << 4) + lr) << 7) + kbyte;
                LDSM4(Bh[g], sBu + swz(ro));
                LDSM4(Bl[g], sBu + swz(ro + 64));
            }
#pragma unroll
            for (int mi = 0; mi < 2; mi++)
#pragma unroll
                for (int nj = 0; nj < 8; nj++) {
                    int g = nj >> 1, p = nj & 1;
                    MMA16816(acc[mi][nj], Ah[mi], Bh[g][p], Bh[g][p + 2]);
                    MMA16816(acc[mi][nj], Ah[mi], Bl[g][p], Bl[g][p + 2]);
                    MMA16816(acc[mi][nj], Al[mi], Bh[g][p], Bh[g][p + 2]);
                }
        }
        __syncthreads();
        if (kb + NSTG < NB) issue(kb + NSTG);
        CP_COMMIT();
    }

#pragma unroll
    for (int mi = 0; mi < 2; mi++) {
        int r0 = wm + (mi << 4) + (l >> 2);
#pragma unroll
        for (int nj = 0; nj < 8; nj++) {
            float* p = C + (size_t)(m0 + r0) * ldc + wn + (nj << 3) + ((l & 3) << 1);
            *(float2*)p = make_float2(acc[mi][nj][0], acc[mi][nj][1]);
            *(float2*)(p + (size_t)8 * ldc) = make_float2(acc[mi][nj][2], acc[mi][nj][3]);
        }
    }
}

// ---------------- fused weight splits (one launch, 4 matrices) ----------------
__global__ void __launch_bounds__(256) wsplit(const float* __restrict__ Wq,
                                              const float* __restrict__ Wk,
                                              const float* __restrict__ Wv,
                                              const float* __restrict__ Wo)
{
    int z = blockIdx.y;
    const float* src; unsigned char* dst; int K;
    if (z == 0)      { src = Wq; dst = g_wqs; K = Hh; }
    else if (z == 1) { src = Wk; dst = g_wks; K = Hh; }
    else if (z == 2) { src = Wv; dst = g_wvs; K = Hh; }
    else             { src = Wo; dst = g_wos; K = Mm; }
    int cpr = K >> 3, nkb = K >> 5;
    int g = blockIdx.x * 256 + threadIdx.x;
    int row = g / cpr, pos = g - row * cpr;
    const float4* s = (const float4*)(src + (size_t)row * K + (size_t)pos * 8);
    float4 a0 = s[0], a1 = s[1];
    uint4 h, lo; pack8(a0, a1, h, lo);
    size_t base = ((size_t)row * nkb + (pos >> 2)) * 128 + (size_t)(pos & 3) * 16;
    *(uint4*)(dst + base)      = h;
    *(uint4*)(dst + base + 64) = lo;
}

// ---------------- per-chunk aggregates ----------------
__global__ void __launch_bounds__(256) agg_kernel()
{
    int i = blockIdx.x;
    int tid = threadIdx.x;
    __shared__ float sw[256];
    __shared__ float sik[256];
    __shared__ float siv[256];
    __shared__ float red[256];
    {
        int b = tid >> 6, c = tid & 63;
        size_t t = (size_t)b * Ss + (size_t)i * CH + c;
        const float4* kr4 = (const float4*)(g_k + t * Mm);
        const float4* vr4 = (const float4*)(g_v + t * Mm);
        float nk = 0.f, nv = 0.f;
#pragma unroll 4
        for (int d = 0; d < 32; d++) {
            float4 a = kr4[d]; nk += a.x * a.x + a.y * a.y + a.z * a.z + a.w * a.w;
            float4 u = vr4[d]; nv += u.x * u.x + u.y * u.y + u.z * u.z + u.w * u.w;
        }
        sik[tid] = 1.f / fmaxf(sqrtf(nk), 1e-12f);
        siv[tid] = 1.f / fmaxf(sqrtf(nv), 1e-12f);
        float wv = g_w[t];
        sw[tid] = wv;
        red[tid] = wv;
    }
    __syncthreads();
    for (int o = 128; o; o >>= 1) { if (tid < o) red[tid] += red[tid + o]; __syncthreads(); }
    float sumw = red[0];
    float wsum = fmaxf(sumw, 1e-8f);
    __syncthreads();

    int d = tid & 127;
    bool isv = (tid >= 128);
    const float* src = isv ? g_v : g_k;
    const float* inv = isv ? siv : sik;
    float acc = 0.f;
#pragma unroll 4
    for (int j = 0; j < 256; j++) {
        size_t tj = (size_t)(j >> 6) * Ss + (size_t)i * CH + (j & 63);
        acc += sw[j] * inv[j] * src[tj * Mm + d];
    }
    float mean = acc / wsum;
    red[tid] = mean * mean;
    __syncthreads();
    for (int o = 64; o; o >>= 1) { if ((tid & 127) < o) red[tid] += red[tid + o]; __syncthreads(); }
    float nrm = fmaxf(sqrtf(red[isv ? 128 : 0]), 1e-12f);
    float outv = mean / nrm;
    if (isv) g_Vagg[i * Mm + d] = outv;
    else     g_Kagg[i * Mm + d] = outv;
    if (tid == 0) g_ws[i] = sumw * (1.f / 256.f);
}

// ---------------- attention read + fused r-split + fused mean_ws ----------------
#define ATTN_SMEM ((8192 + 8192 + 4096 + 8192) * 4)   // kt(/rsm) + vsm + psm + qsm = 112KB
__global__ void __launch_bounds__(256) attn_kernel(const float* __restrict__ log_beta,
                                                   float* __restrict__ out, int out_size)
{
    extern __shared__ float sm[];
    float* kt  = sm;               // [d][slot] 128x64 — reused as rsm later
    float* vsm = kt + 8192;        // [slot][d] 64x128
    float* psm = vsm + 8192;       // [warp][c8][slot]
    float* qsm = psm + 4096;       // [tok][d] 64x128
    __shared__ float str[64];
    __shared__ float ssum;

    int i = blockIdx.x;
    int bb = blockIdx.y;
    int tid = threadIdx.x;
    float beta = expf(log_beta[0]);
    size_t tbase = (size_t)bb * Ss + (size_t)i * CH;

    for (int idx = tid; idx < 8192; idx += 256) {
        int d = idx >> 6, slot = idx & 63;
        kt[idx] = g_Kagg[slot * 128 + d];
    }
    for (int idx = tid; idx < 8192; idx += 256) vsm[idx] = g_Vagg[idx];
    for (int idx = tid; idx < 8192; idx += 256)
        qsm[idx] = g_q[(tbase + (size_t)(idx >> 7)) * Mm + (idx & 127)];
    if (tid < 64) {
        float dc = powf(0.999f, 64.f);
        float s = 0.f;
        if (tid < i) s = g_ws[tid] * powf(dc, (float)(i - 1 - tid));
        str[tid] = s;
    }
    __syncthreads();
    if (tid == 0) {
        float s = 0.f;
        for (int j = 0; j < 64; j++) s += str[j];
        ssum = s;
        if (i == 0 && bb == 0 && out_size > NTOK * Hh) {
            float m = 0.f;
            for (int j = 0; j < NC; j++) m += g_ws[j];
            out[(size_t)NTOK * Hh] = m / (float)NC;
        }
    }
    __syncthreads();

    bool valid = (ssum >= 1e-8f);
    int w = tid >> 5, lane = tid & 31;
    float m0ok = (str[lane] > 1e-8f)      ? 0.f : -1e9f;
    float m1ok = (str[lane + 32] > 1e-8f) ? 0.f : -1e9f;

    float s0[8], s1[8];
#pragma unroll
    for (int c8 = 0; c8 < 8; c8++) { s0[c8] = 0.f; s1[c8] = 0.f; }
    for (int d4 = 0; d4 < 32; d4++) {
        float kv0[4], kv1[4];
#pragma unroll
        for (int ii = 0; ii < 4; ii++) {
            kv0[ii] = kt[(d4 * 4 + ii) * 64 + lane];
            kv1[ii] = kt[(d4 * 4 + ii) * 64 + 32 + lane];
        }
#pragma unroll
        for (int c8 = 0; c8 < 8; c8++) {
            float4 q = *(const float4*)(qsm + (w * 8 + c8) * 128 + d4 * 4);  // LDS broadcast
            s0[c8] += q.x * kv0[0] + q.y * kv0[1] + q.z * kv0[2] + q.w * kv0[3];
            s1[c8] += q.x * kv1[0] + q.y * kv1[1] + q.z * kv1[2] + q.w * kv1[3];
        }
    }
#pragma unroll
    for (int c8 = 0; c8 < 8; c8++) {
        float sv0 = s0[c8] * beta + m0ok;
        float sv1 = s1[c8] * beta + m1ok;
        float mx = fmaxf(sv0, sv1);
#pragma unroll
        for (int o = 16; o; o >>= 1) mx = fmaxf(mx, __shfl_xor_sync(0xffffffffu, mx, o));
        float p0 = expf(sv0 - mx);
        float p1 = expf(sv1 - mx);
        float sum = p0 + p1;
#pragma unroll
        for (int o = 16; o; o >>= 1) sum += __shfl_xor_sync(0xffffffffu, sum, o);
        float invs = 1.f / sum;
        psm[w * 512 + c8 * 64 + lane]      = p0 * invs;
        psm[w * 512 + c8 * 64 + 32 + lane] = p1 * invs;
    }
    __syncthreads();   // all warps done with kt — reusable as rsm

    float a[8][4];
#pragma unroll
    for (int c8 = 0; c8 < 8; c8++)
#pragma unroll
        for (int cc = 0; cc < 4; cc++) a[c8][cc] = 0.f;
    for (int j = 0; j < 64; j++) {
        float v0 = vsm[j * 128 + lane];
        float v1 = vsm[j * 128 + 32 + lane];
        float v2 = vsm[j * 128 + 64 + lane];
        float v3 = vsm[j * 128 + 96 + lane];
#pragma unroll
        for (int c8 = 0; c8 < 8; c8++) {
            float pj = psm[w * 512 + c8 * 64 + j];
            a[c8][0] += pj * v0; a[c8][1] += pj * v1;
            a[c8][2] += pj * v2; a[c8][3] += pj * v3;
        }
    }
    float* rsm = kt;
#pragma unroll
    for (int c8 = 0; c8 < 8; c8++) {
        int lt = w * 8 + c8;
        rsm[lt * 128 + lane]      = valid ? a[c8][0] : 0.f;
        rsm[lt * 128 + lane + 32] = valid ? a[c8][1] : 0.f;
        rsm[lt * 128 + lane + 64] = valid ? a[c8][2] : 0.f;
        rsm[lt * 128 + lane + 96] = valid ? a[c8][3] : 0.f;
    }
    __syncthreads();

    // ---- pack r -> g_rs (bf16 hi/lo tile layout) ----
#pragma unroll
    for (int u = 0; u < 4; u++) {
        int c = tid + (u << 8);
        int lt = c >> 4, pos = c & 15;
        float4 a0 = *(float4*)(rsm + lt * 128 + pos * 8);
        float4 a1 = *(float4*)(rsm + lt * 128 + pos * 8 + 4);
        uint4 h, lo; pack8(a0, a1, h, lo);
        size_t grow = tbase + lt;
        size_t base = (grow * 4 + (size_t)(pos >> 2)) * 128 + (size_t)(pos & 3) * 16;
        *(uint4*)(g_rs + base)      = h;
        *(uint4*)(g_rs + base + 64) = lo;
    }
}

// ---------------- per-token output norm clamp ----------------
__global__ void __launch_bounds__(256) norm_kernel(float* __restrict__ out)
{
    __shared__ float red[256];
    size_t t = blockIdx.x;
    float* row = out + t * (size_t)Hh;
    int tid = threadIdx.x;
    float4* r4 = (float4*)row;
    float ss = 0.f;
#pragma unroll
    for (int u = 0; u < 2; u++) {
        float4 v = r4[tid + u * 256];
        ss += v.x * v.x + v.y * v.y + v.z * v.z + v.w * v.w;
    }
    red[tid] = ss;
    __syncthreads();
    for (int o = 128; o; o >>= 1) { if (tid < o) red[tid] += red[tid + o]; __syncthreads(); }
    float nrm = fmaxf(sqrtf(red[0]), 1e-6f);
    float sc = fminf(10.f / nrm, 1.f);
    if (sc < 1.f) {
#pragma unroll
        for (int u = 0; u < 2; u++) {
            float4 v = r4[tid + u * 256];
            v.x *= sc; v.y *= sc; v.z *= sc; v.w *= sc;
            r4[tid + u * 256] = v;
        }
    }
}

// ---------------- launch ----------------
extern "C" void kernel_launch(void* const* d_in, const int* in_sizes, int n_in,
                              void* d_out, int out_size)
{
    const float* x  = (const float*)d_in[0];
    const float* Wq = (const float*)d_in[1];
    const float* Wk = (const float*)d_in[2];
    const float* Wv = (const float*)d_in[3];
    const float* Wo = (const float*)d_in[4];
    const float* Wg = (const float*)d_in[5];
    const float* gb = (const float*)d_in[6];
    const float* lb = (const float*)d_in[7];
    float* out = (float*)d_out;

    cudaFuncSetAttribute(attn_kernel, cudaFuncAttributeMaxDynamicSharedMemorySize, ATTN_SMEM);
    cudaFuncSetAttribute(mega_proj, cudaFuncAttributeMaxDynamicSharedMemorySize, MEGA_SMEM);
    cudaFuncSetAttribute(out_mma,  cudaFuncAttributeMaxDynamicSharedMemorySize, GEMM_SMEM);

    // 1. all weight splits in one launch
    wsplit<<<dim3(128, 4), 256>>>(Wq, Wk, Wv, Wo);
    // 2. fused split + gate + q/k/v projections (16 warps for latency hiding)
    mega_proj<<<NTOK / 64, 512, MEGA_SMEM>>>(x, Wg, gb);
    // 3. per-chunk write aggregates
    agg_kernel<<<NC, 256>>>();
    // 4. attention reads (+ fused r-split + mean_ws)
    attn_kernel<<<dim3(NC, Bb), 256, ATTN_SMEM>>>(lb, out, out_size);
    // 5. output projection
    out_mma<<<dim3(NTOK / 128, Hh / 128), 256, GEMM_SMEM>>>(out);
    // 6. norm clamp
    norm_kernel<<<NTOK, 256>>>(out);
}